// round 1
// baseline (speedup 1.0000x reference)
#include <cuda_runtime.h>
#include <cuda_bf16.h>
#include <math.h>

// ---------------- problem constants ----------------
#define BB   16
#define TT   512
#define NTOK (BB*TT)        // 8192
#define DD   1024
#define HH   16
#define HDIM 64
#define LL   12
#define DFF  4096
#define V0   1025
#define TOUT 511
#define NHEADROWS (BB*TOUT) // 8176

// ---------------- scratch (device globals; no allocation allowed) -------
__device__ float g_h   [NTOK*DD];
__device__ float g_hn  [NTOK*DD];
__device__ float g_qkv [NTOK*3*DD];
__device__ float g_o   [NTOK*DD];        // also reused as gathered head input
__device__ float g_attn[(size_t)BB*HH*TT*TT];
__device__ float g_ffn [NTOK*DFF];
__device__ float g_tein[BB*DD];
__device__ float g_teh [BB*DFF];
__device__ float g_te  [BB*DD];
__device__ float g_cos [TT*32];
__device__ float g_sin [TT*32];

__device__ __forceinline__ float gelu_exact(float x) {
    return 0.5f * x * (1.0f + erff(x * 0.70710678118654752440f));
}

// ---------------- rope tables ----------------
__global__ void rope_init_kernel(float* cosT, float* sinT) {
    int idx = blockIdx.x * blockDim.x + threadIdx.x;   // t*32 + j
    if (idx >= TT*32) return;
    int t = idx >> 5, j = idx & 31;
    float freq = expf(-(float)j * (logf(10000.0f) / 32.0f));
    float ang = (float)t * freq;
    cosT[idx] = cosf(ang);
    sinT[idx] = sinf(ang);
}

// ---------------- time embedding input ----------------
__global__ void te_in_kernel(const int* __restrict__ t, float* __restrict__ out) {
    int b = blockIdx.x;
    int j = threadIdx.x;                    // 0..511
    float tv = (float)t[b];
    float e  = expf((float)j * (-logf(10000.0f) / 511.0f));
    float v  = tv * e;
    out[b*DD + j]       = sinf(v);
    out[b*DD + 512 + j] = cosf(v);
}

// small GEMM: C[16,N] = A[16,K] @ B[K,N] + bias, optional gelu. one thread per column n.
template<int EPI>  // 0 = bias only, 2 = gelu(bias+)
__global__ void tgemm_kernel(const float* __restrict__ A, const float* __restrict__ Bw,
                             const float* __restrict__ bias, float* __restrict__ C,
                             int K, int N) {
    int n = blockIdx.x * blockDim.x + threadIdx.x;
    if (n >= N) return;
    float acc[16];
    #pragma unroll
    for (int m = 0; m < 16; m++) acc[m] = 0.f;
    for (int k = 0; k < K; k++) {
        float bv = Bw[(size_t)k*N + n];
        #pragma unroll
        for (int m = 0; m < 16; m++) acc[m] += A[m*K + k] * bv;
    }
    float bs = bias[n];
    #pragma unroll
    for (int m = 0; m < 16; m++) {
        float v = acc[m] + bs;
        if (EPI == 2) v = gelu_exact(v);
        C[(size_t)m*N + n] = v;
    }
}

// ---------------- embedding ----------------
__global__ void embed_kernel(const int* __restrict__ x, const int* __restrict__ level,
                             const float* __restrict__ tok_emb, const float* __restrict__ level_emb,
                             const float* __restrict__ te, float* __restrict__ h) {
    int n = blockIdx.x;           // token
    int b = n >> 9;               // /T
    int lvl = level[0];
    const float4* tk = (const float4*)(tok_emb + (size_t)x[n]*DD);
    const float4* le = (const float4*)(level_emb + (size_t)lvl*DD);
    const float4* tv = (const float4*)(te + (size_t)b*DD);
    float4* out = (float4*)(h + (size_t)n*DD);
    int i = threadIdx.x;          // 256 threads, 4 floats each
    float4 a = tk[i], c = le[i], d = tv[i];
    out[i] = make_float4(a.x+c.x+d.x, a.y+c.y+d.y, a.z+c.z+d.z, a.w+c.w+d.w);
}

// ---------------- layernorm (row of 1024) ----------------
__global__ void __launch_bounds__(256) layernorm_kernel(
        const float* __restrict__ x, const float* __restrict__ g,
        const float* __restrict__ b, float* __restrict__ y) {
    size_t row = blockIdx.x;
    int tid = threadIdx.x;
    const float4* xr = (const float4*)(x + row*DD);
    float4 v = xr[tid];
    float s  = v.x + v.y + v.z + v.w;
    float ss = v.x*v.x + v.y*v.y + v.z*v.z + v.w*v.w;
    __shared__ float sh1[8], sh2[8], shm[2];
    int lane = tid & 31, w = tid >> 5;
    #pragma unroll
    for (int o = 16; o > 0; o >>= 1) {
        s  += __shfl_xor_sync(0xffffffffu, s,  o);
        ss += __shfl_xor_sync(0xffffffffu, ss, o);
    }
    if (lane == 0) { sh1[w] = s; sh2[w] = ss; }
    __syncthreads();
    if (tid == 0) {
        float ts = 0.f, tss = 0.f;
        #pragma unroll
        for (int i = 0; i < 8; i++) { ts += sh1[i]; tss += sh2[i]; }
        float mean = ts * (1.0f/DD);
        float var  = tss * (1.0f/DD) - mean*mean;
        shm[0] = mean;
        shm[1] = rsqrtf(var + 1e-5f);
    }
    __syncthreads();
    float mean = shm[0], rs = shm[1];
    float4 gg = ((const float4*)g)[tid];
    float4 bb = ((const float4*)b)[tid];
    float4 o;
    o.x = (v.x-mean)*rs*gg.x + bb.x;
    o.y = (v.y-mean)*rs*gg.y + bb.y;
    o.z = (v.z-mean)*rs*gg.z + bb.z;
    o.w = (v.w-mean)*rs*gg.w + bb.w;
    ((float4*)(y + row*DD))[tid] = o;
}

// ---------------- generic SGEMM: C = A[MxK] @ B[KxN] (+res / gelu) ------
// 128x128 tile, BK=8, 256 threads, 8x8 per thread. K must be a multiple of 8.
template<int EPI>   // 0 none, 1 add residual Cres, 2 gelu
__global__ void __launch_bounds__(256) sgemm_kernel(
        const float* __restrict__ A, const float* __restrict__ Bm,
        const float* __restrict__ Cres, float* __restrict__ C,
        int M, int N, int K) {
    __shared__ float As[8][128];
    __shared__ float Bs[8][128];
    int tid = threadIdx.x;
    int tx = tid & 15, ty = tid >> 4;
    int bn0 = blockIdx.x * 128;
    int bm0 = blockIdx.y * 128;

    float acc[8][8];
    #pragma unroll
    for (int i = 0; i < 8; i++)
        #pragma unroll
        for (int j = 0; j < 8; j++) acc[i][j] = 0.f;

    int arow = tid >> 1;            // 0..127
    int acol = (tid & 1) * 4;       // 0 or 4
    int brow = tid >> 5;            // 0..7
    int bcol = (tid & 31) * 4;      // 0..124
    int aGlobRow = bm0 + arow;
    int bGlobCol = bn0 + bcol;
    bool nvec = ((N & 3) == 0);

    for (int k0 = 0; k0 < K; k0 += 8) {
        float4 av = make_float4(0.f,0.f,0.f,0.f);
        if (aGlobRow < M)
            av = *reinterpret_cast<const float4*>(&A[(size_t)aGlobRow*K + k0 + acol]);
        As[acol+0][arow] = av.x;
        As[acol+1][arow] = av.y;
        As[acol+2][arow] = av.z;
        As[acol+3][arow] = av.w;

        float4 bv;
        size_t boff = (size_t)(k0 + brow) * N + bGlobCol;
        if (nvec && bGlobCol + 3 < N) {
            bv = *reinterpret_cast<const float4*>(&Bm[boff]);
        } else {
            bv.x = (bGlobCol+0 < N) ? Bm[boff+0] : 0.f;
            bv.y = (bGlobCol+1 < N) ? Bm[boff+1] : 0.f;
            bv.z = (bGlobCol+2 < N) ? Bm[boff+2] : 0.f;
            bv.w = (bGlobCol+3 < N) ? Bm[boff+3] : 0.f;
        }
        *reinterpret_cast<float4*>(&Bs[brow][bcol]) = bv;
        __syncthreads();

        #pragma unroll
        for (int k = 0; k < 8; k++) {
            float4 a0 = *reinterpret_cast<const float4*>(&As[k][ty*8]);
            float4 a1 = *reinterpret_cast<const float4*>(&As[k][ty*8+4]);
            float4 b0 = *reinterpret_cast<const float4*>(&Bs[k][tx*8]);
            float4 b1 = *reinterpret_cast<const float4*>(&Bs[k][tx*8+4]);
            float ar[8] = {a0.x,a0.y,a0.z,a0.w,a1.x,a1.y,a1.z,a1.w};
            float br[8] = {b0.x,b0.y,b0.z,b0.w,b1.x,b1.y,b1.z,b1.w};
            #pragma unroll
            for (int i = 0; i < 8; i++)
                #pragma unroll
                for (int j = 0; j < 8; j++)
                    acc[i][j] += ar[i] * br[j];
        }
        __syncthreads();
    }

    #pragma unroll
    for (int i = 0; i < 8; i++) {
        int row = bm0 + ty*8 + i;
        if (row >= M) continue;
        #pragma unroll
        for (int j = 0; j < 8; j++) {
            int col = bn0 + tx*8 + j;
            if (col >= N) continue;
            float v = acc[i][j];
            if (EPI == 1) v += Cres[(size_t)row*N + col];
            if (EPI == 2) v = gelu_exact(v);
            C[(size_t)row*N + col] = v;
        }
    }
}

// ---------------- RoPE in place on q,k ----------------
__global__ void rope_kernel(float* __restrict__ qkv,
                            const float* __restrict__ cosT, const float* __restrict__ sinT) {
    int n = blockIdx.x;           // token
    int tid = threadIdx.x;        // 512 = 16 heads * 32 pairs
    int h = tid >> 5, j = tid & 31;
    int t = n & (TT-1);
    float c = cosT[t*32 + j], s = sinT[t*32 + j];
    #pragma unroll
    for (int cc = 0; cc < 2; cc++) {
        size_t off = (size_t)n*3*DD + cc*DD + h*HDIM + 2*j;
        float x1 = qkv[off], x2 = qkv[off+1];
        qkv[off]   = x1*c - x2*s;
        qkv[off+1] = x1*s + x2*c;
    }
}

// ---------------- attention: S = scale * Q K^T ----------------
// grid (T/64 kt, T/64 qt, B*H), block 256
__global__ void __launch_bounds__(256) attn_score_kernel(
        const float* __restrict__ qkv, float* __restrict__ attn) {
    __shared__ float Qs[64][68];
    __shared__ float Ks[64][68];
    int bh = blockIdx.z;
    int b = bh >> 4, h = bh & 15;
    int q0 = blockIdx.y * 64, k0 = blockIdx.x * 64;
    int tid = threadIdx.x;
    int tx = tid & 15, ty = tid >> 4;

    #pragma unroll
    for (int l = 0; l < 4; l++) {
        int lin = tid + l*256;
        int row = lin >> 4;
        int c4  = (lin & 15) << 2;
        size_t nq = (size_t)(b*TT + q0 + row);
        size_t nk = (size_t)(b*TT + k0 + row);
        float4 qv = *reinterpret_cast<const float4*>(&qkv[nq*3*DD + h*HDIM + c4]);
        float4 kv = *reinterpret_cast<const float4*>(&qkv[nk*3*DD + DD + h*HDIM + c4]);
        *reinterpret_cast<float4*>(&Qs[row][c4]) = qv;
        *reinterpret_cast<float4*>(&Ks[row][c4]) = kv;
    }
    __syncthreads();

    float acc[4][4];
    #pragma unroll
    for (int i = 0; i < 4; i++)
        #pragma unroll
        for (int j = 0; j < 4; j++) acc[i][j] = 0.f;

    #pragma unroll 8
    for (int d = 0; d < 64; d++) {
        float ar[4], br[4];
        #pragma unroll
        for (int i = 0; i < 4; i++) ar[i] = Qs[ty*4+i][d];
        #pragma unroll
        for (int j = 0; j < 4; j++) br[j] = Ks[tx*4+j][d];
        #pragma unroll
        for (int i = 0; i < 4; i++)
            #pragma unroll
            for (int j = 0; j < 4; j++) acc[i][j] += ar[i]*br[j];
    }

    const float scale = 0.125f;   // 1/sqrt(64)
    #pragma unroll
    for (int i = 0; i < 4; i++) {
        size_t rowoff = ((size_t)bh*TT + q0 + ty*4 + i) * TT + k0;
        #pragma unroll
        for (int j = 0; j < 4; j++)
            attn[rowoff + tx*4 + j] = acc[i][j] * scale;
    }
}

// ---------------- softmax over rows of length 512 ----------------
__global__ void __launch_bounds__(128) softmax_kernel(float* __restrict__ attn) {
    size_t row = blockIdx.x;
    float* p = attn + row * TT;
    int tid = threadIdx.x;
    float v[4];
    float m = -1e30f;
    #pragma unroll
    for (int i = 0; i < 4; i++) { v[i] = p[tid + i*128]; m = fmaxf(m, v[i]); }
    __shared__ float sh[4], shv[2];
    int lane = tid & 31, w = tid >> 5;
    #pragma unroll
    for (int o = 16; o > 0; o >>= 1) m = fmaxf(m, __shfl_xor_sync(0xffffffffu, m, o));
    if (lane == 0) sh[w] = m;
    __syncthreads();
    if (tid == 0) shv[0] = fmaxf(fmaxf(sh[0],sh[1]), fmaxf(sh[2],sh[3]));
    __syncthreads();
    m = shv[0];
    float s = 0.f;
    #pragma unroll
    for (int i = 0; i < 4; i++) { v[i] = expf(v[i]-m); s += v[i]; }
    #pragma unroll
    for (int o = 16; o > 0; o >>= 1) s += __shfl_xor_sync(0xffffffffu, s, o);
    if (lane == 0) sh[w] = s;
    __syncthreads();
    if (tid == 0) shv[1] = sh[0]+sh[1]+sh[2]+sh[3];
    __syncthreads();
    float inv = 1.0f / shv[1];
    #pragma unroll
    for (int i = 0; i < 4; i++) p[tid + i*128] = v[i] * inv;
}

// ---------------- O = P V ----------------
// grid (T/64 qt, B*H), block 256. Output tile 64 q x 64 d.
__global__ void __launch_bounds__(256) attn_av_kernel(
        const float* __restrict__ attn, const float* __restrict__ qkv,
        float* __restrict__ o) {
    __shared__ float Ps[64][68];
    __shared__ float Vs[64][68];
    int bh = blockIdx.y;
    int b = bh >> 4, h = bh & 15;
    int q0 = blockIdx.x * 64;
    int tid = threadIdx.x;
    int tx = tid & 15, ty = tid >> 4;

    float acc[4][4];
    #pragma unroll
    for (int i = 0; i < 4; i++)
        #pragma unroll
        for (int j = 0; j < 4; j++) acc[i][j] = 0.f;

    for (int kk0 = 0; kk0 < TT; kk0 += 64) {
        #pragma unroll
        for (int l = 0; l < 4; l++) {
            int lin = tid + l*256;
            int row = lin >> 4;
            int c4  = (lin & 15) << 2;
            float4 pv = *reinterpret_cast<const float4*>(
                &attn[((size_t)bh*TT + q0 + row)*TT + kk0 + c4]);
            float4 vv = *reinterpret_cast<const float4*>(
                &qkv[(size_t)(b*TT + kk0 + row)*3*DD + 2*DD + h*HDIM + c4]);
            *reinterpret_cast<float4*>(&Ps[row][c4]) = pv;
            *reinterpret_cast<float4*>(&Vs[row][c4]) = vv;
        }
        __syncthreads();
        #pragma unroll 8
        for (int kk = 0; kk < 64; kk++) {
            float4 b4 = *reinterpret_cast<const float4*>(&Vs[kk][tx*4]);
            float br[4] = {b4.x, b4.y, b4.z, b4.w};
            float ar[4];
            #pragma unroll
            for (int i = 0; i < 4; i++) ar[i] = Ps[ty*4+i][kk];
            #pragma unroll
            for (int i = 0; i < 4; i++)
                #pragma unroll
                for (int j = 0; j < 4; j++) acc[i][j] += ar[i]*br[j];
        }
        __syncthreads();
    }

    #pragma unroll
    for (int i = 0; i < 4; i++) {
        size_t off = (size_t)(b*TT + q0 + ty*4 + i)*DD + h*HDIM;
        #pragma unroll
        for (int j = 0; j < 4; j++)
            o[off + tx*4 + j] = acc[i][j];
    }
}

// ---------------- gather rows t=1..511 for head ----------------
__global__ void gather_kernel(const float* __restrict__ hn, float* __restrict__ out) {
    int m = blockIdx.x;              // 0..8175
    int b = m / TOUT;
    int t = m % TOUT + 1;
    const float4* src = (const float4*)(hn + (size_t)(b*TT + t)*DD);
    float4* dst = (float4*)(out + (size_t)m*DD);
    dst[threadIdx.x] = src[threadIdx.x];
}

// ---------------- host side ----------------
static inline int cdiv(int a, int b) { return (a + b - 1) / b; }

extern "C" void kernel_launch(void* const* d_in, const int* in_sizes, int n_in,
                              void* d_out, int out_size) {
    const int*   x         = (const int*)  d_in[0];
    const int*   t         = (const int*)  d_in[1];
    const int*   level     = (const int*)  d_in[2];
    const float* tok_emb   = (const float*)d_in[3];
    const float* level_emb = (const float*)d_in[4];
    const float* time_w1   = (const float*)d_in[5];
    const float* time_b1   = (const float*)d_in[6];
    const float* time_w2   = (const float*)d_in[7];
    const float* time_b2   = (const float*)d_in[8];
    const float* ln1_g     = (const float*)d_in[9];
    const float* ln1_b     = (const float*)d_in[10];
    const float* qkv_w     = (const float*)d_in[11];
    const float* proj_w    = (const float*)d_in[12];
    const float* ln2_g     = (const float*)d_in[13];
    const float* ln2_b     = (const float*)d_in[14];
    const float* fc1_w     = (const float*)d_in[15];
    const float* fc2_w     = (const float*)d_in[16];
    const float* lnf_g     = (const float*)d_in[17];
    const float* lnf_b     = (const float*)d_in[18];
    const float* head0_w   = (const float*)d_in[19];

    float *ph, *phn, *pqkv, *po, *pattn, *pffn, *ptein, *pteh, *pte, *pcos, *psin;
    cudaGetSymbolAddress((void**)&ph,    g_h);
    cudaGetSymbolAddress((void**)&phn,   g_hn);
    cudaGetSymbolAddress((void**)&pqkv,  g_qkv);
    cudaGetSymbolAddress((void**)&po,    g_o);
    cudaGetSymbolAddress((void**)&pattn, g_attn);
    cudaGetSymbolAddress((void**)&pffn,  g_ffn);
    cudaGetSymbolAddress((void**)&ptein, g_tein);
    cudaGetSymbolAddress((void**)&pteh,  g_teh);
    cudaGetSymbolAddress((void**)&pte,   g_te);
    cudaGetSymbolAddress((void**)&pcos,  g_cos);
    cudaGetSymbolAddress((void**)&psin,  g_sin);

    // rope tables + time embedding
    rope_init_kernel<<<cdiv(TT*32, 512), 512>>>(pcos, psin);
    te_in_kernel<<<BB, 512>>>(t, ptein);
    tgemm_kernel<2><<<cdiv(DFF,128), 128>>>(ptein, time_w1, time_b1, pteh, DD, DFF);
    tgemm_kernel<0><<<cdiv(DD,128), 128>>>(pteh, time_w2, time_b2, pte, DFF, DD);

    // token + level + time embedding
    embed_kernel<<<NTOK, 256>>>(x, level, tok_emb, level_emb, pte, ph);

    dim3 blk(256);
    for (int i = 0; i < LL; i++) {
        layernorm_kernel<<<NTOK, 256>>>(ph, ln1_g + i*DD, ln1_b + i*DD, phn);

        sgemm_kernel<0><<<dim3(cdiv(3*DD,128), cdiv(NTOK,128)), blk>>>(
            phn, qkv_w + (size_t)i*DD*3*DD, nullptr, pqkv, NTOK, 3*DD, DD);

        rope_kernel<<<NTOK, 512>>>(pqkv, pcos, psin);

        attn_score_kernel<<<dim3(TT/64, TT/64, BB*HH), blk>>>(pqkv, pattn);
        softmax_kernel<<<BB*HH*TT, 128>>>(pattn);
        attn_av_kernel<<<dim3(TT/64, BB*HH), blk>>>(pattn, pqkv, po);

        sgemm_kernel<1><<<dim3(cdiv(DD,128), cdiv(NTOK,128)), blk>>>(
            po, proj_w + (size_t)i*DD*DD, ph, ph, NTOK, DD, DD);

        layernorm_kernel<<<NTOK, 256>>>(ph, ln2_g + i*DD, ln2_b + i*DD, phn);

        sgemm_kernel<2><<<dim3(cdiv(DFF,128), cdiv(NTOK,128)), blk>>>(
            phn, fc1_w + (size_t)i*DD*DFF, nullptr, pffn, NTOK, DFF, DD);

        sgemm_kernel<1><<<dim3(cdiv(DD,128), cdiv(NTOK,128)), blk>>>(
            pffn, fc2_w + (size_t)i*DFF*DD, ph, ph, NTOK, DD, DFF);
    }

    layernorm_kernel<<<NTOK, 256>>>(ph, lnf_g, lnf_b, phn);
    gather_kernel<<<NHEADROWS, 256>>>(phn, po);
    sgemm_kernel<0><<<dim3(cdiv(V0,128), cdiv(NHEADROWS,128)), blk>>>(
        po, head0_w, nullptr, (float*)d_out, NHEADROWS, V0, DD);
}

// round 3
// speedup vs baseline: 2.2790x; 2.2790x over previous
#include <cuda_runtime.h>
#include <cuda_bf16.h>
#include <math.h>
#include <stdint.h>

// ---------------- problem constants ----------------
#define BB   16
#define TT   512
#define NTOK (BB*TT)        // 8192
#define DD   1024
#define HH   16
#define HDIM 64
#define LL   12
#define DFF  4096
#define V0   1025
#define TOUT 511
#define NHEADROWS (BB*TOUT) // 8176

// ---------------- scratch (device globals; no allocation allowed) -------
__device__ float g_h   [NTOK*DD];
__device__ float g_hn  [NTOK*DD];
__device__ float g_qkv [NTOK*3*DD];
__device__ float g_o   [NTOK*DD];        // also reused as gathered head input
__device__ float g_attn[(size_t)BB*HH*TT*TT];
__device__ float g_ffn [NTOK*DFF];
__device__ float g_tein[BB*DD];
__device__ float g_teh [BB*DFF];
__device__ float g_te  [BB*DD];
__device__ float g_cos [TT*32];
__device__ float g_sin [TT*32];

__device__ __forceinline__ float gelu_exact(float x) {
    return 0.5f * x * (1.0f + erff(x * 0.70710678118654752440f));
}

__device__ __forceinline__ uint32_t f2tf32(float x) {
    uint32_t r; asm("cvt.rna.tf32.f32 %0, %1;" : "=r"(r) : "f"(x)); return r;
}

// C += A(row) * B(col)  for m16n8k8 tf32
__device__ __forceinline__ void mma_tf32(float* c, const uint32_t* a, const uint32_t* b) {
    asm volatile(
        "mma.sync.aligned.m16n8k8.row.col.f32.tf32.tf32.f32 "
        "{%0,%1,%2,%3}, {%4,%5,%6,%7}, {%8,%9}, {%0,%1,%2,%3};"
        : "+f"(c[0]), "+f"(c[1]), "+f"(c[2]), "+f"(c[3])
        : "r"(a[0]), "r"(a[1]), "r"(a[2]), "r"(a[3]), "r"(b[0]), "r"(b[1]));
}

// ---------------- rope tables ----------------
__global__ void rope_init_kernel(float* cosT, float* sinT) {
    int idx = blockIdx.x * blockDim.x + threadIdx.x;   // t*32 + j
    if (idx >= TT*32) return;
    int t = idx >> 5, j = idx & 31;
    float freq = expf(-(float)j * (logf(10000.0f) / 32.0f));
    float ang = (float)t * freq;
    cosT[idx] = cosf(ang);
    sinT[idx] = sinf(ang);
}

// ---------------- time embedding input ----------------
__global__ void te_in_kernel(const int* __restrict__ t, float* __restrict__ out) {
    int b = blockIdx.x;
    int j = threadIdx.x;                    // 0..511
    float tv = (float)t[b];
    float e  = expf((float)j * (-logf(10000.0f) / 511.0f));
    float v  = tv * e;
    out[b*DD + j]       = sinf(v);
    out[b*DD + 512 + j] = cosf(v);
}

// small GEMM: C[16,N] = A[16,K] @ B[K,N] + bias, optional gelu.
template<int EPI>  // 0 = bias only, 2 = gelu(bias+)
__global__ void tgemm_kernel(const float* __restrict__ A, const float* __restrict__ Bw,
                             const float* __restrict__ bias, float* __restrict__ C,
                             int K, int N) {
    int n = blockIdx.x * blockDim.x + threadIdx.x;
    if (n >= N) return;
    float acc[16];
    #pragma unroll
    for (int m = 0; m < 16; m++) acc[m] = 0.f;
    for (int k = 0; k < K; k++) {
        float bv = Bw[(size_t)k*N + n];
        #pragma unroll
        for (int m = 0; m < 16; m++) acc[m] += A[m*K + k] * bv;
    }
    float bs = bias[n];
    #pragma unroll
    for (int m = 0; m < 16; m++) {
        float v = acc[m] + bs;
        if (EPI == 2) v = gelu_exact(v);
        C[(size_t)m*N + n] = v;
    }
}

// ---------------- embedding ----------------
__global__ void embed_kernel(const int* __restrict__ x, const int* __restrict__ level,
                             const float* __restrict__ tok_emb, const float* __restrict__ level_emb,
                             const float* __restrict__ te, float* __restrict__ h) {
    int n = blockIdx.x;           // token
    int b = n >> 9;               // /T
    int lvl = level[0];
    const float4* tk = (const float4*)(tok_emb + (size_t)x[n]*DD);
    const float4* le = (const float4*)(level_emb + (size_t)lvl*DD);
    const float4* tv = (const float4*)(te + (size_t)b*DD);
    float4* out = (float4*)(h + (size_t)n*DD);
    int i = threadIdx.x;          // 256 threads, 4 floats each
    float4 a = tk[i], c = le[i], d = tv[i];
    out[i] = make_float4(a.x+c.x+d.x, a.y+c.y+d.y, a.z+c.z+d.z, a.w+c.w+d.w);
}

// ---------------- layernorm (row of 1024) ----------------
__global__ void __launch_bounds__(256) layernorm_kernel(
        const float* __restrict__ x, const float* __restrict__ g,
        const float* __restrict__ b, float* __restrict__ y) {
    size_t row = blockIdx.x;
    int tid = threadIdx.x;
    const float4* xr = (const float4*)(x + row*DD);
    float4 v = xr[tid];
    float s  = v.x + v.y + v.z + v.w;
    float ss = v.x*v.x + v.y*v.y + v.z*v.z + v.w*v.w;
    __shared__ float sh1[8], sh2[8], shm[2];
    int lane = tid & 31, w = tid >> 5;
    #pragma unroll
    for (int o = 16; o > 0; o >>= 1) {
        s  += __shfl_xor_sync(0xffffffffu, s,  o);
        ss += __shfl_xor_sync(0xffffffffu, ss, o);
    }
    if (lane == 0) { sh1[w] = s; sh2[w] = ss; }
    __syncthreads();
    if (tid == 0) {
        float ts = 0.f, tss = 0.f;
        #pragma unroll
        for (int i = 0; i < 8; i++) { ts += sh1[i]; tss += sh2[i]; }
        float mean = ts * (1.0f/DD);
        float var  = tss * (1.0f/DD) - mean*mean;
        shm[0] = mean;
        shm[1] = rsqrtf(var + 1e-5f);
    }
    __syncthreads();
    float mean = shm[0], rs = shm[1];
    float4 gg = ((const float4*)g)[tid];
    float4 bb = ((const float4*)b)[tid];
    float4 o;
    o.x = (v.x-mean)*rs*gg.x + bb.x;
    o.y = (v.y-mean)*rs*gg.y + bb.y;
    o.z = (v.z-mean)*rs*gg.z + bb.z;
    o.w = (v.w-mean)*rs*gg.w + bb.w;
    ((float4*)(y + row*DD))[tid] = o;
}

// ---------------- tf32 tensor-core GEMM: C = A[MxK] @ B[KxN] ------------
// 128x128 tile, BK=16, 256 threads / 8 warps, warp tile 32x64 (m16n8k8).
template<int EPI>   // 0 none, 1 add residual Cres, 2 gelu
__global__ void __launch_bounds__(256) tf32gemm_kernel(
        const float* __restrict__ A, const float* __restrict__ Bm,
        const float* __restrict__ Cres, float* __restrict__ C,
        int M, int N, int K) {
    __shared__ __align__(16) uint32_t As[16][136];   // [k][m], pitch 136 -> conflict-free frag LDS
    __shared__ __align__(16) uint32_t Bs[16][136];   // [k][n]
    int tid = threadIdx.x;
    int bn0 = blockIdx.x * 128;
    int bm0 = blockIdx.y * 128;
    int wid = tid >> 5, lane = tid & 31;
    int wm = (wid & 3) * 32;       // warp m offset
    int wn = (wid >> 2) * 64;      // warp n offset

    float c[2][8][4];
    #pragma unroll
    for (int mt = 0; mt < 2; mt++)
        #pragma unroll
        for (int nt = 0; nt < 8; nt++)
            #pragma unroll
            for (int i = 0; i < 4; i++) c[mt][nt][i] = 0.f;

    // staging indices
    int aRow = tid >> 1;            // 0..127
    int aCol = (tid & 1) * 8;       // 0 or 8
    int bRow = tid >> 4;            // 0..15
    int bCol = (tid & 15) * 8;      // 0..120
    bool aValid = (bm0 + aRow) < M;
    bool bvec = ((N & 3) == 0) && (bn0 + bCol + 7 < N);

    float4 pa0, pa1;
    float  pb[8];

#define TGL_LOAD(k0) do {                                                    \
        if (aValid) {                                                        \
            const float* ap = A + (size_t)(bm0 + aRow)*K + (k0) + aCol;      \
            pa0 = *reinterpret_cast<const float4*>(ap);                      \
            pa1 = *reinterpret_cast<const float4*>(ap + 4);                  \
        } else {                                                             \
            pa0 = make_float4(0.f,0.f,0.f,0.f);                              \
            pa1 = make_float4(0.f,0.f,0.f,0.f);                              \
        }                                                                    \
        const float* bp = Bm + (size_t)((k0) + bRow)*N;                      \
        if (bvec) {                                                          \
            float4 t0 = *reinterpret_cast<const float4*>(bp + bn0 + bCol);   \
            float4 t1 = *reinterpret_cast<const float4*>(bp + bn0 + bCol+4); \
            pb[0]=t0.x; pb[1]=t0.y; pb[2]=t0.z; pb[3]=t0.w;                  \
            pb[4]=t1.x; pb[5]=t1.y; pb[6]=t1.z; pb[7]=t1.w;                  \
        } else {                                                             \
            _Pragma("unroll")                                                \
            for (int j = 0; j < 8; j++) {                                    \
                int cl = bn0 + bCol + j;                                     \
                pb[j] = (cl < N) ? bp[cl] : 0.f;                             \
            }                                                                \
        }                                                                    \
    } while (0)

    TGL_LOAD(0);

    for (int k0 = 0; k0 < K; k0 += 16) {
        // stage to smem (tf32-rounded)
        As[aCol+0][aRow] = f2tf32(pa0.x);
        As[aCol+1][aRow] = f2tf32(pa0.y);
        As[aCol+2][aRow] = f2tf32(pa0.z);
        As[aCol+3][aRow] = f2tf32(pa0.w);
        As[aCol+4][aRow] = f2tf32(pa1.x);
        As[aCol+5][aRow] = f2tf32(pa1.y);
        As[aCol+6][aRow] = f2tf32(pa1.z);
        As[aCol+7][aRow] = f2tf32(pa1.w);
        #pragma unroll
        for (int j = 0; j < 8; j++) Bs[bRow][bCol+j] = f2tf32(pb[j]);
        __syncthreads();

        if (k0 + 16 < K) TGL_LOAD(k0 + 16);   // prefetch next tile (overlaps MMA)

        #pragma unroll
        for (int ks = 0; ks < 2; ks++) {
            int kr = ks*8 + (lane & 3);
            int mc = lane >> 2;
            uint32_t af[2][4], bf[8][2];
            #pragma unroll
            for (int mt = 0; mt < 2; mt++) {
                af[mt][0] = As[kr  ][wm + mt*16 + mc];
                af[mt][1] = As[kr  ][wm + mt*16 + 8 + mc];
                af[mt][2] = As[kr+4][wm + mt*16 + mc];
                af[mt][3] = As[kr+4][wm + mt*16 + 8 + mc];
            }
            #pragma unroll
            for (int nt = 0; nt < 8; nt++) {
                bf[nt][0] = Bs[kr  ][wn + nt*8 + mc];
                bf[nt][1] = Bs[kr+4][wn + nt*8 + mc];
            }
            #pragma unroll
            for (int mt = 0; mt < 2; mt++)
                #pragma unroll
                for (int nt = 0; nt < 8; nt++)
                    mma_tf32(c[mt][nt], af[mt], bf[nt]);
        }
        __syncthreads();
    }
#undef TGL_LOAD

    // epilogue
    #pragma unroll
    for (int mt = 0; mt < 2; mt++) {
        int r0 = bm0 + wm + mt*16 + (lane >> 2);
        #pragma unroll
        for (int nt = 0; nt < 8; nt++) {
            int col = bn0 + wn + nt*8 + (lane & 3)*2;
            #pragma unroll
            for (int half = 0; half < 2; half++) {
                int r = r0 + half*8;
                if (r >= M) continue;
                #pragma unroll
                for (int cc = 0; cc < 2; cc++) {
                    int cl = col + cc;
                    if (cl >= N) continue;
                    float v = c[mt][nt][half*2 + cc];
                    if (EPI == 1) v += Cres[(size_t)r*N + cl];
                    if (EPI == 2) v = gelu_exact(v);
                    C[(size_t)r*N + cl] = v;
                }
            }
        }
    }
}

// ---------------- RoPE in place on q,k ----------------
__global__ void rope_kernel(float* __restrict__ qkv,
                            const float* __restrict__ cosT, const float* __restrict__ sinT) {
    int n = blockIdx.x;           // token
    int tid = threadIdx.x;        // 512 = 16 heads * 32 pairs
    int h = tid >> 5, j = tid & 31;
    int t = n & (TT-1);
    float c = cosT[t*32 + j], s = sinT[t*32 + j];
    #pragma unroll
    for (int cc = 0; cc < 2; cc++) {
        size_t off = (size_t)n*3*DD + cc*DD + h*HDIM + 2*j;
        float x1 = qkv[off], x2 = qkv[off+1];
        qkv[off]   = x1*c - x2*s;
        qkv[off+1] = x1*s + x2*c;
    }
}

// ---------------- attention: S = scale * Q K^T  (tf32 mma) ----------------
// grid (T/64 kt, T/64 qt, B*H), block 256; warp tile 16x32.
__global__ void __launch_bounds__(256) attn_score_mma(
        const float* __restrict__ qkv, float* __restrict__ attn) {
    __shared__ __align__(16) uint32_t Qs[64][72];   // [d][q]
    __shared__ __align__(16) uint32_t Ks[64][72];   // [d][k-token]
    int bh = blockIdx.z;
    int b = bh >> 4, h = bh & 15;
    int q0 = blockIdx.y * 64, k0 = blockIdx.x * 64;
    int tid = threadIdx.x, wid = tid >> 5, lane = tid & 31;

    int tok = tid >> 2;             // 0..63
    int dB  = (tid & 3) * 16;       // 0,16,32,48
    size_t qbase = (size_t)(b*TT + q0 + tok)*3*DD + h*HDIM + dB;
    size_t kbase = (size_t)(b*TT + k0 + tok)*3*DD + DD + h*HDIM + dB;
    #pragma unroll
    for (int j4 = 0; j4 < 4; j4++) {
        float4 qv = *reinterpret_cast<const float4*>(qkv + qbase + j4*4);
        float4 kv = *reinterpret_cast<const float4*>(qkv + kbase + j4*4);
        int d = dB + j4*4;
        Qs[d+0][tok] = f2tf32(qv.x); Qs[d+1][tok] = f2tf32(qv.y);
        Qs[d+2][tok] = f2tf32(qv.z); Qs[d+3][tok] = f2tf32(qv.w);
        Ks[d+0][tok] = f2tf32(kv.x); Ks[d+1][tok] = f2tf32(kv.y);
        Ks[d+2][tok] = f2tf32(kv.z); Ks[d+3][tok] = f2tf32(kv.w);
    }
    __syncthreads();

    int wm = (wid & 3) * 16;       // 4 warps over q
    int wn = (wid >> 2) * 32;      // 2 warps over k
    float c[4][4];
    #pragma unroll
    for (int nt = 0; nt < 4; nt++)
        #pragma unroll
        for (int i = 0; i < 4; i++) c[nt][i] = 0.f;

    int mc = lane >> 2;
    #pragma unroll
    for (int ks = 0; ks < 8; ks++) {
        int kr = ks*8 + (lane & 3);
        uint32_t af[4];
        af[0] = Qs[kr  ][wm + mc];
        af[1] = Qs[kr  ][wm + 8 + mc];
        af[2] = Qs[kr+4][wm + mc];
        af[3] = Qs[kr+4][wm + 8 + mc];
        #pragma unroll
        for (int nt = 0; nt < 4; nt++) {
            uint32_t bf[2];
            bf[0] = Ks[kr  ][wn + nt*8 + mc];
            bf[1] = Ks[kr+4][wn + nt*8 + mc];
            mma_tf32(c[nt], af, bf);
        }
    }

    const float scale = 0.125f;   // 1/sqrt(64)
    int qrow = q0 + wm + (lane >> 2);
    int col  = k0 + wn + (lane & 3)*2;
    #pragma unroll
    for (int nt = 0; nt < 4; nt++) {
        size_t o0 = ((size_t)bh*TT + qrow    )*TT + col + nt*8;
        size_t o1 = ((size_t)bh*TT + qrow + 8)*TT + col + nt*8;
        attn[o0]     = c[nt][0]*scale;
        attn[o0 + 1] = c[nt][1]*scale;
        attn[o1]     = c[nt][2]*scale;
        attn[o1 + 1] = c[nt][3]*scale;
    }
}

// ---------------- softmax over rows of length 512 ----------------
__global__ void __launch_bounds__(128) softmax_kernel(float* __restrict__ attn) {
    size_t row = blockIdx.x;
    float* p = attn + row * TT;
    int tid = threadIdx.x;
    float v[4];
    float m = -1e30f;
    #pragma unroll
    for (int i = 0; i < 4; i++) { v[i] = p[tid + i*128]; m = fmaxf(m, v[i]); }
    __shared__ float sh[4], shv[2];
    int lane = tid & 31, w = tid >> 5;
    #pragma unroll
    for (int o = 16; o > 0; o >>= 1) m = fmaxf(m, __shfl_xor_sync(0xffffffffu, m, o));
    if (lane == 0) sh[w] = m;
    __syncthreads();
    if (tid == 0) shv[0] = fmaxf(fmaxf(sh[0],sh[1]), fmaxf(sh[2],sh[3]));
    __syncthreads();
    m = shv[0];
    float s = 0.f;
    #pragma unroll
    for (int i = 0; i < 4; i++) { v[i] = expf(v[i]-m); s += v[i]; }
    #pragma unroll
    for (int o = 16; o > 0; o >>= 1) s += __shfl_xor_sync(0xffffffffu, s, o);
    if (lane == 0) sh[w] = s;
    __syncthreads();
    if (tid == 0) shv[1] = sh[0]+sh[1]+sh[2]+sh[3];
    __syncthreads();
    float inv = 1.0f / shv[1];
    #pragma unroll
    for (int i = 0; i < 4; i++) p[tid + i*128] = v[i] * inv;
}

// ---------------- O = P V  (tf32 mma) ----------------
// grid (T/64 qt, B*H), block 256; output tile 64 q x 64 d.
__global__ void __launch_bounds__(256) attn_av_mma(
        const float* __restrict__ attn, const float* __restrict__ qkv,
        float* __restrict__ o) {
    __shared__ __align__(16) uint32_t Ps[64][72];   // [k][q]  (transposed P chunk)
    __shared__ __align__(16) uint32_t Vs[64][72];   // [k][d]
    int bh = blockIdx.y;
    int b = bh >> 4, h = bh & 15;
    int q0 = blockIdx.x * 64;
    int tid = threadIdx.x, wid = tid >> 5, lane = tid & 31;

    int row = tid >> 2;             // q-row for P / token for V (0..63)
    int cB  = (tid & 3) * 16;

    int wm = (wid & 3) * 16;
    int wn = (wid >> 2) * 32;
    float c[4][4];
    #pragma unroll
    for (int nt = 0; nt < 4; nt++)
        #pragma unroll
        for (int i = 0; i < 4; i++) c[nt][i] = 0.f;

    int mc = lane >> 2;
    for (int kc = 0; kc < TT; kc += 64) {
        const float* prow = attn + ((size_t)bh*TT + q0 + row)*TT + kc + cB;
        const float* vrow = qkv + (size_t)(b*TT + kc + row)*3*DD + 2*DD + h*HDIM + cB;
        #pragma unroll
        for (int j4 = 0; j4 < 4; j4++) {
            float4 pv = *reinterpret_cast<const float4*>(prow + j4*4);
            float4 vv = *reinterpret_cast<const float4*>(vrow + j4*4);
            int k = cB + j4*4;
            Ps[k+0][row] = f2tf32(pv.x); Ps[k+1][row] = f2tf32(pv.y);
            Ps[k+2][row] = f2tf32(pv.z); Ps[k+3][row] = f2tf32(pv.w);
            Vs[row][k+0] = f2tf32(vv.x); Vs[row][k+1] = f2tf32(vv.y);
            Vs[row][k+2] = f2tf32(vv.z); Vs[row][k+3] = f2tf32(vv.w);
        }
        __syncthreads();

        #pragma unroll
        for (int ks = 0; ks < 8; ks++) {
            int kr = ks*8 + (lane & 3);
            uint32_t af[4];
            af[0] = Ps[kr  ][wm + mc];
            af[1] = Ps[kr  ][wm + 8 + mc];
            af[2] = Ps[kr+4][wm + mc];
            af[3] = Ps[kr+4][wm + 8 + mc];
            #pragma unroll
            for (int nt = 0; nt < 4; nt++) {
                uint32_t bf[2];
                bf[0] = Vs[kr  ][wn + nt*8 + mc];
                bf[1] = Vs[kr+4][wn + nt*8 + mc];
                mma_tf32(c[nt], af, bf);
            }
        }
        __syncthreads();
    }

    int qrow = q0 + wm + (lane >> 2);
    int col  = h*HDIM + wn + (lane & 3)*2;
    #pragma unroll
    for (int nt = 0; nt < 4; nt++) {
        size_t o0 = (size_t)(b*TT + qrow    )*DD + col + nt*8;
        size_t o1 = (size_t)(b*TT + qrow + 8)*DD + col + nt*8;
        o[o0]     = c[nt][0];
        o[o0 + 1] = c[nt][1];
        o[o1]     = c[nt][2];
        o[o1 + 1] = c[nt][3];
    }
}

// ---------------- gather rows t=1..511 for head ----------------
__global__ void gather_kernel(const float* __restrict__ hn, float* __restrict__ out) {
    int m = blockIdx.x;              // 0..8175
    int b = m / TOUT;
    int t = m % TOUT + 1;
    const float4* src = (const float4*)(hn + (size_t)(b*TT + t)*DD);
    float4* dst = (float4*)(out + (size_t)m*DD);
    dst[threadIdx.x] = src[threadIdx.x];
}

// ---------------- host side ----------------
static inline int cdiv(int a, int b) { return (a + b - 1) / b; }

extern "C" void kernel_launch(void* const* d_in, const int* in_sizes, int n_in,
                              void* d_out, int out_size) {
    const int*   x         = (const int*)  d_in[0];
    const int*   t         = (const int*)  d_in[1];
    const int*   level     = (const int*)  d_in[2];
    const float* tok_emb   = (const float*)d_in[3];
    const float* level_emb = (const float*)d_in[4];
    const float* time_w1   = (const float*)d_in[5];
    const float* time_b1   = (const float*)d_in[6];
    const float* time_w2   = (const float*)d_in[7];
    const float* time_b2   = (const float*)d_in[8];
    const float* ln1_g     = (const float*)d_in[9];
    const float* ln1_b     = (const float*)d_in[10];
    const float* qkv_w     = (const float*)d_in[11];
    const float* proj_w    = (const float*)d_in[12];
    const float* ln2_g     = (const float*)d_in[13];
    const float* ln2_b     = (const float*)d_in[14];
    const float* fc1_w     = (const float*)d_in[15];
    const float* fc2_w     = (const float*)d_in[16];
    const float* lnf_g     = (const float*)d_in[17];
    const float* lnf_b     = (const float*)d_in[18];
    const float* head0_w   = (const float*)d_in[19];

    float *ph, *phn, *pqkv, *po, *pattn, *pffn, *ptein, *pteh, *pte, *pcos, *psin;
    cudaGetSymbolAddress((void**)&ph,    g_h);
    cudaGetSymbolAddress((void**)&phn,   g_hn);
    cudaGetSymbolAddress((void**)&pqkv,  g_qkv);
    cudaGetSymbolAddress((void**)&po,    g_o);
    cudaGetSymbolAddress((void**)&pattn, g_attn);
    cudaGetSymbolAddress((void**)&pffn,  g_ffn);
    cudaGetSymbolAddress((void**)&ptein, g_tein);
    cudaGetSymbolAddress((void**)&pteh,  g_teh);
    cudaGetSymbolAddress((void**)&pte,   g_te);
    cudaGetSymbolAddress((void**)&pcos,  g_cos);
    cudaGetSymbolAddress((void**)&psin,  g_sin);

    // rope tables + time embedding
    rope_init_kernel<<<cdiv(TT*32, 512), 512>>>(pcos, psin);
    te_in_kernel<<<BB, 512>>>(t, ptein);
    tgemm_kernel<2><<<cdiv(DFF,128), 128>>>(ptein, time_w1, time_b1, pteh, DD, DFF);
    tgemm_kernel<0><<<cdiv(DD,128), 128>>>(pteh, time_w2, time_b2, pte, DFF, DD);

    // token + level + time embedding
    embed_kernel<<<NTOK, 256>>>(x, level, tok_emb, level_emb, pte, ph);

    dim3 blk(256);
    for (int i = 0; i < LL; i++) {
        layernorm_kernel<<<NTOK, 256>>>(ph, ln1_g + i*DD, ln1_b + i*DD, phn);

        tf32gemm_kernel<0><<<dim3(cdiv(3*DD,128), cdiv(NTOK,128)), blk>>>(
            phn, qkv_w + (size_t)i*DD*3*DD, nullptr, pqkv, NTOK, 3*DD, DD);

        rope_kernel<<<NTOK, 512>>>(pqkv, pcos, psin);

        attn_score_mma<<<dim3(TT/64, TT/64, BB*HH), blk>>>(pqkv, pattn);
        softmax_kernel<<<BB*HH*TT, 128>>>(pattn);
        attn_av_mma<<<dim3(TT/64, BB*HH), blk>>>(pattn, pqkv, po);

        tf32gemm_kernel<1><<<dim3(cdiv(DD,128), cdiv(NTOK,128)), blk>>>(
            po, proj_w + (size_t)i*DD*DD, ph, ph, NTOK, DD, DD);

        layernorm_kernel<<<NTOK, 256>>>(ph, ln2_g + i*DD, ln2_b + i*DD, phn);

        tf32gemm_kernel<2><<<dim3(cdiv(DFF,128), cdiv(NTOK,128)), blk>>>(
            phn, fc1_w + (size_t)i*DD*DFF, nullptr, pffn, NTOK, DFF, DD);

        tf32gemm_kernel<1><<<dim3(cdiv(DD,128), cdiv(NTOK,128)), blk>>>(
            pffn, fc2_w + (size_t)i*DFF*DD, ph, ph, NTOK, DD, DFF);
    }

    layernorm_kernel<<<NTOK, 256>>>(ph, lnf_g, lnf_b, phn);
    gather_kernel<<<NHEADROWS, 256>>>(phn, po);
    tf32gemm_kernel<0><<<dim3(cdiv(V0,128), cdiv(NHEADROWS,128)), blk>>>(
        po, head0_w, nullptr, (float*)d_out, NHEADROWS, V0, DD);
}

// round 4
// speedup vs baseline: 2.5600x; 1.1233x over previous
#include <cuda_runtime.h>
#include <cuda_bf16.h>
#include <math.h>
#include <stdint.h>

// ---------------- problem constants ----------------
#define BB   16
#define TT   512
#define NTOK (BB*TT)        // 8192
#define DD   1024
#define HH   16
#define HDIM 64
#define LL   12
#define DFF  4096
#define V0   1025
#define TOUT 511
#define NHEADROWS (BB*TOUT) // 8176

// ---------------- scratch (device globals; no allocation allowed) -------
__device__ float g_h   [NTOK*DD];
__device__ float g_hn  [NTOK*DD];
__device__ float g_qkv [NTOK*3*DD];
__device__ float g_o   [NTOK*DD];
__device__ float g_attn[(size_t)BB*HH*TT*TT];
__device__ float g_ffn [NTOK*DFF];
__device__ float g_tein[BB*DD];
__device__ float g_teh [BB*DFF];
__device__ float g_te  [BB*DD];
__device__ float g_cos [TT*32];
__device__ float g_sin [TT*32];
// tf32-pre-rounded weight copies
__device__ float g_qkvw [LL*DD*3*DD];
__device__ float g_projw[LL*DD*DD];
__device__ float g_fc1w [LL*DD*DFF];
__device__ float g_fc2w [LL*DFF*DD];

__device__ __forceinline__ float gelu_exact(float x) {
    return 0.5f * x * (1.0f + erff(x * 0.70710678118654752440f));
}
__device__ __forceinline__ uint32_t f2tf32(float x) {
    uint32_t r; asm("cvt.rna.tf32.f32 %0, %1;" : "=r"(r) : "f"(x)); return r;
}
__device__ __forceinline__ float roundtf(float x) { return __uint_as_float(f2tf32(x)); }

__device__ __forceinline__ void mma_tf32(float* c, const uint32_t* a, const uint32_t* b) {
    asm volatile(
        "mma.sync.aligned.m16n8k8.row.col.f32.tf32.tf32.f32 "
        "{%0,%1,%2,%3}, {%4,%5,%6,%7}, {%8,%9}, {%0,%1,%2,%3};"
        : "+f"(c[0]), "+f"(c[1]), "+f"(c[2]), "+f"(c[3])
        : "r"(a[0]), "r"(a[1]), "r"(a[2]), "r"(a[3]), "r"(b[0]), "r"(b[1]));
}

__device__ __forceinline__ void cp_async16(uint32_t saddr, const void* gptr) {
    asm volatile("cp.async.cg.shared.global [%0], [%1], 16;\n" :: "r"(saddr), "l"(gptr));
}
__device__ __forceinline__ uint32_t sptr(const void* p) {
    return (uint32_t)__cvta_generic_to_shared(p);
}

// ---------------- weight pre-round (RNA tf32) ----------------
__global__ void round_kernel(const float* __restrict__ src, float* __restrict__ dst, int n4) {
    int i = blockIdx.x * blockDim.x + threadIdx.x;
    int stride = gridDim.x * blockDim.x;
    for (; i < n4; i += stride) {
        float4 v = ((const float4*)src)[i];
        v.x = roundtf(v.x); v.y = roundtf(v.y); v.z = roundtf(v.z); v.w = roundtf(v.w);
        ((float4*)dst)[i] = v;
    }
}

// ---------------- rope tables ----------------
__global__ void rope_init_kernel(float* cosT, float* sinT) {
    int idx = blockIdx.x * blockDim.x + threadIdx.x;
    if (idx >= TT*32) return;
    int t = idx >> 5, j = idx & 31;
    float freq = expf(-(float)j * (logf(10000.0f) / 32.0f));
    float ang = (float)t * freq;
    cosT[idx] = cosf(ang);
    sinT[idx] = sinf(ang);
}

// ---------------- time embedding ----------------
__global__ void te_in_kernel(const int* __restrict__ t, float* __restrict__ out) {
    int b = blockIdx.x;
    int j = threadIdx.x;
    float tv = (float)t[b];
    float e  = expf((float)j * (-logf(10000.0f) / 511.0f));
    float v  = tv * e;
    out[b*DD + j]       = sinf(v);
    out[b*DD + 512 + j] = cosf(v);
}

template<int EPI>  // 0 = bias only, 2 = gelu(bias+)
__global__ void tgemm_kernel(const float* __restrict__ A, const float* __restrict__ Bw,
                             const float* __restrict__ bias, float* __restrict__ C,
                             int K, int N) {
    int n = blockIdx.x * blockDim.x + threadIdx.x;
    if (n >= N) return;
    float acc[16];
    #pragma unroll
    for (int m = 0; m < 16; m++) acc[m] = 0.f;
    for (int k = 0; k < K; k++) {
        float bv = Bw[(size_t)k*N + n];
        #pragma unroll
        for (int m = 0; m < 16; m++) acc[m] += A[m*K + k] * bv;
    }
    float bs = bias[n];
    #pragma unroll
    for (int m = 0; m < 16; m++) {
        float v = acc[m] + bs;
        if (EPI == 2) v = gelu_exact(v);
        C[(size_t)m*N + n] = v;
    }
}

// ---------------- embedding ----------------
__global__ void embed_kernel(const int* __restrict__ x, const int* __restrict__ level,
                             const float* __restrict__ tok_emb, const float* __restrict__ level_emb,
                             const float* __restrict__ te, float* __restrict__ h) {
    int n = blockIdx.x;
    int b = n >> 9;
    int lvl = level[0];
    const float4* tk = (const float4*)(tok_emb + (size_t)x[n]*DD);
    const float4* le = (const float4*)(level_emb + (size_t)lvl*DD);
    const float4* tv = (const float4*)(te + (size_t)b*DD);
    float4* out = (float4*)(h + (size_t)n*DD);
    int i = threadIdx.x;
    float4 a = tk[i], c = le[i], d = tv[i];
    out[i] = make_float4(a.x+c.x+d.x, a.y+c.y+d.y, a.z+c.z+d.z, a.w+c.w+d.w);
}

// ---------------- layernorm (row of 1024), output RNA-tf32-rounded -------
__global__ void __launch_bounds__(256) layernorm_kernel(
        const float* __restrict__ x, const float* __restrict__ g,
        const float* __restrict__ b, float* __restrict__ y) {
    size_t row = blockIdx.x;
    int tid = threadIdx.x;
    const float4* xr = (const float4*)(x + row*DD);
    float4 v = xr[tid];
    float s  = v.x + v.y + v.z + v.w;
    float ss = v.x*v.x + v.y*v.y + v.z*v.z + v.w*v.w;
    __shared__ float sh1[8], sh2[8], shm[2];
    int lane = tid & 31, w = tid >> 5;
    #pragma unroll
    for (int o = 16; o > 0; o >>= 1) {
        s  += __shfl_xor_sync(0xffffffffu, s,  o);
        ss += __shfl_xor_sync(0xffffffffu, ss, o);
    }
    if (lane == 0) { sh1[w] = s; sh2[w] = ss; }
    __syncthreads();
    if (tid == 0) {
        float ts = 0.f, tss = 0.f;
        #pragma unroll
        for (int i = 0; i < 8; i++) { ts += sh1[i]; tss += sh2[i]; }
        float mean = ts * (1.0f/DD);
        float var  = tss * (1.0f/DD) - mean*mean;
        shm[0] = mean;
        shm[1] = rsqrtf(var + 1e-5f);
    }
    __syncthreads();
    float mean = shm[0], rs = shm[1];
    float4 gg = ((const float4*)g)[tid];
    float4 bb = ((const float4*)b)[tid];
    float4 o;
    o.x = roundtf((v.x-mean)*rs*gg.x + bb.x);
    o.y = roundtf((v.y-mean)*rs*gg.y + bb.y);
    o.z = roundtf((v.z-mean)*rs*gg.z + bb.z);
    o.w = roundtf((v.w-mean)*rs*gg.w + bb.w);
    ((float4*)(y + row*DD))[tid] = o;
}

// =======================================================================
// Fast tf32 GEMM: C = A[MxK] @ B[KxN]. Requires M%128==0, N%128==0, K%16==0.
// Inputs must already be RNA-tf32-rounded. 4-stage cp.async pipeline.
// EPI: 1 = +residual (no round), 2 = gelu (round), 3 = rope-on-qkv (round)
// =======================================================================
#define MG_SMEM 75776
template<int EPI>
__global__ void __launch_bounds__(256) mgemm_kernel(
        const float* __restrict__ A, const float* __restrict__ B,
        const float* __restrict__ Cres, float* __restrict__ C,
        int N, int K,
        const float* __restrict__ cosT, const float* __restrict__ sinT) {
    extern __shared__ float smem[];
    float* As = smem;                 // 4 stages x 128 rows x pitch 20
    float* Bs = smem + 4*2560;        // 4 stages x 16 rows  x pitch 136

    int tid = threadIdx.x;
    int bn0 = blockIdx.x * 128;
    int bm0 = blockIdx.y * 128;
    int wid = tid >> 5, lane = tid & 31;
    int wm = (wid & 3) * 32;
    int wn = (wid >> 2) * 64;
    int mc = lane >> 2;
    int lk = lane & 3;

    float c[2][8][4];
    #pragma unroll
    for (int mt = 0; mt < 2; mt++)
        #pragma unroll
        for (int nt = 0; nt < 8; nt++)
            #pragma unroll
            for (int i = 0; i < 4; i++) c[mt][nt][i] = 0.f;

    int NIT = K >> 4;

    auto issue_stage = [&](int it) {
        int k0 = it << 4;
        float* as = As + (it & 3) * 2560;
        float* bs = Bs + (it & 3) * 2176;
        #pragma unroll
        for (int j = 0; j < 2; j++) {
            int ch = (tid << 1) + j;
            int row = ch >> 2, q = (ch & 3) << 2;
            cp_async16(sptr(as + row*20 + q),
                       A + (size_t)(bm0 + row)*K + k0 + q);
        }
        #pragma unroll
        for (int j = 0; j < 2; j++) {
            int ch = (tid << 1) + j;
            int k = ch >> 5, q = (ch & 31) << 2;
            cp_async16(sptr(bs + k*136 + q),
                       B + (size_t)(k0 + k)*N + bn0 + q);
        }
    };

    issue_stage(0); asm volatile("cp.async.commit_group;\n");
    issue_stage(1); asm volatile("cp.async.commit_group;\n");
    issue_stage(2); asm volatile("cp.async.commit_group;\n");

    for (int it = 0; it < NIT; it++) {
        asm volatile("cp.async.wait_group 2;\n");
        __syncthreads();
        if (it + 3 < NIT) issue_stage(it + 3);
        asm volatile("cp.async.commit_group;\n");

        const float* as = As + (it & 3) * 2560;
        const float* bs = Bs + (it & 3) * 2176;
        #pragma unroll
        for (int ks = 0; ks < 2; ks++) {
            int kr = ks*8 + lk;
            uint32_t af[2][4], bf[8][2];
            #pragma unroll
            for (int mt = 0; mt < 2; mt++) {
                const float* a0 = as + (wm + mt*16 + mc)*20;
                const float* a1 = as + (wm + mt*16 + 8 + mc)*20;
                af[mt][0] = __float_as_uint(a0[kr]);
                af[mt][1] = __float_as_uint(a1[kr]);
                af[mt][2] = __float_as_uint(a0[kr+4]);
                af[mt][3] = __float_as_uint(a1[kr+4]);
            }
            #pragma unroll
            for (int nt = 0; nt < 8; nt++) {
                bf[nt][0] = __float_as_uint(bs[kr*136     + wn + nt*8 + mc]);
                bf[nt][1] = __float_as_uint(bs[(kr+4)*136 + wn + nt*8 + mc]);
            }
            #pragma unroll
            for (int mt = 0; mt < 2; mt++)
                #pragma unroll
                for (int nt = 0; nt < 8; nt++)
                    mma_tf32(c[mt][nt], af[mt], bf[nt]);
        }
        __syncthreads();
    }

    // ---------------- epilogue ----------------
    #pragma unroll
    for (int mt = 0; mt < 2; mt++) {
        int r0 = bm0 + wm + mt*16 + mc;
        #pragma unroll
        for (int nt = 0; nt < 8; nt++) {
            int col = bn0 + wn + nt*8 + lk*2;
            #pragma unroll
            for (int half = 0; half < 2; half++) {
                int r = r0 + half*8;
                float v0 = c[mt][nt][half*2 + 0];
                float v1 = c[mt][nt][half*2 + 1];
                if (EPI == 1) {
                    const float2 res = *reinterpret_cast<const float2*>(Cres + (size_t)r*N + col);
                    v0 += res.x; v1 += res.y;
                } else if (EPI == 2) {
                    v0 = roundtf(gelu_exact(v0));
                    v1 = roundtf(gelu_exact(v1));
                } else if (EPI == 3) {
                    if (col < 2*DD) {   // q or k region: apply rope to the (even,odd) pair
                        int j = (col & 63) >> 1;
                        int t = r & (TT-1);
                        float cc = cosT[t*32 + j], ss = sinT[t*32 + j];
                        float x1 = v0, x2 = v1;
                        v0 = x1*cc - x2*ss;
                        v1 = x1*ss + x2*cc;
                    }
                    v0 = roundtf(v0); v1 = roundtf(v1);
                }
                *reinterpret_cast<float2*>(C + (size_t)r*N + col) = make_float2(v0, v1);
            }
        }
    }
}

// ---------------- reference tf32 GEMM (bounds-checked) for head ----------
template<int EPI>   // 0 none
__global__ void __launch_bounds__(256) tf32gemm_kernel(
        const float* __restrict__ A, const float* __restrict__ Bm,
        const float* __restrict__ Cres, float* __restrict__ C,
        int M, int N, int K) {
    __shared__ __align__(16) uint32_t As[16][136];
    __shared__ __align__(16) uint32_t Bs[16][136];
    int tid = threadIdx.x;
    int bn0 = blockIdx.x * 128;
    int bm0 = blockIdx.y * 128;
    int wid = tid >> 5, lane = tid & 31;
    int wm = (wid & 3) * 32;
    int wn = (wid >> 2) * 64;

    float c[2][8][4];
    #pragma unroll
    for (int mt = 0; mt < 2; mt++)
        #pragma unroll
        for (int nt = 0; nt < 8; nt++)
            #pragma unroll
            for (int i = 0; i < 4; i++) c[mt][nt][i] = 0.f;

    int aRow = tid >> 1;
    int aCol = (tid & 1) * 8;
    int bRow = tid >> 4;
    int bCol = (tid & 15) * 8;
    bool aValid = (bm0 + aRow) < M;

    float4 pa0, pa1;
    float  pb[8];

#define TGL_LOAD(k0) do {                                                    \
        if (aValid) {                                                        \
            const float* ap = A + (size_t)(bm0 + aRow)*K + (k0) + aCol;      \
            pa0 = *reinterpret_cast<const float4*>(ap);                      \
            pa1 = *reinterpret_cast<const float4*>(ap + 4);                  \
        } else {                                                             \
            pa0 = make_float4(0.f,0.f,0.f,0.f);                              \
            pa1 = make_float4(0.f,0.f,0.f,0.f);                              \
        }                                                                    \
        const float* bp = Bm + (size_t)((k0) + bRow)*N;                      \
        _Pragma("unroll")                                                    \
        for (int j = 0; j < 8; j++) {                                        \
            int cl = bn0 + bCol + j;                                         \
            pb[j] = (cl < N) ? bp[cl] : 0.f;                                 \
        }                                                                    \
    } while (0)

    TGL_LOAD(0);

    for (int k0 = 0; k0 < K; k0 += 16) {
        As[aCol+0][aRow] = f2tf32(pa0.x);
        As[aCol+1][aRow] = f2tf32(pa0.y);
        As[aCol+2][aRow] = f2tf32(pa0.z);
        As[aCol+3][aRow] = f2tf32(pa0.w);
        As[aCol+4][aRow] = f2tf32(pa1.x);
        As[aCol+5][aRow] = f2tf32(pa1.y);
        As[aCol+6][aRow] = f2tf32(pa1.z);
        As[aCol+7][aRow] = f2tf32(pa1.w);
        #pragma unroll
        for (int j = 0; j < 8; j++) Bs[bRow][bCol+j] = f2tf32(pb[j]);
        __syncthreads();

        if (k0 + 16 < K) TGL_LOAD(k0 + 16);

        #pragma unroll
        for (int ks = 0; ks < 2; ks++) {
            int kr = ks*8 + (lane & 3);
            int mc = lane >> 2;
            uint32_t af[2][4], bf[8][2];
            #pragma unroll
            for (int mt = 0; mt < 2; mt++) {
                af[mt][0] = As[kr  ][wm + mt*16 + mc];
                af[mt][1] = As[kr  ][wm + mt*16 + 8 + mc];
                af[mt][2] = As[kr+4][wm + mt*16 + mc];
                af[mt][3] = As[kr+4][wm + mt*16 + 8 + mc];
            }
            #pragma unroll
            for (int nt = 0; nt < 8; nt++) {
                bf[nt][0] = Bs[kr  ][wn + nt*8 + mc];
                bf[nt][1] = Bs[kr+4][wn + nt*8 + mc];
            }
            #pragma unroll
            for (int mt = 0; mt < 2; mt++)
                #pragma unroll
                for (int nt = 0; nt < 8; nt++)
                    mma_tf32(c[mt][nt], af[mt], bf[nt]);
        }
        __syncthreads();
    }
#undef TGL_LOAD

    #pragma unroll
    for (int mt = 0; mt < 2; mt++) {
        int r0 = bm0 + wm + mt*16 + (lane >> 2);
        #pragma unroll
        for (int nt = 0; nt < 8; nt++) {
            int col = bn0 + wn + nt*8 + (lane & 3)*2;
            #pragma unroll
            for (int half = 0; half < 2; half++) {
                int r = r0 + half*8;
                if (r >= M) continue;
                #pragma unroll
                for (int cc = 0; cc < 2; cc++) {
                    int cl = col + cc;
                    if (cl >= N) continue;
                    C[(size_t)r*N + cl] = c[mt][nt][half*2 + cc];
                }
            }
        }
    }
}

// ---------------- attention: S = scale * Q K^T (tf32 mma) ----------------
__global__ void __launch_bounds__(256) attn_score_mma(
        const float* __restrict__ qkv, float* __restrict__ attn) {
    __shared__ __align__(16) uint32_t Qs[64][72];
    __shared__ __align__(16) uint32_t Ks[64][72];
    int bh = blockIdx.z;
    int b = bh >> 4, h = bh & 15;
    int q0 = blockIdx.y * 64, k0 = blockIdx.x * 64;
    int tid = threadIdx.x, wid = tid >> 5, lane = tid & 31;

    int tok = tid >> 2;
    int dB  = (tid & 3) * 16;
    size_t qbase = (size_t)(b*TT + q0 + tok)*3*DD + h*HDIM + dB;
    size_t kbase = (size_t)(b*TT + k0 + tok)*3*DD + DD + h*HDIM + dB;
    #pragma unroll
    for (int j4 = 0; j4 < 4; j4++) {
        float4 qv = *reinterpret_cast<const float4*>(qkv + qbase + j4*4);
        float4 kv = *reinterpret_cast<const float4*>(qkv + kbase + j4*4);
        int d = dB + j4*4;
        Qs[d+0][tok] = __float_as_uint(qv.x); Qs[d+1][tok] = __float_as_uint(qv.y);
        Qs[d+2][tok] = __float_as_uint(qv.z); Qs[d+3][tok] = __float_as_uint(qv.w);
        Ks[d+0][tok] = __float_as_uint(kv.x); Ks[d+1][tok] = __float_as_uint(kv.y);
        Ks[d+2][tok] = __float_as_uint(kv.z); Ks[d+3][tok] = __float_as_uint(kv.w);
    }
    __syncthreads();

    int wm = (wid & 3) * 16;
    int wn = (wid >> 2) * 32;
    float c[4][4];
    #pragma unroll
    for (int nt = 0; nt < 4; nt++)
        #pragma unroll
        for (int i = 0; i < 4; i++) c[nt][i] = 0.f;

    int mc = lane >> 2;
    #pragma unroll
    for (int ks = 0; ks < 8; ks++) {
        int kr = ks*8 + (lane & 3);
        uint32_t af[4];
        af[0] = Qs[kr  ][wm + mc];
        af[1] = Qs[kr  ][wm + 8 + mc];
        af[2] = Qs[kr+4][wm + mc];
        af[3] = Qs[kr+4][wm + 8 + mc];
        #pragma unroll
        for (int nt = 0; nt < 4; nt++) {
            uint32_t bf[2];
            bf[0] = Ks[kr  ][wn + nt*8 + mc];
            bf[1] = Ks[kr+4][wn + nt*8 + mc];
            mma_tf32(c[nt], af, bf);
        }
    }

    const float scale = 0.125f;
    int qrow = q0 + wm + (lane >> 2);
    int col  = k0 + wn + (lane & 3)*2;
    #pragma unroll
    for (int nt = 0; nt < 4; nt++) {
        size_t o0 = ((size_t)bh*TT + qrow    )*TT + col + nt*8;
        size_t o1 = ((size_t)bh*TT + qrow + 8)*TT + col + nt*8;
        attn[o0]     = c[nt][0]*scale;
        attn[o0 + 1] = c[nt][1]*scale;
        attn[o1]     = c[nt][2]*scale;
        attn[o1 + 1] = c[nt][3]*scale;
    }
}

// ---------------- softmax over rows of length 512, rounded output -------
__global__ void __launch_bounds__(128) softmax_kernel(float* __restrict__ attn) {
    size_t row = blockIdx.x;
    float* p = attn + row * TT;
    int tid = threadIdx.x;
    float v[4];
    float m = -1e30f;
    #pragma unroll
    for (int i = 0; i < 4; i++) { v[i] = p[tid + i*128]; m = fmaxf(m, v[i]); }
    __shared__ float sh[4], shv[2];
    int lane = tid & 31, w = tid >> 5;
    #pragma unroll
    for (int o = 16; o > 0; o >>= 1) m = fmaxf(m, __shfl_xor_sync(0xffffffffu, m, o));
    if (lane == 0) sh[w] = m;
    __syncthreads();
    if (tid == 0) shv[0] = fmaxf(fmaxf(sh[0],sh[1]), fmaxf(sh[2],sh[3]));
    __syncthreads();
    m = shv[0];
    float s = 0.f;
    #pragma unroll
    for (int i = 0; i < 4; i++) { v[i] = expf(v[i]-m); s += v[i]; }
    #pragma unroll
    for (int o = 16; o > 0; o >>= 1) s += __shfl_xor_sync(0xffffffffu, s, o);
    if (lane == 0) sh[w] = s;
    __syncthreads();
    if (tid == 0) shv[1] = sh[0]+sh[1]+sh[2]+sh[3];
    __syncthreads();
    float inv = 1.0f / shv[1];
    #pragma unroll
    for (int i = 0; i < 4; i++) p[tid + i*128] = roundtf(v[i] * inv);
}

// ---------------- O = P V (tf32 mma), rounded output ----------------
__global__ void __launch_bounds__(256) attn_av_mma(
        const float* __restrict__ attn, const float* __restrict__ qkv,
        float* __restrict__ o) {
    __shared__ __align__(16) uint32_t Ps[64][72];
    __shared__ __align__(16) uint32_t Vs[64][72];
    int bh = blockIdx.y;
    int b = bh >> 4, h = bh & 15;
    int q0 = blockIdx.x * 64;
    int tid = threadIdx.x, wid = tid >> 5, lane = tid & 31;

    int row = tid >> 2;
    int cB  = (tid & 3) * 16;

    int wm = (wid & 3) * 16;
    int wn = (wid >> 2) * 32;
    float c[4][4];
    #pragma unroll
    for (int nt = 0; nt < 4; nt++)
        #pragma unroll
        for (int i = 0; i < 4; i++) c[nt][i] = 0.f;

    int mc = lane >> 2;
    for (int kc = 0; kc < TT; kc += 64) {
        const float* prow = attn + ((size_t)bh*TT + q0 + row)*TT + kc + cB;
        const float* vrow = qkv + (size_t)(b*TT + kc + row)*3*DD + 2*DD + h*HDIM + cB;
        #pragma unroll
        for (int j4 = 0; j4 < 4; j4++) {
            float4 pv = *reinterpret_cast<const float4*>(prow + j4*4);
            float4 vv = *reinterpret_cast<const float4*>(vrow + j4*4);
            int k = cB + j4*4;
            Ps[k+0][row] = __float_as_uint(pv.x); Ps[k+1][row] = __float_as_uint(pv.y);
            Ps[k+2][row] = __float_as_uint(pv.z); Ps[k+3][row] = __float_as_uint(pv.w);
            Vs[row][k+0] = __float_as_uint(vv.x); Vs[row][k+1] = __float_as_uint(vv.y);
            Vs[row][k+2] = __float_as_uint(vv.z); Vs[row][k+3] = __float_as_uint(vv.w);
        }
        __syncthreads();

        #pragma unroll
        for (int ks = 0; ks < 8; ks++) {
            int kr = ks*8 + (lane & 3);
            uint32_t af[4];
            af[0] = Ps[kr  ][wm + mc];
            af[1] = Ps[kr  ][wm + 8 + mc];
            af[2] = Ps[kr+4][wm + mc];
            af[3] = Ps[kr+4][wm + 8 + mc];
            #pragma unroll
            for (int nt = 0; nt < 4; nt++) {
                uint32_t bf[2];
                bf[0] = Vs[kr  ][wn + nt*8 + mc];
                bf[1] = Vs[kr+4][wn + nt*8 + mc];
                mma_tf32(c[nt], af, bf);
            }
        }
        __syncthreads();
    }

    int qrow = q0 + wm + (lane >> 2);
    int col  = h*HDIM + wn + (lane & 3)*2;
    #pragma unroll
    for (int nt = 0; nt < 4; nt++) {
        size_t o0 = (size_t)(b*TT + qrow    )*DD + col + nt*8;
        size_t o1 = (size_t)(b*TT + qrow + 8)*DD + col + nt*8;
        o[o0]     = roundtf(c[nt][0]);
        o[o0 + 1] = roundtf(c[nt][1]);
        o[o1]     = roundtf(c[nt][2]);
        o[o1 + 1] = roundtf(c[nt][3]);
    }
}

// ---------------- gather rows t=1..511 for head ----------------
__global__ void gather_kernel(const float* __restrict__ hn, float* __restrict__ out) {
    int m = blockIdx.x;
    int b = m / TOUT;
    int t = m % TOUT + 1;
    const float4* src = (const float4*)(hn + (size_t)(b*TT + t)*DD);
    float4* dst = (float4*)(out + (size_t)m*DD);
    dst[threadIdx.x] = src[threadIdx.x];
}

// ---------------- host side ----------------
static inline int cdiv(int a, int b) { return (a + b - 1) / b; }

extern "C" void kernel_launch(void* const* d_in, const int* in_sizes, int n_in,
                              void* d_out, int out_size) {
    const int*   x         = (const int*)  d_in[0];
    const int*   t         = (const int*)  d_in[1];
    const int*   level     = (const int*)  d_in[2];
    const float* tok_emb   = (const float*)d_in[3];
    const float* level_emb = (const float*)d_in[4];
    const float* time_w1   = (const float*)d_in[5];
    const float* time_b1   = (const float*)d_in[6];
    const float* time_w2   = (const float*)d_in[7];
    const float* time_b2   = (const float*)d_in[8];
    const float* ln1_g     = (const float*)d_in[9];
    const float* ln1_b     = (const float*)d_in[10];
    const float* qkv_w     = (const float*)d_in[11];
    const float* proj_w    = (const float*)d_in[12];
    const float* ln2_g     = (const float*)d_in[13];
    const float* ln2_b     = (const float*)d_in[14];
    const float* fc1_w     = (const float*)d_in[15];
    const float* fc2_w     = (const float*)d_in[16];
    const float* lnf_g     = (const float*)d_in[17];
    const float* lnf_b     = (const float*)d_in[18];
    const float* head0_w   = (const float*)d_in[19];

    float *ph, *phn, *pqkv, *po, *pattn, *pffn, *ptein, *pteh, *pte, *pcos, *psin;
    float *pqkvw, *pprojw, *pfc1w, *pfc2w;
    cudaGetSymbolAddress((void**)&ph,    g_h);
    cudaGetSymbolAddress((void**)&phn,   g_hn);
    cudaGetSymbolAddress((void**)&pqkv,  g_qkv);
    cudaGetSymbolAddress((void**)&po,    g_o);
    cudaGetSymbolAddress((void**)&pattn, g_attn);
    cudaGetSymbolAddress((void**)&pffn,  g_ffn);
    cudaGetSymbolAddress((void**)&ptein, g_tein);
    cudaGetSymbolAddress((void**)&pteh,  g_teh);
    cudaGetSymbolAddress((void**)&pte,   g_te);
    cudaGetSymbolAddress((void**)&pcos,  g_cos);
    cudaGetSymbolAddress((void**)&psin,  g_sin);
    cudaGetSymbolAddress((void**)&pqkvw, g_qkvw);
    cudaGetSymbolAddress((void**)&pprojw,g_projw);
    cudaGetSymbolAddress((void**)&pfc1w, g_fc1w);
    cudaGetSymbolAddress((void**)&pfc2w, g_fc2w);

    cudaFuncSetAttribute(mgemm_kernel<1>, cudaFuncAttributeMaxDynamicSharedMemorySize, MG_SMEM);
    cudaFuncSetAttribute(mgemm_kernel<2>, cudaFuncAttributeMaxDynamicSharedMemorySize, MG_SMEM);
    cudaFuncSetAttribute(mgemm_kernel<3>, cudaFuncAttributeMaxDynamicSharedMemorySize, MG_SMEM);

    // weight pre-rounding (RNA tf32)
    round_kernel<<<2048, 256>>>(qkv_w,  pqkvw,  LL*DD*3*DD/4);
    round_kernel<<<2048, 256>>>(proj_w, pprojw, LL*DD*DD/4);
    round_kernel<<<2048, 256>>>(fc1_w,  pfc1w,  LL*DD*DFF/4);
    round_kernel<<<2048, 256>>>(fc2_w,  pfc2w,  LL*DFF*DD/4);

    // rope tables + time embedding
    rope_init_kernel<<<cdiv(TT*32, 512), 512>>>(pcos, psin);
    te_in_kernel<<<BB, 512>>>(t, ptein);
    tgemm_kernel<2><<<cdiv(DFF,128), 128>>>(ptein, time_w1, time_b1, pteh, DD, DFF);
    tgemm_kernel<0><<<cdiv(DD,128), 128>>>(pteh, time_w2, time_b2, pte, DFF, DD);

    // token + level + time embedding
    embed_kernel<<<NTOK, 256>>>(x, level, tok_emb, level_emb, pte, ph);

    dim3 blk(256);
    for (int i = 0; i < LL; i++) {
        layernorm_kernel<<<NTOK, 256>>>(ph, ln1_g + i*DD, ln1_b + i*DD, phn);

        // qkv gemm + fused rope + round
        mgemm_kernel<3><<<dim3(3*DD/128, NTOK/128), blk, MG_SMEM>>>(
            phn, pqkvw + (size_t)i*DD*3*DD, nullptr, pqkv, 3*DD, DD, pcos, psin);

        attn_score_mma<<<dim3(TT/64, TT/64, BB*HH), blk>>>(pqkv, pattn);
        softmax_kernel<<<BB*HH*TT, 128>>>(pattn);
        attn_av_mma<<<dim3(TT/64, BB*HH), blk>>>(pattn, pqkv, po);

        mgemm_kernel<1><<<dim3(DD/128, NTOK/128), blk, MG_SMEM>>>(
            po, pprojw + (size_t)i*DD*DD, ph, ph, DD, DD, pcos, psin);

        layernorm_kernel<<<NTOK, 256>>>(ph, ln2_g + i*DD, ln2_b + i*DD, phn);

        mgemm_kernel<2><<<dim3(DFF/128, NTOK/128), blk, MG_SMEM>>>(
            phn, pfc1w + (size_t)i*DD*DFF, nullptr, pffn, DFF, DD, pcos, psin);

        mgemm_kernel<1><<<dim3(DD/128, NTOK/128), blk, MG_SMEM>>>(
            pffn, pfc2w + (size_t)i*DFF*DD, ph, ph, DD, DFF, pcos, psin);
    }

    layernorm_kernel<<<NTOK, 256>>>(ph, lnf_g, lnf_b, phn);
    gather_kernel<<<NHEADROWS, 256>>>(phn, po);
    tf32gemm_kernel<0><<<dim3(cdiv(V0,128), cdiv(NHEADROWS,128)), blk>>>(
        po, head0_w, nullptr, (float*)d_out, NHEADROWS, V0, DD);
}

// round 6
// speedup vs baseline: 4.1889x; 1.6363x over previous
#include <cuda_runtime.h>
#include <cuda_fp16.h>
#include <math.h>
#include <stdint.h>

// ---------------- problem constants ----------------
#define BB   16
#define TT   512
#define NTOK (BB*TT)        // 8192
#define DD   1024
#define HH   16
#define HDIM 64
#define LL   12
#define DFF  4096
#define V0   1025
#define TOUT 511
#define NHEADROWS (BB*TOUT) // 8176

// ---------------- scratch (device globals; no allocation allowed) -------
__device__ float  g_h    [NTOK*DD];
__device__ float  g_hn   [NTOK*DD];          // final-LN fp32 out (head path)
__device__ float  g_attn [(size_t)BB*HH*TT*TT]; // fp32 scores; later reused as head input
__device__ float  g_tein [BB*DD];
__device__ float  g_teh  [BB*DFF];
__device__ float  g_te   [BB*DD];
__device__ float  g_cos  [TT*32];
__device__ float  g_sin  [TT*32];
__device__ __half g_hnh  [NTOK*DD];          // LN out (half) for layer GEMMs
__device__ __half g_qkvh [NTOK*3*DD];
__device__ __half g_oh   [NTOK*DD];
__device__ __half g_ffnh [NTOK*DFF];
__device__ __half g_attnP[(size_t)BB*HH*TT*TT];
// transposed half weights  [L][N][K] K-major
__device__ __half g_qkvw [LL*DD*3*DD];
__device__ __half g_projw[LL*DD*DD];
__device__ __half g_fc1w [LL*DD*DFF];
__device__ __half g_fc2w [LL*DFF*DD];

__device__ __forceinline__ float gelu_exact(float x) {
    return 0.5f * x * (1.0f + erff(x * 0.70710678118654752440f));
}
__device__ __forceinline__ uint32_t f2tf32(float x) {
    uint32_t r; asm("cvt.rna.tf32.f32 %0, %1;" : "=r"(r) : "f"(x)); return r;
}

// fp16 mma: C(16x8,f32) += A(16x16,f16 row) * B(16x8,f16 col)
__device__ __forceinline__ void mma_f16(float* c, const uint32_t* a, const uint32_t* b) {
    asm volatile(
        "mma.sync.aligned.m16n8k16.row.col.f32.f16.f16.f32 "
        "{%0,%1,%2,%3}, {%4,%5,%6,%7}, {%8,%9}, {%0,%1,%2,%3};"
        : "+f"(c[0]), "+f"(c[1]), "+f"(c[2]), "+f"(c[3])
        : "r"(a[0]), "r"(a[1]), "r"(a[2]), "r"(a[3]), "r"(b[0]), "r"(b[1]));
}
// tf32 mma (head gemm only)
__device__ __forceinline__ void mma_tf32(float* c, const uint32_t* a, const uint32_t* b) {
    asm volatile(
        "mma.sync.aligned.m16n8k8.row.col.f32.tf32.tf32.f32 "
        "{%0,%1,%2,%3}, {%4,%5,%6,%7}, {%8,%9}, {%0,%1,%2,%3};"
        : "+f"(c[0]), "+f"(c[1]), "+f"(c[2]), "+f"(c[3])
        : "r"(a[0]), "r"(a[1]), "r"(a[2]), "r"(a[3]), "r"(b[0]), "r"(b[1]));
}
__device__ __forceinline__ void cp_async16(uint32_t saddr, const void* gptr) {
    asm volatile("cp.async.cg.shared.global [%0], [%1], 16;\n" :: "r"(saddr), "l"(gptr));
}

// ---------------- weight transpose + half convert: W[K,N] -> WT[N,K] ----
__global__ void transpose_half_kernel(const float* __restrict__ src, __half* __restrict__ dst,
                                      int K, int N) {
    __shared__ float tile[32][33];
    size_t loff = (size_t)blockIdx.z * K * N;
    int n0 = blockIdx.x * 32, k0 = blockIdx.y * 32;
    int tx = threadIdx.x, ty = threadIdx.y;   // 32x8
    #pragma unroll
    for (int i = 0; i < 32; i += 8)
        tile[ty+i][tx] = src[loff + (size_t)(k0+ty+i)*N + n0+tx];
    __syncthreads();
    #pragma unroll
    for (int i = 0; i < 32; i += 8)
        dst[loff + (size_t)(n0+ty+i)*K + k0+tx] = __float2half_rn(tile[tx][ty+i]);
}

// ---------------- rope tables ----------------
__global__ void rope_init_kernel(float* cosT, float* sinT) {
    int idx = blockIdx.x * blockDim.x + threadIdx.x;
    if (idx >= TT*32) return;
    int t = idx >> 5, j = idx & 31;
    float freq = expf(-(float)j * (logf(10000.0f) / 32.0f));
    float ang = (float)t * freq;
    cosT[idx] = cosf(ang);
    sinT[idx] = sinf(ang);
}

// ---------------- time embedding ----------------
__global__ void te_in_kernel(const int* __restrict__ t, float* __restrict__ out) {
    int b = blockIdx.x;
    int j = threadIdx.x;
    float tv = (float)t[b];
    float e  = expf((float)j * (-logf(10000.0f) / 511.0f));
    float v  = tv * e;
    out[b*DD + j]       = sinf(v);
    out[b*DD + 512 + j] = cosf(v);
}

template<int EPI>  // 0 = bias only, 2 = gelu(bias+)
__global__ void tgemm_kernel(const float* __restrict__ A, const float* __restrict__ Bw,
                             const float* __restrict__ bias, float* __restrict__ C,
                             int K, int N) {
    int n = blockIdx.x * blockDim.x + threadIdx.x;
    if (n >= N) return;
    float acc[16];
    #pragma unroll
    for (int m = 0; m < 16; m++) acc[m] = 0.f;
    for (int k = 0; k < K; k++) {
        float bv = Bw[(size_t)k*N + n];
        #pragma unroll
        for (int m = 0; m < 16; m++) acc[m] += A[m*K + k] * bv;
    }
    float bs = bias[n];
    #pragma unroll
    for (int m = 0; m < 16; m++) {
        float v = acc[m] + bs;
        if (EPI == 2) v = gelu_exact(v);
        C[(size_t)m*N + n] = v;
    }
}

// ---------------- embedding ----------------
__global__ void embed_kernel(const int* __restrict__ x, const int* __restrict__ level,
                             const float* __restrict__ tok_emb, const float* __restrict__ level_emb,
                             const float* __restrict__ te, float* __restrict__ h) {
    int n = blockIdx.x;
    int b = n >> 9;
    int lvl = level[0];
    const float4* tk = (const float4*)(tok_emb + (size_t)x[n]*DD);
    const float4* le = (const float4*)(level_emb + (size_t)lvl*DD);
    const float4* tv = (const float4*)(te + (size_t)b*DD);
    float4* out = (float4*)(h + (size_t)n*DD);
    int i = threadIdx.x;
    float4 a = tk[i], c = le[i], d = tv[i];
    out[i] = make_float4(a.x+c.x+d.x, a.y+c.y+d.y, a.z+c.z+d.z, a.w+c.w+d.w);
}

// ---------------- layernorm: OUTHALF=1 -> half out, 0 -> float out ------
template<int OUTHALF>
__global__ void __launch_bounds__(256) layernorm_kernel(
        const float* __restrict__ x, const float* __restrict__ g,
        const float* __restrict__ b, void* __restrict__ yv) {
    size_t row = blockIdx.x;
    int tid = threadIdx.x;
    const float4* xr = (const float4*)(x + row*DD);
    float4 v = xr[tid];
    float s  = v.x + v.y + v.z + v.w;
    float ss = v.x*v.x + v.y*v.y + v.z*v.z + v.w*v.w;
    __shared__ float sh1[8], sh2[8], shm[2];
    int lane = tid & 31, w = tid >> 5;
    #pragma unroll
    for (int o = 16; o > 0; o >>= 1) {
        s  += __shfl_xor_sync(0xffffffffu, s,  o);
        ss += __shfl_xor_sync(0xffffffffu, ss, o);
    }
    if (lane == 0) { sh1[w] = s; sh2[w] = ss; }
    __syncthreads();
    if (tid == 0) {
        float ts = 0.f, tss = 0.f;
        #pragma unroll
        for (int i = 0; i < 8; i++) { ts += sh1[i]; tss += sh2[i]; }
        float mean = ts * (1.0f/DD);
        float var  = tss * (1.0f/DD) - mean*mean;
        shm[0] = mean;
        shm[1] = rsqrtf(var + 1e-5f);
    }
    __syncthreads();
    float mean = shm[0], rs = shm[1];
    float4 gg = ((const float4*)g)[tid];
    float4 bb = ((const float4*)b)[tid];
    float o0 = (v.x-mean)*rs*gg.x + bb.x;
    float o1 = (v.y-mean)*rs*gg.y + bb.y;
    float o2 = (v.z-mean)*rs*gg.z + bb.z;
    float o3 = (v.w-mean)*rs*gg.w + bb.w;
    if (OUTHALF) {
        __half2* y = (__half2*)((__half*)yv + row*DD);
        y[tid*2+0] = __halves2half2(__float2half_rn(o0), __float2half_rn(o1));
        y[tid*2+1] = __halves2half2(__float2half_rn(o2), __float2half_rn(o3));
    } else {
        ((float4*)((float*)yv + row*DD))[tid] = make_float4(o0, o1, o2, o3);
    }
}

// =======================================================================
// fp16 GEMM: C = A[M,K] @ BT[N,K]^T.  M%128==0, N%128==0, K%32==0.
// A,BT half row-major (K-major). 128x128x32 tile, 4-stage cp.async.
// EPI: 1 = +residual(float out), 2 = gelu(half out), 3 = rope-qkv(half out)
// =======================================================================
#define HPITCH 40                 // halves per smem row (32 + 8 pad): conflict-free
#define HSTAGE 20480              // bytes per stage (A 10240 + B 10240)
#define HG_SMEM (4*HSTAGE)        // 81920

template<int EPI>
__global__ void __launch_bounds__(256) hgemm_kernel(
        const __half* __restrict__ A, const __half* __restrict__ BT,
        const float* __restrict__ Cres, void* __restrict__ Cv,
        int N, int K,
        const float* __restrict__ cosT, const float* __restrict__ sinT) {
    extern __shared__ __align__(16) char smem[];
    uint32_t sb = (uint32_t)__cvta_generic_to_shared(smem);
    int tid = threadIdx.x;
    int bn0 = blockIdx.x * 128, bm0 = blockIdx.y * 128;
    int wid = tid >> 5, lane = tid & 31;
    int wm = (wid & 3) * 32;       // warp m offset
    int wn = (wid >> 2) * 64;      // warp n offset
    int mc = lane >> 2;            // 0..7
    int kq2 = (lane & 3) * 2;      // 0,2,4,6

    float c[2][8][4];
    #pragma unroll
    for (int mt = 0; mt < 2; mt++)
        #pragma unroll
        for (int nt = 0; nt < 8; nt++)
            #pragma unroll
            for (int i = 0; i < 4; i++) c[mt][nt][i] = 0.f;

    int NIT = K >> 5;

    auto load_stage = [&](int s) {
        int b = s & 3;
        int k0 = s << 5;
        uint32_t abase = sb + b*HSTAGE;
        uint32_t bbase = abase + 10240;
        #pragma unroll
        for (int j = 0; j < 2; j++) {
            int ch = (tid << 1) + j;       // 0..511
            int row = ch >> 2, q = ch & 3;
            cp_async16(abase + row*80 + q*16, A + (size_t)(bm0 + row)*K + k0 + q*8);
        }
        #pragma unroll
        for (int j = 0; j < 2; j++) {
            int ch = (tid << 1) + j;
            int row = ch >> 2, q = ch & 3;
            cp_async16(bbase + row*80 + q*16, BT + (size_t)(bn0 + row)*K + k0 + q*8);
        }
    };

    load_stage(0); asm volatile("cp.async.commit_group;");
    load_stage(1); asm volatile("cp.async.commit_group;");
    load_stage(2); asm volatile("cp.async.commit_group;");

    for (int it = 0; it < NIT; it++) {
        asm volatile("cp.async.wait_group 2;");
        __syncthreads();

        const __half* as = (const __half*)(smem + (it & 3)*HSTAGE);
        const __half* bs = as + 5120;
        #pragma unroll
        for (int ks = 0; ks < 2; ks++) {
            int kb = ks*16 + kq2;
            uint32_t af[2][4], bf[8][2];
            #pragma unroll
            for (int mt = 0; mt < 2; mt++) {
                const __half* a0 = as + (wm + mt*16 + mc)*HPITCH + kb;
                const __half* a1 = as + (wm + mt*16 + 8 + mc)*HPITCH + kb;
                af[mt][0] = *(const uint32_t*)a0;
                af[mt][1] = *(const uint32_t*)a1;
                af[mt][2] = *(const uint32_t*)(a0 + 8);
                af[mt][3] = *(const uint32_t*)(a1 + 8);
            }
            #pragma unroll
            for (int nt = 0; nt < 8; nt++) {
                const __half* b0 = bs + (wn + nt*8 + mc)*HPITCH + kb;
                bf[nt][0] = *(const uint32_t*)b0;
                bf[nt][1] = *(const uint32_t*)(b0 + 8);
            }
            #pragma unroll
            for (int mt = 0; mt < 2; mt++)
                #pragma unroll
                for (int nt = 0; nt < 8; nt++)
                    mma_f16(c[mt][nt], af[mt], bf[nt]);
        }
        __syncthreads();
        if (it + 3 < NIT) load_stage(it + 3);
        asm volatile("cp.async.commit_group;");
    }

    // ---------------- epilogue ----------------
    #pragma unroll
    for (int mt = 0; mt < 2; mt++) {
        int r0 = bm0 + wm + mt*16 + mc;
        #pragma unroll
        for (int nt = 0; nt < 8; nt++) {
            int col = bn0 + wn + nt*8 + kq2;
            #pragma unroll
            for (int half_ = 0; half_ < 2; half_++) {
                int r = r0 + half_*8;
                float v0 = c[mt][nt][half_*2 + 0];
                float v1 = c[mt][nt][half_*2 + 1];
                if (EPI == 1) {
                    float* C = (float*)Cv;
                    const float2 res = *reinterpret_cast<const float2*>(Cres + (size_t)r*N + col);
                    v0 += res.x; v1 += res.y;
                    *reinterpret_cast<float2*>(C + (size_t)r*N + col) = make_float2(v0, v1);
                } else if (EPI == 2) {
                    __half* C = (__half*)Cv;
                    __half2 hv = __halves2half2(__float2half_rn(gelu_exact(v0)),
                                                __float2half_rn(gelu_exact(v1)));
                    *reinterpret_cast<__half2*>(C + (size_t)r*N + col) = hv;
                } else {   // EPI 3: rope on q/k pairs
                    __half* C = (__half*)Cv;
                    if (col < 2*DD) {
                        int j = (col & 63) >> 1;
                        int t = r & (TT-1);
                        float cc = cosT[t*32 + j], ssn = sinT[t*32 + j];
                        float x1 = v0, x2 = v1;
                        v0 = x1*cc - x2*ssn;
                        v1 = x1*ssn + x2*cc;
                    }
                    __half2 hv = __halves2half2(__float2half_rn(v0), __float2half_rn(v1));
                    *reinterpret_cast<__half2*>(C + (size_t)r*N + col) = hv;
                }
            }
        }
    }
}

// ---------------- attention: S = scale * Q K^T  (fp16 mma) --------------
// grid (T/64 kt, T/64 qt, B*H), 256 thr. warp tile 16x32.
__global__ void __launch_bounds__(256) attn_score_h(
        const __half* __restrict__ qkv, float* __restrict__ attn) {
    __shared__ __align__(16) __half Qs[64][72];
    __shared__ __align__(16) __half Ks[64][72];
    int bh = blockIdx.z;
    int b = bh >> 4, h = bh & 15;
    int q0 = blockIdx.y * 64, k0 = blockIdx.x * 64;
    int tid = threadIdx.x, wid = tid >> 5, lane = tid & 31;

    #pragma unroll
    for (int j = 0; j < 2; j++) {
        int ch = (tid << 1) + j;          // 0..511
        int row = ch >> 3, q = ch & 7;
        float4 qv = *reinterpret_cast<const float4*>(
            qkv + (size_t)(b*TT + q0 + row)*3*DD + h*HDIM + q*8);
        float4 kv = *reinterpret_cast<const float4*>(
            qkv + (size_t)(b*TT + k0 + row)*3*DD + DD + h*HDIM + q*8);
        *reinterpret_cast<float4*>(&Qs[row][q*8]) = qv;
        *reinterpret_cast<float4*>(&Ks[row][q*8]) = kv;
    }
    __syncthreads();

    int wm = (wid & 3) * 16;
    int wn = (wid >> 2) * 32;
    int mc = lane >> 2, kq2 = (lane & 3) * 2;
    float c[4][4];
    #pragma unroll
    for (int nt = 0; nt < 4; nt++)
        #pragma unroll
        for (int i = 0; i < 4; i++) c[nt][i] = 0.f;

    #pragma unroll
    for (int ks = 0; ks < 4; ks++) {
        int kb = ks*16 + kq2;
        uint32_t af[4];
        const __half* a0 = &Qs[wm + mc][kb];
        const __half* a1 = &Qs[wm + 8 + mc][kb];
        af[0] = *(const uint32_t*)a0;
        af[1] = *(const uint32_t*)a1;
        af[2] = *(const uint32_t*)(a0 + 8);
        af[3] = *(const uint32_t*)(a1 + 8);
        #pragma unroll
        for (int nt = 0; nt < 4; nt++) {
            const __half* b0 = &Ks[wn + nt*8 + mc][kb];
            uint32_t bf[2];
            bf[0] = *(const uint32_t*)b0;
            bf[1] = *(const uint32_t*)(b0 + 8);
            mma_f16(c[nt], af, bf);
        }
    }

    const float scale = 0.125f;
    int qrow = q0 + wm + mc;
    int col  = k0 + wn + kq2;
    #pragma unroll
    for (int nt = 0; nt < 4; nt++) {
        size_t o0 = ((size_t)bh*TT + qrow    )*TT + col + nt*8;
        size_t o1 = ((size_t)bh*TT + qrow + 8)*TT + col + nt*8;
        attn[o0]     = c[nt][0]*scale;
        attn[o0 + 1] = c[nt][1]*scale;
        attn[o1]     = c[nt][2]*scale;
        attn[o1 + 1] = c[nt][3]*scale;
    }
}

// ---------------- softmax: float scores -> half probs -------------------
__global__ void __launch_bounds__(128) softmax_kernel(
        const float* __restrict__ attn, __half* __restrict__ attnP) {
    size_t row = blockIdx.x;
    const float* p = attn + row * TT;
    __half* po = attnP + row * TT;
    int tid = threadIdx.x;
    float v[4];
    float m = -1e30f;
    #pragma unroll
    for (int i = 0; i < 4; i++) { v[i] = p[tid + i*128]; m = fmaxf(m, v[i]); }
    __shared__ float sh[4], shv[2];
    int lane = tid & 31, w = tid >> 5;
    #pragma unroll
    for (int o = 16; o > 0; o >>= 1) m = fmaxf(m, __shfl_xor_sync(0xffffffffu, m, o));
    if (lane == 0) sh[w] = m;
    __syncthreads();
    if (tid == 0) shv[0] = fmaxf(fmaxf(sh[0],sh[1]), fmaxf(sh[2],sh[3]));
    __syncthreads();
    m = shv[0];
    float s = 0.f;
    #pragma unroll
    for (int i = 0; i < 4; i++) { v[i] = expf(v[i]-m); s += v[i]; }
    #pragma unroll
    for (int o = 16; o > 0; o >>= 1) s += __shfl_xor_sync(0xffffffffu, s, o);
    if (lane == 0) sh[w] = s;
    __syncthreads();
    if (tid == 0) shv[1] = sh[0]+sh[1]+sh[2]+sh[3];
    __syncthreads();
    float inv = 1.0f / shv[1];
    #pragma unroll
    for (int i = 0; i < 4; i++) po[tid + i*128] = __float2half_rn(v[i] * inv);
}

// ---------------- O = P V  (fp16 mma) ----------------
// grid (T/64 qt, B*H), 256 thr. out tile 64 q x 64 d.
__global__ void __launch_bounds__(256) attn_av_h(
        const __half* __restrict__ attnP, const __half* __restrict__ qkv,
        __half* __restrict__ o) {
    __shared__ __align__(16) __half Ps[64][72];
    __shared__ __align__(16) __half Vs[64][72];   // [d][ktok]
    int bh = blockIdx.y;
    int b = bh >> 4, h = bh & 15;
    int q0 = blockIdx.x * 64;
    int tid = threadIdx.x, wid = tid >> 5, lane = tid & 31;

    int wm = (wid & 3) * 16;
    int wn = (wid >> 2) * 32;
    int mc = lane >> 2, kq2 = (lane & 3) * 2;
    float c[4][4];
    #pragma unroll
    for (int nt = 0; nt < 4; nt++)
        #pragma unroll
        for (int i = 0; i < 4; i++) c[nt][i] = 0.f;

    for (int kc = 0; kc < TT; kc += 64) {
        #pragma unroll
        for (int j = 0; j < 2; j++) {
            int ch = (tid << 1) + j;
            int row = ch >> 3, q = ch & 7;
            // P rows (contiguous in k)
            float4 pv = *reinterpret_cast<const float4*>(
                attnP + ((size_t)bh*TT + q0 + row)*TT + kc + q*8);
            *reinterpret_cast<float4*>(&Ps[row][q*8]) = pv;
            // V transpose: row=tok, 8 d values -> Vs[d][tok]
            float4 vv = *reinterpret_cast<const float4*>(
                qkv + (size_t)(b*TT + kc + row)*3*DD + 2*DD + h*HDIM + q*8);
            const __half* hp = (const __half*)&vv;
            #pragma unroll
            for (int i = 0; i < 8; i++) Vs[q*8 + i][row] = hp[i];
        }
        __syncthreads();

        #pragma unroll
        for (int ks = 0; ks < 4; ks++) {
            int kb = ks*16 + kq2;
            uint32_t af[4];
            const __half* a0 = &Ps[wm + mc][kb];
            const __half* a1 = &Ps[wm + 8 + mc][kb];
            af[0] = *(const uint32_t*)a0;
            af[1] = *(const uint32_t*)a1;
            af[2] = *(const uint32_t*)(a0 + 8);
            af[3] = *(const uint32_t*)(a1 + 8);
            #pragma unroll
            for (int nt = 0; nt < 4; nt++) {
                const __half* b0 = &Vs[wn + nt*8 + mc][kb];
                uint32_t bf[2];
                bf[0] = *(const uint32_t*)b0;
                bf[1] = *(const uint32_t*)(b0 + 8);
                mma_f16(c[nt], af, bf);
            }
        }
        __syncthreads();
    }

    int qrow = q0 + wm + mc;
    int col  = h*HDIM + wn + kq2;
    #pragma unroll
    for (int nt = 0; nt < 4; nt++) {
        size_t o0 = (size_t)(b*TT + qrow    )*DD + col + nt*8;
        size_t o1 = (size_t)(b*TT + qrow + 8)*DD + col + nt*8;
        *reinterpret_cast<__half2*>(o + o0) =
            __halves2half2(__float2half_rn(c[nt][0]), __float2half_rn(c[nt][1]));
        *reinterpret_cast<__half2*>(o + o1) =
            __halves2half2(__float2half_rn(c[nt][2]), __float2half_rn(c[nt][3]));
    }
}

// ---------------- gather rows t=1..511 for head ----------------
__global__ void gather_kernel(const float* __restrict__ hn, float* __restrict__ out) {
    int m = blockIdx.x;
    int b = m / TOUT;
    int t = m % TOUT + 1;
    const float4* src = (const float4*)(hn + (size_t)(b*TT + t)*DD);
    float4* dst = (float4*)(out + (size_t)m*DD);
    dst[threadIdx.x] = src[threadIdx.x];
}

// ---------------- head GEMM (bounds-checked legacy tf32 mma) -------------
__global__ void __launch_bounds__(256) tf32gemm_kernel(
        const float* __restrict__ A, const float* __restrict__ Bm,
        float* __restrict__ C, int M, int N, int K) {
    __shared__ __align__(16) uint32_t As[16][136];
    __shared__ __align__(16) uint32_t Bs[16][136];
    int tid = threadIdx.x;
    int bn0 = blockIdx.x * 128;
    int bm0 = blockIdx.y * 128;
    int wid = tid >> 5, lane = tid & 31;
    int wm = (wid & 3) * 32;
    int wn = (wid >> 2) * 64;

    float c[2][8][4];
    #pragma unroll
    for (int mt = 0; mt < 2; mt++)
        #pragma unroll
        for (int nt = 0; nt < 8; nt++)
            #pragma unroll
            for (int i = 0; i < 4; i++) c[mt][nt][i] = 0.f;

    int aRow = tid >> 1;
    int aCol = (tid & 1) * 8;
    int bRow = tid >> 4;
    int bCol = (tid & 15) * 8;
    bool aValid = (bm0 + aRow) < M;

    float4 pa0, pa1;
    float  pb[8];

#define TGL_LOAD(k0) do {                                                    \
        if (aValid) {                                                        \
            const float* ap = A + (size_t)(bm0 + aRow)*K + (k0) + aCol;      \
            pa0 = *reinterpret_cast<const float4*>(ap);                      \
            pa1 = *reinterpret_cast<const float4*>(ap + 4);                  \
        } else {                                                             \
            pa0 = make_float4(0.f,0.f,0.f,0.f);                              \
            pa1 = make_float4(0.f,0.f,0.f,0.f);                              \
        }                                                                    \
        const float* bp = Bm + (size_t)((k0) + bRow)*N;                      \
        _Pragma("unroll")                                                    \
        for (int j = 0; j < 8; j++) {                                        \
            int cl = bn0 + bCol + j;                                         \
            pb[j] = (cl < N) ? bp[cl] : 0.f;                                 \
        }                                                                    \
    } while (0)

    TGL_LOAD(0);

    for (int k0 = 0; k0 < K; k0 += 16) {
        As[aCol+0][aRow] = f2tf32(pa0.x);
        As[aCol+1][aRow] = f2tf32(pa0.y);
        As[aCol+2][aRow] = f2tf32(pa0.z);
        As[aCol+3][aRow] = f2tf32(pa0.w);
        As[aCol+4][aRow] = f2tf32(pa1.x);
        As[aCol+5][aRow] = f2tf32(pa1.y);
        As[aCol+6][aRow] = f2tf32(pa1.z);
        As[aCol+7][aRow] = f2tf32(pa1.w);
        #pragma unroll
        for (int j = 0; j < 8; j++) Bs[bRow][bCol+j] = f2tf32(pb[j]);
        __syncthreads();

        if (k0 + 16 < K) TGL_LOAD(k0 + 16);

        #pragma unroll
        for (int ks = 0; ks < 2; ks++) {
            int kr = ks*8 + (lane & 3);
            int mc = lane >> 2;
            uint32_t af[2][4], bf[8][2];
            #pragma unroll
            for (int mt = 0; mt < 2; mt++) {
                af[mt][0] = As[kr  ][wm + mt*16 + mc];
                af[mt][1] = As[kr  ][wm + mt*16 + 8 + mc];
                af[mt][2] = As[kr+4][wm + mt*16 + mc];
                af[mt][3] = As[kr+4][wm + mt*16 + 8 + mc];
            }
            #pragma unroll
            for (int nt = 0; nt < 8; nt++) {
                bf[nt][0] = Bs[kr  ][wn + nt*8 + mc];
                bf[nt][1] = Bs[kr+4][wn + nt*8 + mc];
            }
            #pragma unroll
            for (int mt = 0; mt < 2; mt++)
                #pragma unroll
                for (int nt = 0; nt < 8; nt++)
                    mma_tf32(c[mt][nt], af[mt], bf[nt]);
        }
        __syncthreads();
    }
#undef TGL_LOAD

    #pragma unroll
    for (int mt = 0; mt < 2; mt++) {
        int r0 = bm0 + wm + mt*16 + (lane >> 2);
        #pragma unroll
        for (int nt = 0; nt < 8; nt++) {
            int col = bn0 + wn + nt*8 + (lane & 3)*2;
            #pragma unroll
            for (int half_ = 0; half_ < 2; half_++) {
                int r = r0 + half_*8;
                if (r >= M) continue;
                #pragma unroll
                for (int cc = 0; cc < 2; cc++) {
                    int cl = col + cc;
                    if (cl >= N) continue;
                    C[(size_t)r*N + cl] = c[mt][nt][half_*2 + cc];
                }
            }
        }
    }
}

// ---------------- host side ----------------
static inline int cdiv(int a, int b) { return (a + b - 1) / b; }

extern "C" void kernel_launch(void* const* d_in, const int* in_sizes, int n_in,
                              void* d_out, int out_size) {
    const int*   x         = (const int*)  d_in[0];
    const int*   t         = (const int*)  d_in[1];
    const int*   level     = (const int*)  d_in[2];
    const float* tok_emb   = (const float*)d_in[3];
    const float* level_emb = (const float*)d_in[4];
    const float* time_w1   = (const float*)d_in[5];
    const float* time_b1   = (const float*)d_in[6];
    const float* time_w2   = (const float*)d_in[7];
    const float* time_b2   = (const float*)d_in[8];
    const float* ln1_g     = (const float*)d_in[9];
    const float* ln1_b     = (const float*)d_in[10];
    const float* qkv_w     = (const float*)d_in[11];
    const float* proj_w    = (const float*)d_in[12];
    const float* ln2_g     = (const float*)d_in[13];
    const float* ln2_b     = (const float*)d_in[14];
    const float* fc1_w     = (const float*)d_in[15];
    const float* fc2_w     = (const float*)d_in[16];
    const float* lnf_g     = (const float*)d_in[17];
    const float* lnf_b     = (const float*)d_in[18];
    const float* head0_w   = (const float*)d_in[19];

    float  *ph, *phn, *pattn, *ptein, *pteh, *pte, *pcos, *psin;
    __half *phnh, *pqkvh, *poh, *pffnh, *pattnP;
    __half *pqkvw, *pprojw, *pfc1w, *pfc2w;
    cudaGetSymbolAddress((void**)&ph,    g_h);
    cudaGetSymbolAddress((void**)&phn,   g_hn);
    cudaGetSymbolAddress((void**)&pattn, g_attn);
    cudaGetSymbolAddress((void**)&ptein, g_tein);
    cudaGetSymbolAddress((void**)&pteh,  g_teh);
    cudaGetSymbolAddress((void**)&pte,   g_te);
    cudaGetSymbolAddress((void**)&pcos,  g_cos);
    cudaGetSymbolAddress((void**)&psin,  g_sin);
    cudaGetSymbolAddress((void**)&phnh,  g_hnh);
    cudaGetSymbolAddress((void**)&pqkvh, g_qkvh);
    cudaGetSymbolAddress((void**)&poh,   g_oh);
    cudaGetSymbolAddress((void**)&pffnh, g_ffnh);
    cudaGetSymbolAddress((void**)&pattnP,g_attnP);
    cudaGetSymbolAddress((void**)&pqkvw, g_qkvw);
    cudaGetSymbolAddress((void**)&pprojw,g_projw);
    cudaGetSymbolAddress((void**)&pfc1w, g_fc1w);
    cudaGetSymbolAddress((void**)&pfc2w, g_fc2w);

    cudaFuncSetAttribute(hgemm_kernel<1>, cudaFuncAttributeMaxDynamicSharedMemorySize, HG_SMEM);
    cudaFuncSetAttribute(hgemm_kernel<2>, cudaFuncAttributeMaxDynamicSharedMemorySize, HG_SMEM);
    cudaFuncSetAttribute(hgemm_kernel<3>, cudaFuncAttributeMaxDynamicSharedMemorySize, HG_SMEM);

    // transpose + halve weights:  W[K,N] -> WT[N,K]
    dim3 tb(32, 8);
    transpose_half_kernel<<<dim3(3*DD/32, DD/32, LL), tb>>>(qkv_w,  pqkvw,  DD, 3*DD);
    transpose_half_kernel<<<dim3(DD/32,   DD/32, LL), tb>>>(proj_w, pprojw, DD, DD);
    transpose_half_kernel<<<dim3(DFF/32,  DD/32, LL), tb>>>(fc1_w,  pfc1w,  DD, DFF);
    transpose_half_kernel<<<dim3(DD/32,  DFF/32, LL), tb>>>(fc2_w,  pfc2w,  DFF, DD);

    // rope tables + time embedding
    rope_init_kernel<<<cdiv(TT*32, 512), 512>>>(pcos, psin);
    te_in_kernel<<<BB, 512>>>(t, ptein);
    tgemm_kernel<2><<<cdiv(DFF,128), 128>>>(ptein, time_w1, time_b1, pteh, DD, DFF);
    tgemm_kernel<0><<<cdiv(DD,128), 128>>>(pteh, time_w2, time_b2, pte, DFF, DD);

    // token + level + time embedding
    embed_kernel<<<NTOK, 256>>>(x, level, tok_emb, level_emb, pte, ph);

    dim3 blk(256);
    for (int i = 0; i < LL; i++) {
        layernorm_kernel<1><<<NTOK, 256>>>(ph, ln1_g + i*DD, ln1_b + i*DD, phnh);

        hgemm_kernel<3><<<dim3(3*DD/128, NTOK/128), blk, HG_SMEM>>>(
            phnh, pqkvw + (size_t)i*DD*3*DD, nullptr, pqkvh, 3*DD, DD, pcos, psin);

        attn_score_h<<<dim3(TT/64, TT/64, BB*HH), blk>>>(pqkvh, pattn);
        softmax_kernel<<<BB*HH*TT, 128>>>(pattn, pattnP);
        attn_av_h<<<dim3(TT/64, BB*HH), blk>>>(pattnP, pqkvh, poh);

        hgemm_kernel<1><<<dim3(DD/128, NTOK/128), blk, HG_SMEM>>>(
            poh, pprojw + (size_t)i*DD*DD, ph, ph, DD, DD, pcos, psin);

        layernorm_kernel<1><<<NTOK, 256>>>(ph, ln2_g + i*DD, ln2_b + i*DD, phnh);

        hgemm_kernel<2><<<dim3(DFF/128, NTOK/128), blk, HG_SMEM>>>(
            phnh, pfc1w + (size_t)i*DD*DFF, nullptr, pffnh, DFF, DD, pcos, psin);

        hgemm_kernel<1><<<dim3(DD/128, NTOK/128), blk, HG_SMEM>>>(
            pffnh, pfc2w + (size_t)i*DFF*DD, ph, ph, DD, DFF, pcos, psin);
    }

    layernorm_kernel<0><<<NTOK, 256>>>(ph, lnf_g, lnf_b, phn);
    gather_kernel<<<NHEADROWS, 256>>>(phn, pattn);
    tf32gemm_kernel<<<dim3(cdiv(V0,128), cdiv(NHEADROWS,128)), blk>>>(
        pattn, head0_w, (float*)d_out, NHEADROWS, V0, DD);
}

// round 7
// speedup vs baseline: 4.9529x; 1.1824x over previous
#include <cuda_runtime.h>
#include <cuda_fp16.h>
#include <math.h>
#include <stdint.h>

// ---------------- problem constants ----------------
#define BB   16
#define TT   512
#define NTOK (BB*TT)        // 8192
#define DD   1024
#define HH   16
#define HDIM 64
#define LL   12
#define DFF  4096
#define V0   1025
#define TOUT 511
#define NHEADROWS (BB*TOUT) // 8176

// ---------------- scratch (device globals; no allocation allowed) -------
__device__ float  g_h    [NTOK*DD];
__device__ float  g_hn   [NTOK*DD];
__device__ float  g_gath [NHEADROWS*DD];
__device__ float  g_tein [BB*DD];
__device__ float  g_teh  [BB*DFF];
__device__ float  g_te   [BB*DD];
__device__ float  g_cos  [TT*32];
__device__ float  g_sin  [TT*32];
__device__ __half g_hnh  [NTOK*DD];
__device__ __half g_qkvh [NTOK*3*DD];
__device__ __half g_oh   [NTOK*DD];
__device__ __half g_ffnh [NTOK*DFF];
// transposed half weights  [L][N][K] K-major
__device__ __half g_qkvw [LL*DD*3*DD];
__device__ __half g_projw[LL*DD*DD];
__device__ __half g_fc1w [LL*DD*DFF];
__device__ __half g_fc2w [LL*DFF*DD];

__device__ __forceinline__ float gelu_exact(float x) {
    return 0.5f * x * (1.0f + erff(x * 0.70710678118654752440f));
}
__device__ __forceinline__ uint32_t f2tf32(float x) {
    uint32_t r; asm("cvt.rna.tf32.f32 %0, %1;" : "=r"(r) : "f"(x)); return r;
}
__device__ __forceinline__ uint32_t packh2(float a, float b) {
    __half2 h = __floats2half2_rn(a, b);
    return *reinterpret_cast<uint32_t*>(&h);
}

// fp16 mma: C(16x8,f32) += A(16x16,f16 row) * B(16x8,f16 col)
__device__ __forceinline__ void mma_f16(float* c, const uint32_t* a, const uint32_t* b) {
    asm volatile(
        "mma.sync.aligned.m16n8k16.row.col.f32.f16.f16.f32 "
        "{%0,%1,%2,%3}, {%4,%5,%6,%7}, {%8,%9}, {%0,%1,%2,%3};"
        : "+f"(c[0]), "+f"(c[1]), "+f"(c[2]), "+f"(c[3])
        : "r"(a[0]), "r"(a[1]), "r"(a[2]), "r"(a[3]), "r"(b[0]), "r"(b[1]));
}
__device__ __forceinline__ void mma_tf32(float* c, const uint32_t* a, const uint32_t* b) {
    asm volatile(
        "mma.sync.aligned.m16n8k8.row.col.f32.tf32.tf32.f32 "
        "{%0,%1,%2,%3}, {%4,%5,%6,%7}, {%8,%9}, {%0,%1,%2,%3};"
        : "+f"(c[0]), "+f"(c[1]), "+f"(c[2]), "+f"(c[3])
        : "r"(a[0]), "r"(a[1]), "r"(a[2]), "r"(a[3]), "r"(b[0]), "r"(b[1]));
}
__device__ __forceinline__ void cp_async16(uint32_t saddr, const void* gptr) {
    asm volatile("cp.async.cg.shared.global [%0], [%1], 16;\n" :: "r"(saddr), "l"(gptr));
}
#define LDSM_X4(r0,r1,r2,r3,a) \
    asm volatile("ldmatrix.sync.aligned.m8n8.x4.shared.b16 {%0,%1,%2,%3}, [%4];" \
        : "=r"(r0),"=r"(r1),"=r"(r2),"=r"(r3) : "r"(a))
#define LDSM_X4T(r0,r1,r2,r3,a) \
    asm volatile("ldmatrix.sync.aligned.m8n8.x4.trans.shared.b16 {%0,%1,%2,%3}, [%4];" \
        : "=r"(r0),"=r"(r1),"=r"(r2),"=r"(r3) : "r"(a))

// ---------------- weight transpose + half convert: W[K,N] -> WT[N,K] ----
__global__ void transpose_half_kernel(const float* __restrict__ src, __half* __restrict__ dst,
                                      int K, int N) {
    __shared__ float tile[32][33];
    size_t loff = (size_t)blockIdx.z * K * N;
    int n0 = blockIdx.x * 32, k0 = blockIdx.y * 32;
    int tx = threadIdx.x, ty = threadIdx.y;   // 32x8
    #pragma unroll
    for (int i = 0; i < 32; i += 8)
        tile[ty+i][tx] = src[loff + (size_t)(k0+ty+i)*N + n0+tx];
    __syncthreads();
    #pragma unroll
    for (int i = 0; i < 32; i += 8)
        dst[loff + (size_t)(n0+ty+i)*K + k0+tx] = __float2half_rn(tile[tx][ty+i]);
}

// ---------------- rope tables ----------------
__global__ void rope_init_kernel(float* cosT, float* sinT) {
    int idx = blockIdx.x * blockDim.x + threadIdx.x;
    if (idx >= TT*32) return;
    int t = idx >> 5, j = idx & 31;
    float freq = expf(-(float)j * (logf(10000.0f) / 32.0f));
    float ang = (float)t * freq;
    cosT[idx] = cosf(ang);
    sinT[idx] = sinf(ang);
}

// ---------------- time embedding ----------------
__global__ void te_in_kernel(const int* __restrict__ t, float* __restrict__ out) {
    int b = blockIdx.x;
    int j = threadIdx.x;
    float tv = (float)t[b];
    float e  = expf((float)j * (-logf(10000.0f) / 511.0f));
    float v  = tv * e;
    out[b*DD + j]       = sinf(v);
    out[b*DD + 512 + j] = cosf(v);
}

template<int EPI>  // 0 = bias only, 2 = gelu(bias+)
__global__ void tgemm_kernel(const float* __restrict__ A, const float* __restrict__ Bw,
                             const float* __restrict__ bias, float* __restrict__ C,
                             int K, int N) {
    int n = blockIdx.x * blockDim.x + threadIdx.x;
    if (n >= N) return;
    float acc[16];
    #pragma unroll
    for (int m = 0; m < 16; m++) acc[m] = 0.f;
    for (int k = 0; k < K; k++) {
        float bv = Bw[(size_t)k*N + n];
        #pragma unroll
        for (int m = 0; m < 16; m++) acc[m] += A[m*K + k] * bv;
    }
    float bs = bias[n];
    #pragma unroll
    for (int m = 0; m < 16; m++) {
        float v = acc[m] + bs;
        if (EPI == 2) v = gelu_exact(v);
        C[(size_t)m*N + n] = v;
    }
}

// ---------------- embedding ----------------
__global__ void embed_kernel(const int* __restrict__ x, const int* __restrict__ level,
                             const float* __restrict__ tok_emb, const float* __restrict__ level_emb,
                             const float* __restrict__ te, float* __restrict__ h) {
    int n = blockIdx.x;
    int b = n >> 9;
    int lvl = level[0];
    const float4* tk = (const float4*)(tok_emb + (size_t)x[n]*DD);
    const float4* le = (const float4*)(level_emb + (size_t)lvl*DD);
    const float4* tv = (const float4*)(te + (size_t)b*DD);
    float4* out = (float4*)(h + (size_t)n*DD);
    int i = threadIdx.x;
    float4 a = tk[i], c = le[i], d = tv[i];
    out[i] = make_float4(a.x+c.x+d.x, a.y+c.y+d.y, a.z+c.z+d.z, a.w+c.w+d.w);
}

// ---------------- layernorm: OUTHALF=1 -> half out, 0 -> float out ------
template<int OUTHALF>
__global__ void __launch_bounds__(256) layernorm_kernel(
        const float* __restrict__ x, const float* __restrict__ g,
        const float* __restrict__ b, void* __restrict__ yv) {
    size_t row = blockIdx.x;
    int tid = threadIdx.x;
    const float4* xr = (const float4*)(x + row*DD);
    float4 v = xr[tid];
    float s  = v.x + v.y + v.z + v.w;
    float ss = v.x*v.x + v.y*v.y + v.z*v.z + v.w*v.w;
    __shared__ float sh1[8], sh2[8], shm[2];
    int lane = tid & 31, w = tid >> 5;
    #pragma unroll
    for (int o = 16; o > 0; o >>= 1) {
        s  += __shfl_xor_sync(0xffffffffu, s,  o);
        ss += __shfl_xor_sync(0xffffffffu, ss, o);
    }
    if (lane == 0) { sh1[w] = s; sh2[w] = ss; }
    __syncthreads();
    if (tid == 0) {
        float ts = 0.f, tss = 0.f;
        #pragma unroll
        for (int i = 0; i < 8; i++) { ts += sh1[i]; tss += sh2[i]; }
        float mean = ts * (1.0f/DD);
        float var  = tss * (1.0f/DD) - mean*mean;
        shm[0] = mean;
        shm[1] = rsqrtf(var + 1e-5f);
    }
    __syncthreads();
    float mean = shm[0], rs = shm[1];
    float4 gg = ((const float4*)g)[tid];
    float4 bb = ((const float4*)b)[tid];
    float o0 = (v.x-mean)*rs*gg.x + bb.x;
    float o1 = (v.y-mean)*rs*gg.y + bb.y;
    float o2 = (v.z-mean)*rs*gg.z + bb.z;
    float o3 = (v.w-mean)*rs*gg.w + bb.w;
    if (OUTHALF) {
        __half2* y = (__half2*)((__half*)yv + row*DD);
        y[tid*2+0] = __halves2half2(__float2half_rn(o0), __float2half_rn(o1));
        y[tid*2+1] = __halves2half2(__float2half_rn(o2), __float2half_rn(o3));
    } else {
        ((float4*)((float*)yv + row*DD))[tid] = make_float4(o0, o1, o2, o3);
    }
}

// =======================================================================
// fp16 GEMM (ldmatrix mainloop): C = A[M,K] @ BT[N,K]^T.
// M%128==0, N%128==0, K%32==0. 128x128x32 tile, 4-stage cp.async.
// EPI: 1 = +residual(float out), 2 = gelu(half out), 3 = rope-qkv(half out, q*0.125)
// =======================================================================
#define HPITCH 40                 // halves per smem row (80 B): conflict-free
#define HSTAGE 20480              // bytes per stage (A 10240 + B 10240)
#define HG_SMEM (4*HSTAGE)        // 81920

template<int EPI>
__global__ void __launch_bounds__(256) hgemm_kernel(
        const __half* __restrict__ A, const __half* __restrict__ BT,
        const float* __restrict__ Cres, void* __restrict__ Cv,
        int N, int K,
        const float* __restrict__ cosT, const float* __restrict__ sinT) {
    extern __shared__ __align__(16) char smem[];
    uint32_t sb = (uint32_t)__cvta_generic_to_shared(smem);
    int tid = threadIdx.x;
    int bn0 = blockIdx.x * 128, bm0 = blockIdx.y * 128;
    int wid = tid >> 5, lane = tid & 31;
    int wm = (wid & 3) * 32;       // warp m offset
    int wn = (wid >> 2) * 64;      // warp n offset
    int mc = lane >> 2;
    int kq2 = (lane & 3) * 2;

    float c[2][8][4];
    #pragma unroll
    for (int mt = 0; mt < 2; mt++)
        #pragma unroll
        for (int nt = 0; nt < 8; nt++)
            #pragma unroll
            for (int i = 0; i < 4; i++) c[mt][nt][i] = 0.f;

    int NIT = K >> 5;

    // per-lane ldmatrix byte offsets within a stage
    int a_r = lane & 15, a_c = (lane >> 4) * 8;
    int b_r = ((lane >> 4) << 3) + (lane & 7), b_c = ((lane >> 3) & 1) * 8;
    uint32_t aoff[2][2], boff[2][4];
    #pragma unroll
    for (int ks = 0; ks < 2; ks++) {
        #pragma unroll
        for (int mt = 0; mt < 2; mt++)
            aoff[ks][mt] = (uint32_t)((wm + mt*16 + a_r)*80 + (ks*16 + a_c)*2);
        #pragma unroll
        for (int p = 0; p < 4; p++)
            boff[ks][p] = (uint32_t)(10240 + (wn + p*16 + b_r)*80 + (ks*16 + b_c)*2);
    }

    auto load_stage = [&](int s) {
        int b = s & 3;
        int k0 = s << 5;
        uint32_t abase = sb + b*HSTAGE;
        uint32_t bbase = abase + 10240;
        #pragma unroll
        for (int j = 0; j < 2; j++) {
            int ch = (tid << 1) + j;       // 0..511
            int row = ch >> 2, q = ch & 3;
            cp_async16(abase + row*80 + q*16, A + (size_t)(bm0 + row)*K + k0 + q*8);
        }
        #pragma unroll
        for (int j = 0; j < 2; j++) {
            int ch = (tid << 1) + j;
            int row = ch >> 2, q = ch & 3;
            cp_async16(bbase + row*80 + q*16, BT + (size_t)(bn0 + row)*K + k0 + q*8);
        }
    };

    load_stage(0); asm volatile("cp.async.commit_group;");
    load_stage(1); asm volatile("cp.async.commit_group;");
    load_stage(2); asm volatile("cp.async.commit_group;");

    for (int it = 0; it < NIT; it++) {
        asm volatile("cp.async.wait_group 2;");
        __syncthreads();

        uint32_t stage = sb + (it & 3)*HSTAGE;
        #pragma unroll
        for (int ks = 0; ks < 2; ks++) {
            uint32_t af[2][4], bf[8][2];
            LDSM_X4(af[0][0], af[0][1], af[0][2], af[0][3], stage + aoff[ks][0]);
            LDSM_X4(af[1][0], af[1][1], af[1][2], af[1][3], stage + aoff[ks][1]);
            #pragma unroll
            for (int p = 0; p < 4; p++)
                LDSM_X4(bf[2*p][0], bf[2*p][1], bf[2*p+1][0], bf[2*p+1][1],
                        stage + boff[ks][p]);
            #pragma unroll
            for (int mt = 0; mt < 2; mt++)
                #pragma unroll
                for (int nt = 0; nt < 8; nt++)
                    mma_f16(c[mt][nt], af[mt], bf[nt]);
        }
        __syncthreads();
        if (it + 3 < NIT) load_stage(it + 3);
        asm volatile("cp.async.commit_group;");
    }

    // ---------------- epilogue ----------------
    #pragma unroll
    for (int mt = 0; mt < 2; mt++) {
        int r0 = bm0 + wm + mt*16 + mc;
        #pragma unroll
        for (int nt = 0; nt < 8; nt++) {
            int col = bn0 + wn + nt*8 + kq2;
            #pragma unroll
            for (int half_ = 0; half_ < 2; half_++) {
                int r = r0 + half_*8;
                float v0 = c[mt][nt][half_*2 + 0];
                float v1 = c[mt][nt][half_*2 + 1];
                if (EPI == 1) {
                    float* C = (float*)Cv;
                    const float2 res = *reinterpret_cast<const float2*>(Cres + (size_t)r*N + col);
                    v0 += res.x; v1 += res.y;
                    *reinterpret_cast<float2*>(C + (size_t)r*N + col) = make_float2(v0, v1);
                } else if (EPI == 2) {
                    __half* C = (__half*)Cv;
                    __half2 hv = __halves2half2(__float2half_rn(gelu_exact(v0)),
                                                __float2half_rn(gelu_exact(v1)));
                    *reinterpret_cast<__half2*>(C + (size_t)r*N + col) = hv;
                } else {   // EPI 3: rope on q/k pairs, q pre-scaled by 1/8 (exact)
                    __half* C = (__half*)Cv;
                    if (col < 2*DD) {
                        int j = (col & 63) >> 1;
                        int t = r & (TT-1);
                        float cc = cosT[t*32 + j], ssn = sinT[t*32 + j];
                        float x1 = v0, x2 = v1;
                        v0 = x1*cc - x2*ssn;
                        v1 = x1*ssn + x2*cc;
                        if (col < DD) { v0 *= 0.125f; v1 *= 0.125f; }
                    }
                    __half2 hv = __halves2half2(__float2half_rn(v0), __float2half_rn(v1));
                    *reinterpret_cast<__half2*>(C + (size_t)r*N + col) = hv;
                }
            }
        }
    }
}

// =======================================================================
// Flash attention: one block = 64 q rows x one (b,h). 4 warps, online softmax.
// Q pre-scaled by 1/sqrt(64) in qkv epilogue. O written as half.
// =======================================================================
__global__ void __launch_bounds__(128) flash_attn_kernel(
        const __half* __restrict__ qkv, __half* __restrict__ o) {
    __shared__ __align__(16) __half Qs[64][72];
    __shared__ __align__(16) __half Ks[2][64][72];
    __shared__ __align__(16) __half Vs[2][64][72];
    int bh = blockIdx.y;
    int b = bh >> 4, h = bh & 15;
    int q0 = blockIdx.x * 64;
    int tid = threadIdx.x, wid = tid >> 5, lane = tid & 31;
    int mc = lane >> 2, kq2 = (lane & 3) * 2;

    uint32_t sQ = (uint32_t)__cvta_generic_to_shared(Qs);
    uint32_t sK = (uint32_t)__cvta_generic_to_shared(Ks);
    uint32_t sV = (uint32_t)__cvta_generic_to_shared(Vs);

    auto load_kv = [&](int kc, int buf) {
        #pragma unroll
        for (int j = 0; j < 4; j++) {
            int ch = tid + j*128;
            int row = ch >> 3, seg = ch & 7;
            size_t base = (size_t)(b*TT + kc*64 + row)*3*DD + h*HDIM + seg*8;
            cp_async16(sK + buf*9216 + row*144 + seg*16, qkv + base + DD);
            cp_async16(sV + buf*9216 + row*144 + seg*16, qkv + base + 2*DD);
        }
    };

    // Q load
    #pragma unroll
    for (int j = 0; j < 4; j++) {
        int ch = tid + j*128;
        int row = ch >> 3, seg = ch & 7;
        cp_async16(sQ + row*144 + seg*16,
                   qkv + (size_t)(b*TT + q0 + row)*3*DD + h*HDIM + seg*8);
    }
    asm volatile("cp.async.commit_group;");
    load_kv(0, 0); asm volatile("cp.async.commit_group;");
    load_kv(1, 1); asm volatile("cp.async.commit_group;");

    asm volatile("cp.async.wait_group 2;");
    __syncthreads();

    // Q fragments (held in registers all loop long)
    uint32_t qf[4][4];
    {
        uint32_t qb = sQ + (uint32_t)((wid*16 + (lane & 15))*144 + ((lane >> 4)*8)*2);
        #pragma unroll
        for (int ks = 0; ks < 4; ks++)
            LDSM_X4(qf[ks][0], qf[ks][1], qf[ks][2], qf[ks][3], qb + ks*32);
    }

    // per-lane K/V ldmatrix offset pieces
    uint32_t kRow = (uint32_t)(((lane >> 4) << 3) + (lane & 7));
    uint32_t kCol = (uint32_t)(((lane >> 3) & 1) * 8);
    uint32_t vRow = (uint32_t)(lane & 15);
    uint32_t vCol = (uint32_t)((lane >> 4) * 8);

    float m0 = -1e30f, m1 = -1e30f, l0 = 0.f, l1 = 0.f;
    float oa[8][4];
    #pragma unroll
    for (int nt = 0; nt < 8; nt++)
        #pragma unroll
        for (int i = 0; i < 4; i++) oa[nt][i] = 0.f;

    for (int kc = 0; kc < 8; kc++) {
        asm volatile("cp.async.wait_group 1;");
        __syncthreads();
        uint32_t kb = sK + (kc & 1)*9216;
        uint32_t vb = sV + (kc & 1)*9216;

        // S = Q K^T (warp owns 16 q rows x 64 k-tokens)
        float s[8][4];
        #pragma unroll
        for (int nt = 0; nt < 8; nt++)
            #pragma unroll
            for (int i = 0; i < 4; i++) s[nt][i] = 0.f;
        #pragma unroll
        for (int ks = 0; ks < 4; ks++) {
            uint32_t bf[8][2];
            #pragma unroll
            for (int p = 0; p < 4; p++)
                LDSM_X4(bf[2*p][0], bf[2*p][1], bf[2*p+1][0], bf[2*p+1][1],
                        kb + (p*16 + kRow)*144 + (ks*16 + kCol)*2);
            #pragma unroll
            for (int nt = 0; nt < 8; nt++) mma_f16(s[nt], qf[ks], bf[nt]);
        }

        // online softmax (rows mc / mc+8; quad = 4 consecutive lanes)
        float mx0 = -1e30f, mx1 = -1e30f;
        #pragma unroll
        for (int nt = 0; nt < 8; nt++) {
            mx0 = fmaxf(mx0, fmaxf(s[nt][0], s[nt][1]));
            mx1 = fmaxf(mx1, fmaxf(s[nt][2], s[nt][3]));
        }
        mx0 = fmaxf(mx0, __shfl_xor_sync(0xffffffffu, mx0, 1));
        mx0 = fmaxf(mx0, __shfl_xor_sync(0xffffffffu, mx0, 2));
        mx1 = fmaxf(mx1, __shfl_xor_sync(0xffffffffu, mx1, 1));
        mx1 = fmaxf(mx1, __shfl_xor_sync(0xffffffffu, mx1, 2));
        float m0n = fmaxf(m0, mx0), m1n = fmaxf(m1, mx1);
        float a0 = __expf(m0 - m0n), a1 = __expf(m1 - m1n);

        uint32_t pf[4][4];
        float sum0 = 0.f, sum1 = 0.f;
        #pragma unroll
        for (int tp = 0; tp < 4; tp++) {
            float p00 = __expf(s[2*tp][0]   - m0n);
            float p01 = __expf(s[2*tp][1]   - m0n);
            float p02 = __expf(s[2*tp][2]   - m1n);
            float p03 = __expf(s[2*tp][3]   - m1n);
            float p10 = __expf(s[2*tp+1][0] - m0n);
            float p11 = __expf(s[2*tp+1][1] - m0n);
            float p12 = __expf(s[2*tp+1][2] - m1n);
            float p13 = __expf(s[2*tp+1][3] - m1n);
            sum0 += p00 + p01 + p10 + p11;
            sum1 += p02 + p03 + p12 + p13;
            pf[tp][0] = packh2(p00, p01);
            pf[tp][1] = packh2(p02, p03);
            pf[tp][2] = packh2(p10, p11);
            pf[tp][3] = packh2(p12, p13);
        }
        sum0 += __shfl_xor_sync(0xffffffffu, sum0, 1);
        sum0 += __shfl_xor_sync(0xffffffffu, sum0, 2);
        sum1 += __shfl_xor_sync(0xffffffffu, sum1, 1);
        sum1 += __shfl_xor_sync(0xffffffffu, sum1, 2);
        l0 = l0*a0 + sum0;
        l1 = l1*a1 + sum1;
        m0 = m0n; m1 = m1n;
        #pragma unroll
        for (int nt = 0; nt < 8; nt++) {
            oa[nt][0] *= a0; oa[nt][1] *= a0;
            oa[nt][2] *= a1; oa[nt][3] *= a1;
        }

        // O += P V  (V fragments via ldmatrix.trans)
        #pragma unroll
        for (int kt = 0; kt < 4; kt++) {
            #pragma unroll
            for (int p = 0; p < 4; p++) {
                uint32_t v0, v1, v2, v3;
                LDSM_X4T(v0, v1, v2, v3,
                         vb + (kt*16 + vRow)*144 + (p*16 + vCol)*2);
                uint32_t bv0[2] = {v0, v1}, bv1[2] = {v2, v3};
                mma_f16(oa[2*p],   pf[kt], bv0);
                mma_f16(oa[2*p+1], pf[kt], bv1);
            }
        }

        __syncthreads();
        if (kc + 2 < 8) load_kv(kc + 2, kc & 1);
        asm volatile("cp.async.commit_group;");
    }

    float i0 = 1.f / l0, i1 = 1.f / l1;
    int r0 = b*TT + q0 + wid*16 + mc;
    #pragma unroll
    for (int nt = 0; nt < 8; nt++) {
        int col = h*HDIM + nt*8 + kq2;
        *reinterpret_cast<__half2*>(o + (size_t)r0*DD + col) =
            __halves2half2(__float2half_rn(oa[nt][0]*i0), __float2half_rn(oa[nt][1]*i0));
        *reinterpret_cast<__half2*>(o + (size_t)(r0+8)*DD + col) =
            __halves2half2(__float2half_rn(oa[nt][2]*i1), __float2half_rn(oa[nt][3]*i1));
    }
}

// ---------------- gather rows t=1..511 for head ----------------
__global__ void gather_kernel(const float* __restrict__ hn, float* __restrict__ out) {
    int m = blockIdx.x;
    int b = m / TOUT;
    int t = m % TOUT + 1;
    const float4* src = (const float4*)(hn + (size_t)(b*TT + t)*DD);
    float4* dst = (float4*)(out + (size_t)m*DD);
    dst[threadIdx.x] = src[threadIdx.x];
}

// ---------------- head GEMM (bounds-checked legacy tf32 mma) -------------
__global__ void __launch_bounds__(256) tf32gemm_kernel(
        const float* __restrict__ A, const float* __restrict__ Bm,
        float* __restrict__ C, int M, int N, int K) {
    __shared__ __align__(16) uint32_t As[16][136];
    __shared__ __align__(16) uint32_t Bs[16][136];
    int tid = threadIdx.x;
    int bn0 = blockIdx.x * 128;
    int bm0 = blockIdx.y * 128;
    int wid = tid >> 5, lane = tid & 31;
    int wm = (wid & 3) * 32;
    int wn = (wid >> 2) * 64;

    float c[2][8][4];
    #pragma unroll
    for (int mt = 0; mt < 2; mt++)
        #pragma unroll
        for (int nt = 0; nt < 8; nt++)
            #pragma unroll
            for (int i = 0; i < 4; i++) c[mt][nt][i] = 0.f;

    int aRow = tid >> 1;
    int aCol = (tid & 1) * 8;
    int bRow = tid >> 4;
    int bCol = (tid & 15) * 8;
    bool aValid = (bm0 + aRow) < M;

    float4 pa0, pa1;
    float  pb[8];

#define TGL_LOAD(k0) do {                                                    \
        if (aValid) {                                                        \
            const float* ap = A + (size_t)(bm0 + aRow)*K + (k0) + aCol;      \
            pa0 = *reinterpret_cast<const float4*>(ap);                      \
            pa1 = *reinterpret_cast<const float4*>(ap + 4);                  \
        } else {                                                             \
            pa0 = make_float4(0.f,0.f,0.f,0.f);                              \
            pa1 = make_float4(0.f,0.f,0.f,0.f);                              \
        }                                                                    \
        const float* bp = Bm + (size_t)((k0) + bRow)*N;                      \
        _Pragma("unroll")                                                    \
        for (int j = 0; j < 8; j++) {                                        \
            int cl = bn0 + bCol + j;                                         \
            pb[j] = (cl < N) ? bp[cl] : 0.f;                                 \
        }                                                                    \
    } while (0)

    TGL_LOAD(0);

    for (int k0 = 0; k0 < K; k0 += 16) {
        As[aCol+0][aRow] = f2tf32(pa0.x);
        As[aCol+1][aRow] = f2tf32(pa0.y);
        As[aCol+2][aRow] = f2tf32(pa0.z);
        As[aCol+3][aRow] = f2tf32(pa0.w);
        As[aCol+4][aRow] = f2tf32(pa1.x);
        As[aCol+5][aRow] = f2tf32(pa1.y);
        As[aCol+6][aRow] = f2tf32(pa1.z);
        As[aCol+7][aRow] = f2tf32(pa1.w);
        #pragma unroll
        for (int j = 0; j < 8; j++) Bs[bRow][bCol+j] = f2tf32(pb[j]);
        __syncthreads();

        if (k0 + 16 < K) TGL_LOAD(k0 + 16);

        #pragma unroll
        for (int ks = 0; ks < 2; ks++) {
            int kr = ks*8 + (lane & 3);
            int mc = lane >> 2;
            uint32_t af[2][4], bf[8][2];
            #pragma unroll
            for (int mt = 0; mt < 2; mt++) {
                af[mt][0] = As[kr  ][wm + mt*16 + mc];
                af[mt][1] = As[kr  ][wm + mt*16 + 8 + mc];
                af[mt][2] = As[kr+4][wm + mt*16 + mc];
                af[mt][3] = As[kr+4][wm + mt*16 + 8 + mc];
            }
            #pragma unroll
            for (int nt = 0; nt < 8; nt++) {
                bf[nt][0] = Bs[kr  ][wn + nt*8 + mc];
                bf[nt][1] = Bs[kr+4][wn + nt*8 + mc];
            }
            #pragma unroll
            for (int mt = 0; mt < 2; mt++)
                #pragma unroll
                for (int nt = 0; nt < 8; nt++)
                    mma_tf32(c[mt][nt], af[mt], bf[nt]);
        }
        __syncthreads();
    }
#undef TGL_LOAD

    #pragma unroll
    for (int mt = 0; mt < 2; mt++) {
        int r0 = bm0 + wm + mt*16 + (lane >> 2);
        #pragma unroll
        for (int nt = 0; nt < 8; nt++) {
            int col = bn0 + wn + nt*8 + (lane & 3)*2;
            #pragma unroll
            for (int half_ = 0; half_ < 2; half_++) {
                int r = r0 + half_*8;
                if (r >= M) continue;
                #pragma unroll
                for (int cc = 0; cc < 2; cc++) {
                    int cl = col + cc;
                    if (cl >= N) continue;
                    C[(size_t)r*N + cl] = c[mt][nt][half_*2 + cc];
                }
            }
        }
    }
}

// ---------------- host side ----------------
static inline int cdiv(int a, int b) { return (a + b - 1) / b; }

extern "C" void kernel_launch(void* const* d_in, const int* in_sizes, int n_in,
                              void* d_out, int out_size) {
    const int*   x         = (const int*)  d_in[0];
    const int*   t         = (const int*)  d_in[1];
    const int*   level     = (const int*)  d_in[2];
    const float* tok_emb   = (const float*)d_in[3];
    const float* level_emb = (const float*)d_in[4];
    const float* time_w1   = (const float*)d_in[5];
    const float* time_b1   = (const float*)d_in[6];
    const float* time_w2   = (const float*)d_in[7];
    const float* time_b2   = (const float*)d_in[8];
    const float* ln1_g     = (const float*)d_in[9];
    const float* ln1_b     = (const float*)d_in[10];
    const float* qkv_w     = (const float*)d_in[11];
    const float* proj_w    = (const float*)d_in[12];
    const float* ln2_g     = (const float*)d_in[13];
    const float* ln2_b     = (const float*)d_in[14];
    const float* fc1_w     = (const float*)d_in[15];
    const float* fc2_w     = (const float*)d_in[16];
    const float* lnf_g     = (const float*)d_in[17];
    const float* lnf_b     = (const float*)d_in[18];
    const float* head0_w   = (const float*)d_in[19];

    float  *ph, *phn, *pgath, *ptein, *pteh, *pte, *pcos, *psin;
    __half *phnh, *pqkvh, *poh, *pffnh;
    __half *pqkvw, *pprojw, *pfc1w, *pfc2w;
    cudaGetSymbolAddress((void**)&ph,    g_h);
    cudaGetSymbolAddress((void**)&phn,   g_hn);
    cudaGetSymbolAddress((void**)&pgath, g_gath);
    cudaGetSymbolAddress((void**)&ptein, g_tein);
    cudaGetSymbolAddress((void**)&pteh,  g_teh);
    cudaGetSymbolAddress((void**)&pte,   g_te);
    cudaGetSymbolAddress((void**)&pcos,  g_cos);
    cudaGetSymbolAddress((void**)&psin,  g_sin);
    cudaGetSymbolAddress((void**)&phnh,  g_hnh);
    cudaGetSymbolAddress((void**)&pqkvh, g_qkvh);
    cudaGetSymbolAddress((void**)&poh,   g_oh);
    cudaGetSymbolAddress((void**)&pffnh, g_ffnh);
    cudaGetSymbolAddress((void**)&pqkvw, g_qkvw);
    cudaGetSymbolAddress((void**)&pprojw,g_projw);
    cudaGetSymbolAddress((void**)&pfc1w, g_fc1w);
    cudaGetSymbolAddress((void**)&pfc2w, g_fc2w);

    cudaFuncSetAttribute(hgemm_kernel<1>, cudaFuncAttributeMaxDynamicSharedMemorySize, HG_SMEM);
    cudaFuncSetAttribute(hgemm_kernel<2>, cudaFuncAttributeMaxDynamicSharedMemorySize, HG_SMEM);
    cudaFuncSetAttribute(hgemm_kernel<3>, cudaFuncAttributeMaxDynamicSharedMemorySize, HG_SMEM);

    // transpose + halve weights:  W[K,N] -> WT[N,K]
    dim3 tb(32, 8);
    transpose_half_kernel<<<dim3(3*DD/32, DD/32, LL), tb>>>(qkv_w,  pqkvw,  DD, 3*DD);
    transpose_half_kernel<<<dim3(DD/32,   DD/32, LL), tb>>>(proj_w, pprojw, DD, DD);
    transpose_half_kernel<<<dim3(DFF/32,  DD/32, LL), tb>>>(fc1_w,  pfc1w,  DD, DFF);
    transpose_half_kernel<<<dim3(DD/32,  DFF/32, LL), tb>>>(fc2_w,  pfc2w,  DFF, DD);

    // rope tables + time embedding
    rope_init_kernel<<<cdiv(TT*32, 512), 512>>>(pcos, psin);
    te_in_kernel<<<BB, 512>>>(t, ptein);
    tgemm_kernel<2><<<cdiv(DFF,128), 128>>>(ptein, time_w1, time_b1, pteh, DD, DFF);
    tgemm_kernel<0><<<cdiv(DD,128), 128>>>(pteh, time_w2, time_b2, pte, DFF, DD);

    // token + level + time embedding
    embed_kernel<<<NTOK, 256>>>(x, level, tok_emb, level_emb, pte, ph);

    dim3 blk(256);
    for (int i = 0; i < LL; i++) {
        layernorm_kernel<1><<<NTOK, 256>>>(ph, ln1_g + i*DD, ln1_b + i*DD, phnh);

        hgemm_kernel<3><<<dim3(3*DD/128, NTOK/128), blk, HG_SMEM>>>(
            phnh, pqkvw + (size_t)i*DD*3*DD, nullptr, pqkvh, 3*DD, DD, pcos, psin);

        flash_attn_kernel<<<dim3(TT/64, BB*HH), 128>>>(pqkvh, poh);

        hgemm_kernel<1><<<dim3(DD/128, NTOK/128), blk, HG_SMEM>>>(
            poh, pprojw + (size_t)i*DD*DD, ph, ph, DD, DD, pcos, psin);

        layernorm_kernel<1><<<NTOK, 256>>>(ph, ln2_g + i*DD, ln2_b + i*DD, phnh);

        hgemm_kernel<2><<<dim3(DFF/128, NTOK/128), blk, HG_SMEM>>>(
            phnh, pfc1w + (size_t)i*DD*DFF, nullptr, pffnh, DFF, DD, pcos, psin);

        hgemm_kernel<1><<<dim3(DD/128, NTOK/128), blk, HG_SMEM>>>(
            pffnh, pfc2w + (size_t)i*DFF*DD, ph, ph, DD, DFF, pcos, psin);
    }

    layernorm_kernel<0><<<NTOK, 256>>>(ph, lnf_g, lnf_b, phn);
    gather_kernel<<<NHEADROWS, 256>>>(phn, pgath);
    tf32gemm_kernel<<<dim3(cdiv(V0,128), cdiv(NHEADROWS,128)), blk>>>(
        pgath, head0_w, (float*)d_out, NHEADROWS, V0, DD);
}

// round 8
// speedup vs baseline: 5.4446x; 1.0993x over previous
#include <cuda_runtime.h>
#include <cuda_fp16.h>
#include <math.h>
#include <stdint.h>

// ---------------- problem constants ----------------
#define BB   16
#define TT   512
#define NTOK (BB*TT)        // 8192
#define DD   1024
#define HH   16
#define HDIM 64
#define LL   12
#define DFF  4096
#define V0   1025
#define TOUT 511
#define NHEADROWS (BB*TOUT) // 8176

// ---------------- scratch (device globals; no allocation allowed) -------
__device__ float  g_h    [NTOK*DD];
__device__ float  g_hn   [NTOK*DD];
__device__ float  g_gath [NHEADROWS*DD];
__device__ float  g_tein [BB*DD];
__device__ float  g_teh  [BB*DFF];
__device__ float  g_te   [BB*DD];
__device__ float  g_cos  [TT*32];
__device__ float  g_sin  [TT*32];
__device__ __half g_hnh  [NTOK*DD];
__device__ __half g_qkvh [NTOK*3*DD];
__device__ __half g_oh   [NTOK*DD];
__device__ __half g_ffnh [NTOK*DFF];
// transposed half weights  [L][N][K] K-major
__device__ __half g_qkvw [LL*DD*3*DD];
__device__ __half g_projw[LL*DD*DD];
__device__ __half g_fc1w [LL*DD*DFF];
__device__ __half g_fc2w [LL*DFF*DD];

__device__ __forceinline__ float gelu_exact(float x) {
    return 0.5f * x * (1.0f + erff(x * 0.70710678118654752440f));
}
__device__ __forceinline__ uint32_t f2tf32(float x) {
    uint32_t r; asm("cvt.rna.tf32.f32 %0, %1;" : "=r"(r) : "f"(x)); return r;
}
__device__ __forceinline__ uint32_t packh2(float a, float b) {
    __half2 h = __floats2half2_rn(a, b);
    return *reinterpret_cast<uint32_t*>(&h);
}

// fp16 mma: C(16x8,f32) += A(16x16,f16 row) * B(16x8,f16 col)
__device__ __forceinline__ void mma_f16(float* c, const uint32_t* a, const uint32_t* b) {
    asm volatile(
        "mma.sync.aligned.m16n8k16.row.col.f32.f16.f16.f32 "
        "{%0,%1,%2,%3}, {%4,%5,%6,%7}, {%8,%9}, {%0,%1,%2,%3};"
        : "+f"(c[0]), "+f"(c[1]), "+f"(c[2]), "+f"(c[3])
        : "r"(a[0]), "r"(a[1]), "r"(a[2]), "r"(a[3]), "r"(b[0]), "r"(b[1]));
}
__device__ __forceinline__ void mma_tf32(float* c, const uint32_t* a, const uint32_t* b) {
    asm volatile(
        "mma.sync.aligned.m16n8k8.row.col.f32.tf32.tf32.f32 "
        "{%0,%1,%2,%3}, {%4,%5,%6,%7}, {%8,%9}, {%0,%1,%2,%3};"
        : "+f"(c[0]), "+f"(c[1]), "+f"(c[2]), "+f"(c[3])
        : "r"(a[0]), "r"(a[1]), "r"(a[2]), "r"(a[3]), "r"(b[0]), "r"(b[1]));
}
__device__ __forceinline__ void cp_async16(uint32_t saddr, const void* gptr) {
    asm volatile("cp.async.cg.shared.global [%0], [%1], 16;\n" :: "r"(saddr), "l"(gptr));
}
#define LDSM_X4(r0,r1,r2,r3,a) \
    asm volatile("ldmatrix.sync.aligned.m8n8.x4.shared.b16 {%0,%1,%2,%3}, [%4];" \
        : "=r"(r0),"=r"(r1),"=r"(r2),"=r"(r3) : "r"(a))
#define LDSM_X4T(r0,r1,r2,r3,a) \
    asm volatile("ldmatrix.sync.aligned.m8n8.x4.trans.shared.b16 {%0,%1,%2,%3}, [%4];" \
        : "=r"(r0),"=r"(r1),"=r"(r2),"=r"(r3) : "r"(a))

// ---------------- weight transpose + half convert: W[K,N] -> WT[N,K] ----
__global__ void transpose_half_kernel(const float* __restrict__ src, __half* __restrict__ dst,
                                      int K, int N) {
    __shared__ float tile[32][33];
    size_t loff = (size_t)blockIdx.z * K * N;
    int n0 = blockIdx.x * 32, k0 = blockIdx.y * 32;
    int tx = threadIdx.x, ty = threadIdx.y;   // 32x8
    #pragma unroll
    for (int i = 0; i < 32; i += 8)
        tile[ty+i][tx] = src[loff + (size_t)(k0+ty+i)*N + n0+tx];
    __syncthreads();
    #pragma unroll
    for (int i = 0; i < 32; i += 8)
        dst[loff + (size_t)(n0+ty+i)*K + k0+tx] = __float2half_rn(tile[tx][ty+i]);
}

// ---------------- rope tables ----------------
__global__ void rope_init_kernel(float* cosT, float* sinT) {
    int idx = blockIdx.x * blockDim.x + threadIdx.x;
    if (idx >= TT*32) return;
    int t = idx >> 5, j = idx & 31;
    float freq = expf(-(float)j * (logf(10000.0f) / 32.0f));
    float ang = (float)t * freq;
    cosT[idx] = cosf(ang);
    sinT[idx] = sinf(ang);
}

// ---------------- time embedding ----------------
__global__ void te_in_kernel(const int* __restrict__ t, float* __restrict__ out) {
    int b = blockIdx.x;
    int j = threadIdx.x;
    float tv = (float)t[b];
    float e  = expf((float)j * (-logf(10000.0f) / 511.0f));
    float v  = tv * e;
    out[b*DD + j]       = sinf(v);
    out[b*DD + 512 + j] = cosf(v);
}

template<int EPI>  // 0 = bias only, 2 = gelu(bias+)
__global__ void tgemm_kernel(const float* __restrict__ A, const float* __restrict__ Bw,
                             const float* __restrict__ bias, float* __restrict__ C,
                             int K, int N) {
    int n = blockIdx.x * blockDim.x + threadIdx.x;
    if (n >= N) return;
    float acc[16];
    #pragma unroll
    for (int m = 0; m < 16; m++) acc[m] = 0.f;
    for (int k = 0; k < K; k++) {
        float bv = Bw[(size_t)k*N + n];
        #pragma unroll
        for (int m = 0; m < 16; m++) acc[m] += A[m*K + k] * bv;
    }
    float bs = bias[n];
    #pragma unroll
    for (int m = 0; m < 16; m++) {
        float v = acc[m] + bs;
        if (EPI == 2) v = gelu_exact(v);
        C[(size_t)m*N + n] = v;
    }
}

// ---------------- embedding ----------------
__global__ void embed_kernel(const int* __restrict__ x, const int* __restrict__ level,
                             const float* __restrict__ tok_emb, const float* __restrict__ level_emb,
                             const float* __restrict__ te, float* __restrict__ h) {
    int n = blockIdx.x;
    int b = n >> 9;
    int lvl = level[0];
    const float4* tk = (const float4*)(tok_emb + (size_t)x[n]*DD);
    const float4* le = (const float4*)(level_emb + (size_t)lvl*DD);
    const float4* tv = (const float4*)(te + (size_t)b*DD);
    float4* out = (float4*)(h + (size_t)n*DD);
    int i = threadIdx.x;
    float4 a = tk[i], c = le[i], d = tv[i];
    out[i] = make_float4(a.x+c.x+d.x, a.y+c.y+d.y, a.z+c.z+d.z, a.w+c.w+d.w);
}

// ---------------- layernorm: OUTHALF=1 -> half out, 0 -> float out ------
template<int OUTHALF>
__global__ void __launch_bounds__(256) layernorm_kernel(
        const float* __restrict__ x, const float* __restrict__ g,
        const float* __restrict__ b, void* __restrict__ yv) {
    size_t row = blockIdx.x;
    int tid = threadIdx.x;
    const float4* xr = (const float4*)(x + row*DD);
    float4 v = xr[tid];
    float s  = v.x + v.y + v.z + v.w;
    float ss = v.x*v.x + v.y*v.y + v.z*v.z + v.w*v.w;
    __shared__ float sh1[8], sh2[8], shm[2];
    int lane = tid & 31, w = tid >> 5;
    #pragma unroll
    for (int o = 16; o > 0; o >>= 1) {
        s  += __shfl_xor_sync(0xffffffffu, s,  o);
        ss += __shfl_xor_sync(0xffffffffu, ss, o);
    }
    if (lane == 0) { sh1[w] = s; sh2[w] = ss; }
    __syncthreads();
    if (tid == 0) {
        float ts = 0.f, tss = 0.f;
        #pragma unroll
        for (int i = 0; i < 8; i++) { ts += sh1[i]; tss += sh2[i]; }
        float mean = ts * (1.0f/DD);
        float var  = tss * (1.0f/DD) - mean*mean;
        shm[0] = mean;
        shm[1] = rsqrtf(var + 1e-5f);
    }
    __syncthreads();
    float mean = shm[0], rs = shm[1];
    float4 gg = ((const float4*)g)[tid];
    float4 bb = ((const float4*)b)[tid];
    float o0 = (v.x-mean)*rs*gg.x + bb.x;
    float o1 = (v.y-mean)*rs*gg.y + bb.y;
    float o2 = (v.z-mean)*rs*gg.z + bb.z;
    float o3 = (v.w-mean)*rs*gg.w + bb.w;
    if (OUTHALF) {
        __half2* y = (__half2*)((__half*)yv + row*DD);
        y[tid*2+0] = __halves2half2(__float2half_rn(o0), __float2half_rn(o1));
        y[tid*2+1] = __halves2half2(__float2half_rn(o2), __float2half_rn(o3));
    } else {
        ((float4*)((float*)yv + row*DD))[tid] = make_float4(o0, o1, o2, o3);
    }
}

// =======================================================================
// fp16 GEMM (ldmatrix mainloop, single-barrier): C = A[M,K] @ BT[N,K]^T.
// M%128==0, N%128==0, K%32==0. 128x128x32 tile, 4-buffer cp.async ring.
// EPI: 1 = +residual(float out), 2 = gelu(half out), 3 = rope-qkv(half out, q*0.125)
// =======================================================================
#define HPITCH 40                 // halves per smem row (80 B): conflict-free
#define HSTAGE 20480              // bytes per stage (A 10240 + B 10240)
#define HG_SMEM (4*HSTAGE)        // 81920

template<int EPI>
__global__ void __launch_bounds__(256) hgemm_kernel(
        const __half* __restrict__ A, const __half* __restrict__ BT,
        const float* __restrict__ Cres, void* __restrict__ Cv,
        int N, int K,
        const float* __restrict__ cosT, const float* __restrict__ sinT) {
    extern __shared__ __align__(16) char smem[];
    uint32_t sb = (uint32_t)__cvta_generic_to_shared(smem);
    int tid = threadIdx.x;
    int bn0 = blockIdx.x * 128, bm0 = blockIdx.y * 128;
    int wid = tid >> 5, lane = tid & 31;
    int wm = (wid & 3) * 32;       // warp m offset
    int wn = (wid >> 2) * 64;      // warp n offset
    int mc = lane >> 2;
    int kq2 = (lane & 3) * 2;

    float c[2][8][4];
    #pragma unroll
    for (int mt = 0; mt < 2; mt++)
        #pragma unroll
        for (int nt = 0; nt < 8; nt++)
            #pragma unroll
            for (int i = 0; i < 4; i++) c[mt][nt][i] = 0.f;

    int NIT = K >> 5;

    // per-lane ldmatrix byte offsets within a stage
    int a_r = lane & 15, a_c = (lane >> 4) * 8;
    int b_r = ((lane >> 4) << 3) + (lane & 7), b_c = ((lane >> 3) & 1) * 8;
    uint32_t aoff[2][2], boff[2][4];
    #pragma unroll
    for (int ks = 0; ks < 2; ks++) {
        #pragma unroll
        for (int mt = 0; mt < 2; mt++)
            aoff[ks][mt] = (uint32_t)((wm + mt*16 + a_r)*80 + (ks*16 + a_c)*2);
        #pragma unroll
        for (int p = 0; p < 4; p++)
            boff[ks][p] = (uint32_t)(10240 + (wn + p*16 + b_r)*80 + (ks*16 + b_c)*2);
    }

    auto load_stage = [&](int s) {
        int b = s & 3;
        int k0 = s << 5;
        uint32_t abase = sb + b*HSTAGE;
        uint32_t bbase = abase + 10240;
        #pragma unroll
        for (int j = 0; j < 2; j++) {
            int ch = (tid << 1) + j;       // 0..511
            int row = ch >> 2, q = ch & 3;
            cp_async16(abase + row*80 + q*16, A + (size_t)(bm0 + row)*K + k0 + q*8);
        }
        #pragma unroll
        for (int j = 0; j < 2; j++) {
            int ch = (tid << 1) + j;
            int row = ch >> 2, q = ch & 3;
            cp_async16(bbase + row*80 + q*16, BT + (size_t)(bn0 + row)*K + k0 + q*8);
        }
    };

    load_stage(0); asm volatile("cp.async.commit_group;");
    load_stage(1); asm volatile("cp.async.commit_group;");
    load_stage(2); asm volatile("cp.async.commit_group;");

    for (int it = 0; it < NIT; it++) {
        asm volatile("cp.async.wait_group 2;");
        __syncthreads();
        // buffer (it+3)&3 was last consumed in iteration it-1; every warp past
        // the barrier above has finished that MMA phase -> safe to refill now.
        if (it + 3 < NIT) load_stage(it + 3);
        asm volatile("cp.async.commit_group;");

        uint32_t stage = sb + (it & 3)*HSTAGE;
        #pragma unroll
        for (int ks = 0; ks < 2; ks++) {
            uint32_t af[2][4], bf[8][2];
            LDSM_X4(af[0][0], af[0][1], af[0][2], af[0][3], stage + aoff[ks][0]);
            LDSM_X4(af[1][0], af[1][1], af[1][2], af[1][3], stage + aoff[ks][1]);
            #pragma unroll
            for (int p = 0; p < 4; p++)
                LDSM_X4(bf[2*p][0], bf[2*p][1], bf[2*p+1][0], bf[2*p+1][1],
                        stage + boff[ks][p]);
            #pragma unroll
            for (int mt = 0; mt < 2; mt++)
                #pragma unroll
                for (int nt = 0; nt < 8; nt++)
                    mma_f16(c[mt][nt], af[mt], bf[nt]);
        }
    }

    // ---------------- epilogue ----------------
    #pragma unroll
    for (int mt = 0; mt < 2; mt++) {
        int r0 = bm0 + wm + mt*16 + mc;
        #pragma unroll
        for (int nt = 0; nt < 8; nt++) {
            int col = bn0 + wn + nt*8 + kq2;
            #pragma unroll
            for (int half_ = 0; half_ < 2; half_++) {
                int r = r0 + half_*8;
                float v0 = c[mt][nt][half_*2 + 0];
                float v1 = c[mt][nt][half_*2 + 1];
                if (EPI == 1) {
                    float* C = (float*)Cv;
                    const float2 res = *reinterpret_cast<const float2*>(Cres + (size_t)r*N + col);
                    v0 += res.x; v1 += res.y;
                    *reinterpret_cast<float2*>(C + (size_t)r*N + col) = make_float2(v0, v1);
                } else if (EPI == 2) {
                    __half* C = (__half*)Cv;
                    __half2 hv = __halves2half2(__float2half_rn(gelu_exact(v0)),
                                                __float2half_rn(gelu_exact(v1)));
                    *reinterpret_cast<__half2*>(C + (size_t)r*N + col) = hv;
                } else {   // EPI 3: rope on q/k pairs, q pre-scaled by 1/8 (exact)
                    __half* C = (__half*)Cv;
                    if (col < 2*DD) {
                        int j = (col & 63) >> 1;
                        int t = r & (TT-1);
                        float cc = cosT[t*32 + j], ssn = sinT[t*32 + j];
                        float x1 = v0, x2 = v1;
                        v0 = x1*cc - x2*ssn;
                        v1 = x1*ssn + x2*cc;
                        if (col < DD) { v0 *= 0.125f; v1 *= 0.125f; }
                    }
                    __half2 hv = __halves2half2(__float2half_rn(v0), __float2half_rn(v1));
                    *reinterpret_cast<__half2*>(C + (size_t)r*N + col) = hv;
                }
            }
        }
    }
}

// =======================================================================
// Flash attention: one block = 128 q rows x one (b,h). 8 warps (16 q each),
// online softmax. Q pre-scaled by 1/sqrt(64). O written as half.
// smem (dynamic): Q 128x72h | K 2x64x72h | V 2x64x72h = 55296 B
// =======================================================================
#define FA_SMEM (128*144 + 2*64*144 + 2*64*144)   // 55296

__global__ void __launch_bounds__(256) flash_attn_kernel(
        const __half* __restrict__ qkv, __half* __restrict__ o) {
    extern __shared__ __align__(16) char fsmem[];
    uint32_t sQ = (uint32_t)__cvta_generic_to_shared(fsmem);
    uint32_t sK = sQ + 128*144;
    uint32_t sV = sK + 2*64*144;
    int bh = blockIdx.y;
    int b = bh >> 4, h = bh & 15;
    int q0 = blockIdx.x * 128;
    int tid = threadIdx.x, wid = tid >> 5, lane = tid & 31;
    int mc = lane >> 2, kq2 = (lane & 3) * 2;

    auto load_kv = [&](int kc, int buf) {
        #pragma unroll
        for (int j = 0; j < 2; j++) {
            int ch = tid + j*256;            // 0..511
            int row = ch >> 3, seg = ch & 7;
            size_t base = (size_t)(b*TT + kc*64 + row)*3*DD + h*HDIM + seg*8;
            cp_async16(sK + buf*9216 + row*144 + seg*16, qkv + base + DD);
            cp_async16(sV + buf*9216 + row*144 + seg*16, qkv + base + 2*DD);
        }
    };

    // Q load: 128 rows x 8 segs = 1024 chunks
    #pragma unroll
    for (int j = 0; j < 4; j++) {
        int ch = tid + j*256;
        int row = ch >> 3, seg = ch & 7;
        cp_async16(sQ + row*144 + seg*16,
                   qkv + (size_t)(b*TT + q0 + row)*3*DD + h*HDIM + seg*8);
    }
    asm volatile("cp.async.commit_group;");
    load_kv(0, 0); asm volatile("cp.async.commit_group;");
    load_kv(1, 1); asm volatile("cp.async.commit_group;");

    asm volatile("cp.async.wait_group 2;");
    __syncthreads();

    // Q fragments (held in registers all loop long)
    uint32_t qf[4][4];
    {
        uint32_t qb = sQ + (uint32_t)((wid*16 + (lane & 15))*144 + ((lane >> 4)*8)*2);
        #pragma unroll
        for (int ks = 0; ks < 4; ks++)
            LDSM_X4(qf[ks][0], qf[ks][1], qf[ks][2], qf[ks][3], qb + ks*32);
    }

    uint32_t kRow = (uint32_t)(((lane >> 4) << 3) + (lane & 7));
    uint32_t kCol = (uint32_t)(((lane >> 3) & 1) * 8);
    uint32_t vRow = (uint32_t)(lane & 15);
    uint32_t vCol = (uint32_t)((lane >> 4) * 8);

    float m0 = -1e30f, m1 = -1e30f, l0 = 0.f, l1 = 0.f;
    float oa[8][4];
    #pragma unroll
    for (int nt = 0; nt < 8; nt++)
        #pragma unroll
        for (int i = 0; i < 4; i++) oa[nt][i] = 0.f;

    for (int kc = 0; kc < 8; kc++) {
        asm volatile("cp.async.wait_group 1;");
        __syncthreads();
        uint32_t kb = sK + (kc & 1)*9216;
        uint32_t vb = sV + (kc & 1)*9216;

        // S = Q K^T (warp owns 16 q rows x 64 k-tokens)
        float s[8][4];
        #pragma unroll
        for (int nt = 0; nt < 8; nt++)
            #pragma unroll
            for (int i = 0; i < 4; i++) s[nt][i] = 0.f;
        #pragma unroll
        for (int ks = 0; ks < 4; ks++) {
            uint32_t bf[8][2];
            #pragma unroll
            for (int p = 0; p < 4; p++)
                LDSM_X4(bf[2*p][0], bf[2*p][1], bf[2*p+1][0], bf[2*p+1][1],
                        kb + (p*16 + kRow)*144 + (ks*16 + kCol)*2);
            #pragma unroll
            for (int nt = 0; nt < 8; nt++) mma_f16(s[nt], qf[ks], bf[nt]);
        }

        // online softmax (rows mc / mc+8; quad = 4 consecutive lanes)
        float mx0 = -1e30f, mx1 = -1e30f;
        #pragma unroll
        for (int nt = 0; nt < 8; nt++) {
            mx0 = fmaxf(mx0, fmaxf(s[nt][0], s[nt][1]));
            mx1 = fmaxf(mx1, fmaxf(s[nt][2], s[nt][3]));
        }
        mx0 = fmaxf(mx0, __shfl_xor_sync(0xffffffffu, mx0, 1));
        mx0 = fmaxf(mx0, __shfl_xor_sync(0xffffffffu, mx0, 2));
        mx1 = fmaxf(mx1, __shfl_xor_sync(0xffffffffu, mx1, 1));
        mx1 = fmaxf(mx1, __shfl_xor_sync(0xffffffffu, mx1, 2));
        float m0n = fmaxf(m0, mx0), m1n = fmaxf(m1, mx1);
        float a0 = __expf(m0 - m0n), a1 = __expf(m1 - m1n);

        uint32_t pf[4][4];
        float sum0 = 0.f, sum1 = 0.f;
        #pragma unroll
        for (int tp = 0; tp < 4; tp++) {
            float p00 = __expf(s[2*tp][0]   - m0n);
            float p01 = __expf(s[2*tp][1]   - m0n);
            float p02 = __expf(s[2*tp][2]   - m1n);
            float p03 = __expf(s[2*tp][3]   - m1n);
            float p10 = __expf(s[2*tp+1][0] - m0n);
            float p11 = __expf(s[2*tp+1][1] - m0n);
            float p12 = __expf(s[2*tp+1][2] - m1n);
            float p13 = __expf(s[2*tp+1][3] - m1n);
            sum0 += p00 + p01 + p10 + p11;
            sum1 += p02 + p03 + p12 + p13;
            pf[tp][0] = packh2(p00, p01);
            pf[tp][1] = packh2(p02, p03);
            pf[tp][2] = packh2(p10, p11);
            pf[tp][3] = packh2(p12, p13);
        }
        sum0 += __shfl_xor_sync(0xffffffffu, sum0, 1);
        sum0 += __shfl_xor_sync(0xffffffffu, sum0, 2);
        sum1 += __shfl_xor_sync(0xffffffffu, sum1, 1);
        sum1 += __shfl_xor_sync(0xffffffffu, sum1, 2);
        l0 = l0*a0 + sum0;
        l1 = l1*a1 + sum1;
        m0 = m0n; m1 = m1n;
        #pragma unroll
        for (int nt = 0; nt < 8; nt++) {
            oa[nt][0] *= a0; oa[nt][1] *= a0;
            oa[nt][2] *= a1; oa[nt][3] *= a1;
        }

        // O += P V  (V fragments via ldmatrix.trans)
        #pragma unroll
        for (int kt = 0; kt < 4; kt++) {
            #pragma unroll
            for (int p = 0; p < 4; p++) {
                uint32_t v0, v1, v2, v3;
                LDSM_X4T(v0, v1, v2, v3,
                         vb + (kt*16 + vRow)*144 + (p*16 + vCol)*2);
                uint32_t bv0[2] = {v0, v1}, bv1[2] = {v2, v3};
                mma_f16(oa[2*p],   pf[kt], bv0);
                mma_f16(oa[2*p+1], pf[kt], bv1);
            }
        }

        __syncthreads();
        if (kc + 2 < 8) load_kv(kc + 2, kc & 1);
        asm volatile("cp.async.commit_group;");
    }

    float i0 = 1.f / l0, i1 = 1.f / l1;
    int r0 = b*TT + q0 + wid*16 + mc;
    #pragma unroll
    for (int nt = 0; nt < 8; nt++) {
        int col = h*HDIM + nt*8 + kq2;
        *reinterpret_cast<__half2*>(o + (size_t)r0*DD + col) =
            __halves2half2(__float2half_rn(oa[nt][0]*i0), __float2half_rn(oa[nt][1]*i0));
        *reinterpret_cast<__half2*>(o + (size_t)(r0+8)*DD + col) =
            __halves2half2(__float2half_rn(oa[nt][2]*i1), __float2half_rn(oa[nt][3]*i1));
    }
}

// ---------------- gather rows t=1..511 for head ----------------
__global__ void gather_kernel(const float* __restrict__ hn, float* __restrict__ out) {
    int m = blockIdx.x;
    int b = m / TOUT;
    int t = m % TOUT + 1;
    const float4* src = (const float4*)(hn + (size_t)(b*TT + t)*DD);
    float4* dst = (float4*)(out + (size_t)m*DD);
    dst[threadIdx.x] = src[threadIdx.x];
}

// ---------------- head GEMM (bounds-checked legacy tf32 mma) -------------
__global__ void __launch_bounds__(256) tf32gemm_kernel(
        const float* __restrict__ A, const float* __restrict__ Bm,
        float* __restrict__ C, int M, int N, int K) {
    __shared__ __align__(16) uint32_t As[16][136];
    __shared__ __align__(16) uint32_t Bs[16][136];
    int tid = threadIdx.x;
    int bn0 = blockIdx.x * 128;
    int bm0 = blockIdx.y * 128;
    int wid = tid >> 5, lane = tid & 31;
    int wm = (wid & 3) * 32;
    int wn = (wid >> 2) * 64;

    float c[2][8][4];
    #pragma unroll
    for (int mt = 0; mt < 2; mt++)
        #pragma unroll
        for (int nt = 0; nt < 8; nt++)
            #pragma unroll
            for (int i = 0; i < 4; i++) c[mt][nt][i] = 0.f;

    int aRow = tid >> 1;
    int aCol = (tid & 1) * 8;
    int bRow = tid >> 4;
    int bCol = (tid & 15) * 8;
    bool aValid = (bm0 + aRow) < M;

    float4 pa0, pa1;
    float  pb[8];

#define TGL_LOAD(k0) do {                                                    \
        if (aValid) {                                                        \
            const float* ap = A + (size_t)(bm0 + aRow)*K + (k0) + aCol;      \
            pa0 = *reinterpret_cast<const float4*>(ap);                      \
            pa1 = *reinterpret_cast<const float4*>(ap + 4);                  \
        } else {                                                             \
            pa0 = make_float4(0.f,0.f,0.f,0.f);                              \
            pa1 = make_float4(0.f,0.f,0.f,0.f);                              \
        }                                                                    \
        const float* bp = Bm + (size_t)((k0) + bRow)*N;                      \
        _Pragma("unroll")                                                    \
        for (int j = 0; j < 8; j++) {                                        \
            int cl = bn0 + bCol + j;                                         \
            pb[j] = (cl < N) ? bp[cl] : 0.f;                                 \
        }                                                                    \
    } while (0)

    TGL_LOAD(0);

    for (int k0 = 0; k0 < K; k0 += 16) {
        As[aCol+0][aRow] = f2tf32(pa0.x);
        As[aCol+1][aRow] = f2tf32(pa0.y);
        As[aCol+2][aRow] = f2tf32(pa0.z);
        As[aCol+3][aRow] = f2tf32(pa0.w);
        As[aCol+4][aRow] = f2tf32(pa1.x);
        As[aCol+5][aRow] = f2tf32(pa1.y);
        As[aCol+6][aRow] = f2tf32(pa1.z);
        As[aCol+7][aRow] = f2tf32(pa1.w);
        #pragma unroll
        for (int j = 0; j < 8; j++) Bs[bRow][bCol+j] = f2tf32(pb[j]);
        __syncthreads();

        if (k0 + 16 < K) TGL_LOAD(k0 + 16);

        #pragma unroll
        for (int ks = 0; ks < 2; ks++) {
            int kr = ks*8 + (lane & 3);
            int mc = lane >> 2;
            uint32_t af[2][4], bf[8][2];
            #pragma unroll
            for (int mt = 0; mt < 2; mt++) {
                af[mt][0] = As[kr  ][wm + mt*16 + mc];
                af[mt][1] = As[kr  ][wm + mt*16 + 8 + mc];
                af[mt][2] = As[kr+4][wm + mt*16 + mc];
                af[mt][3] = As[kr+4][wm + mt*16 + 8 + mc];
            }
            #pragma unroll
            for (int nt = 0; nt < 8; nt++) {
                bf[nt][0] = Bs[kr  ][wn + nt*8 + mc];
                bf[nt][1] = Bs[kr+4][wn + nt*8 + mc];
            }
            #pragma unroll
            for (int mt = 0; mt < 2; mt++)
                #pragma unroll
                for (int nt = 0; nt < 8; nt++)
                    mma_tf32(c[mt][nt], af[mt], bf[nt]);
        }
        __syncthreads();
    }
#undef TGL_LOAD

    #pragma unroll
    for (int mt = 0; mt < 2; mt++) {
        int r0 = bm0 + wm + mt*16 + (lane >> 2);
        #pragma unroll
        for (int nt = 0; nt < 8; nt++) {
            int col = bn0 + wn + nt*8 + (lane & 3)*2;
            #pragma unroll
            for (int half_ = 0; half_ < 2; half_++) {
                int r = r0 + half_*8;
                if (r >= M) continue;
                #pragma unroll
                for (int cc = 0; cc < 2; cc++) {
                    int cl = col + cc;
                    if (cl >= N) continue;
                    C[(size_t)r*N + cl] = c[mt][nt][half_*2 + cc];
                }
            }
        }
    }
}

// ---------------- host side ----------------
static inline int cdiv(int a, int b) { return (a + b - 1) / b; }

extern "C" void kernel_launch(void* const* d_in, const int* in_sizes, int n_in,
                              void* d_out, int out_size) {
    const int*   x         = (const int*)  d_in[0];
    const int*   t         = (const int*)  d_in[1];
    const int*   level     = (const int*)  d_in[2];
    const float* tok_emb   = (const float*)d_in[3];
    const float* level_emb = (const float*)d_in[4];
    const float* time_w1   = (const float*)d_in[5];
    const float* time_b1   = (const float*)d_in[6];
    const float* time_w2   = (const float*)d_in[7];
    const float* time_b2   = (const float*)d_in[8];
    const float* ln1_g     = (const float*)d_in[9];
    const float* ln1_b     = (const float*)d_in[10];
    const float* qkv_w     = (const float*)d_in[11];
    const float* proj_w    = (const float*)d_in[12];
    const float* ln2_g     = (const float*)d_in[13];
    const float* ln2_b     = (const float*)d_in[14];
    const float* fc1_w     = (const float*)d_in[15];
    const float* fc2_w     = (const float*)d_in[16];
    const float* lnf_g     = (const float*)d_in[17];
    const float* lnf_b     = (const float*)d_in[18];
    const float* head0_w   = (const float*)d_in[19];

    float  *ph, *phn, *pgath, *ptein, *pteh, *pte, *pcos, *psin;
    __half *phnh, *pqkvh, *poh, *pffnh;
    __half *pqkvw, *pprojw, *pfc1w, *pfc2w;
    cudaGetSymbolAddress((void**)&ph,    g_h);
    cudaGetSymbolAddress((void**)&phn,   g_hn);
    cudaGetSymbolAddress((void**)&pgath, g_gath);
    cudaGetSymbolAddress((void**)&ptein, g_tein);
    cudaGetSymbolAddress((void**)&pteh,  g_teh);
    cudaGetSymbolAddress((void**)&pte,   g_te);
    cudaGetSymbolAddress((void**)&pcos,  g_cos);
    cudaGetSymbolAddress((void**)&psin,  g_sin);
    cudaGetSymbolAddress((void**)&phnh,  g_hnh);
    cudaGetSymbolAddress((void**)&pqkvh, g_qkvh);
    cudaGetSymbolAddress((void**)&poh,   g_oh);
    cudaGetSymbolAddress((void**)&pffnh, g_ffnh);
    cudaGetSymbolAddress((void**)&pqkvw, g_qkvw);
    cudaGetSymbolAddress((void**)&pprojw,g_projw);
    cudaGetSymbolAddress((void**)&pfc1w, g_fc1w);
    cudaGetSymbolAddress((void**)&pfc2w, g_fc2w);

    cudaFuncSetAttribute(hgemm_kernel<1>, cudaFuncAttributeMaxDynamicSharedMemorySize, HG_SMEM);
    cudaFuncSetAttribute(hgemm_kernel<2>, cudaFuncAttributeMaxDynamicSharedMemorySize, HG_SMEM);
    cudaFuncSetAttribute(hgemm_kernel<3>, cudaFuncAttributeMaxDynamicSharedMemorySize, HG_SMEM);
    cudaFuncSetAttribute(flash_attn_kernel, cudaFuncAttributeMaxDynamicSharedMemorySize, FA_SMEM);

    // transpose + halve weights:  W[K,N] -> WT[N,K]
    dim3 tb(32, 8);
    transpose_half_kernel<<<dim3(3*DD/32, DD/32, LL), tb>>>(qkv_w,  pqkvw,  DD, 3*DD);
    transpose_half_kernel<<<dim3(DD/32,   DD/32, LL), tb>>>(proj_w, pprojw, DD, DD);
    transpose_half_kernel<<<dim3(DFF/32,  DD/32, LL), tb>>>(fc1_w,  pfc1w,  DD, DFF);
    transpose_half_kernel<<<dim3(DD/32,  DFF/32, LL), tb>>>(fc2_w,  pfc2w,  DFF, DD);

    // rope tables + time embedding
    rope_init_kernel<<<cdiv(TT*32, 512), 512>>>(pcos, psin);
    te_in_kernel<<<BB, 512>>>(t, ptein);
    tgemm_kernel<2><<<cdiv(DFF,128), 128>>>(ptein, time_w1, time_b1, pteh, DD, DFF);
    tgemm_kernel<0><<<cdiv(DD,128), 128>>>(pteh, time_w2, time_b2, pte, DFF, DD);

    // token + level + time embedding
    embed_kernel<<<NTOK, 256>>>(x, level, tok_emb, level_emb, pte, ph);

    dim3 blk(256);
    for (int i = 0; i < LL; i++) {
        layernorm_kernel<1><<<NTOK, 256>>>(ph, ln1_g + i*DD, ln1_b + i*DD, phnh);

        hgemm_kernel<3><<<dim3(3*DD/128, NTOK/128), blk, HG_SMEM>>>(
            phnh, pqkvw + (size_t)i*DD*3*DD, nullptr, pqkvh, 3*DD, DD, pcos, psin);

        flash_attn_kernel<<<dim3(TT/128, BB*HH), 256, FA_SMEM>>>(pqkvh, poh);

        hgemm_kernel<1><<<dim3(DD/128, NTOK/128), blk, HG_SMEM>>>(
            poh, pprojw + (size_t)i*DD*DD, ph, ph, DD, DD, pcos, psin);

        layernorm_kernel<1><<<NTOK, 256>>>(ph, ln2_g + i*DD, ln2_b + i*DD, phnh);

        hgemm_kernel<2><<<dim3(DFF/128, NTOK/128), blk, HG_SMEM>>>(
            phnh, pfc1w + (size_t)i*DD*DFF, nullptr, pffnh, DFF, DD, pcos, psin);

        hgemm_kernel<1><<<dim3(DD/128, NTOK/128), blk, HG_SMEM>>>(
            pffnh, pfc2w + (size_t)i*DFF*DD, ph, ph, DD, DFF, pcos, psin);
    }

    layernorm_kernel<0><<<NTOK, 256>>>(ph, lnf_g, lnf_b, phn);
    gather_kernel<<<NHEADROWS, 256>>>(phn, pgath);
    tf32gemm_kernel<<<dim3(cdiv(V0,128), cdiv(NHEADROWS,128)), blk>>>(
        pgath, head0_w, (float*)d_out, NHEADROWS, V0, DD);
}

// round 9
// speedup vs baseline: 5.5588x; 1.0210x over previous
#include <cuda_runtime.h>
#include <cuda_fp16.h>
#include <math.h>
#include <stdint.h>

// ---------------- problem constants ----------------
#define BB   16
#define TT   512
#define NTOK (BB*TT)        // 8192
#define DD   1024
#define HH   16
#define HDIM 64
#define LL   12
#define DFF  4096
#define V0   1025
#define TOUT 511
#define NHEADROWS (BB*TOUT) // 8176
#define NHPAD 1152          // head N padded to 9*128

// ---------------- scratch (device globals; no allocation allowed) -------
__device__ float  g_h    [NTOK*DD];
__device__ float  g_tein [BB*DD];
__device__ float  g_teh  [BB*DFF];
__device__ float  g_te   [BB*DD];
__device__ float  g_cos  [TT*32];
__device__ float  g_sin  [TT*32];
__device__ __half g_hnh  [NTOK*DD];     // LN out (half); also gathered head input
__device__ __half g_qkvh [NTOK*3*DD];
__device__ __half g_oh   [NTOK*DD];
__device__ __half g_ffnh [NTOK*DFF];
// transposed half weights  [L][N][K] K-major
__device__ __half g_qkvw [LL*DD*3*DD];
__device__ __half g_projw[LL*DD*DD];
__device__ __half g_fc1w [LL*DD*DFF];
__device__ __half g_fc2w [LL*DFF*DD];
__device__ __half g_headw[NHPAD*DD];    // head weight [1152][1024], zero-padded

__device__ __forceinline__ float gelu_exact(float x) {
    return 0.5f * x * (1.0f + erff(x * 0.70710678118654752440f));
}
__device__ __forceinline__ uint32_t packh2(float a, float b) {
    __half2 h = __floats2half2_rn(a, b);
    return *reinterpret_cast<uint32_t*>(&h);
}
// p = 2^f for two packed args (MUFU f16x2)
__device__ __forceinline__ uint32_t exp2h2(float f0, float f1) {
    __half2 h = __floats2half2_rn(f0, f1);
    __half2 p = h2exp2(h);
    return *reinterpret_cast<uint32_t*>(&p);
}

// fp16 mma: C(16x8,f32) += A(16x16,f16 row) * B(16x8,f16 col)
__device__ __forceinline__ void mma_f16(float* c, const uint32_t* a, const uint32_t* b) {
    asm volatile(
        "mma.sync.aligned.m16n8k16.row.col.f32.f16.f16.f32 "
        "{%0,%1,%2,%3}, {%4,%5,%6,%7}, {%8,%9}, {%0,%1,%2,%3};"
        : "+f"(c[0]), "+f"(c[1]), "+f"(c[2]), "+f"(c[3])
        : "r"(a[0]), "r"(a[1]), "r"(a[2]), "r"(a[3]), "r"(b[0]), "r"(b[1]));
}
__device__ __forceinline__ void cp_async16(uint32_t saddr, const void* gptr) {
    asm volatile("cp.async.cg.shared.global [%0], [%1], 16;\n" :: "r"(saddr), "l"(gptr));
}
#define LDSM_X4(r0,r1,r2,r3,a) \
    asm volatile("ldmatrix.sync.aligned.m8n8.x4.shared.b16 {%0,%1,%2,%3}, [%4];" \
        : "=r"(r0),"=r"(r1),"=r"(r2),"=r"(r3) : "r"(a))
#define LDSM_X4T(r0,r1,r2,r3,a) \
    asm volatile("ldmatrix.sync.aligned.m8n8.x4.trans.shared.b16 {%0,%1,%2,%3}, [%4];" \
        : "=r"(r0),"=r"(r1),"=r"(r2),"=r"(r3) : "r"(a))

// ---------------- weight transpose + half convert: W[K,N] -> WT[N,K] ----
__global__ void transpose_half_kernel(const float* __restrict__ src, __half* __restrict__ dst,
                                      int K, int N) {
    __shared__ float tile[32][33];
    size_t loff = (size_t)blockIdx.z * K * N;
    int n0 = blockIdx.x * 32, k0 = blockIdx.y * 32;
    int tx = threadIdx.x, ty = threadIdx.y;   // 32x8
    #pragma unroll
    for (int i = 0; i < 32; i += 8)
        tile[ty+i][tx] = src[loff + (size_t)(k0+ty+i)*N + n0+tx];
    __syncthreads();
    #pragma unroll
    for (int i = 0; i < 32; i += 8)
        dst[loff + (size_t)(n0+ty+i)*K + k0+tx] = __float2half_rn(tile[tx][ty+i]);
}

// head weight: src [1024][1025] fp32 -> dst [1152][1024] half, zero-padded
__global__ void transpose_head_kernel(const float* __restrict__ src, __half* __restrict__ dst) {
    __shared__ float tile[32][33];
    int n0 = blockIdx.x * 32, k0 = blockIdx.y * 32;
    int tx = threadIdx.x, ty = threadIdx.y;   // 32x8
    #pragma unroll
    for (int i = 0; i < 32; i += 8) {
        int n = n0 + tx;
        tile[ty+i][tx] = (n < V0) ? src[(size_t)(k0+ty+i)*V0 + n] : 0.f;
    }
    __syncthreads();
    #pragma unroll
    for (int i = 0; i < 32; i += 8)
        dst[(size_t)(n0+ty+i)*DD + k0+tx] = __float2half_rn(tile[tx][ty+i]);
}

// ---------------- rope tables ----------------
__global__ void rope_init_kernel(float* cosT, float* sinT) {
    int idx = blockIdx.x * blockDim.x + threadIdx.x;
    if (idx >= TT*32) return;
    int t = idx >> 5, j = idx & 31;
    float freq = expf(-(float)j * (logf(10000.0f) / 32.0f));
    float ang = (float)t * freq;
    cosT[idx] = cosf(ang);
    sinT[idx] = sinf(ang);
}

// ---------------- time embedding ----------------
__global__ void te_in_kernel(const int* __restrict__ t, float* __restrict__ out) {
    int b = blockIdx.x;
    int j = threadIdx.x;
    float tv = (float)t[b];
    float e  = expf((float)j * (-logf(10000.0f) / 511.0f));
    float v  = tv * e;
    out[b*DD + j]       = sinf(v);
    out[b*DD + 512 + j] = cosf(v);
}

template<int EPI>  // 0 = bias only, 2 = gelu(bias+)
__global__ void tgemm_kernel(const float* __restrict__ A, const float* __restrict__ Bw,
                             const float* __restrict__ bias, float* __restrict__ C,
                             int K, int N) {
    int n = blockIdx.x * blockDim.x + threadIdx.x;
    if (n >= N) return;
    float acc[16];
    #pragma unroll
    for (int m = 0; m < 16; m++) acc[m] = 0.f;
    for (int k = 0; k < K; k++) {
        float bv = Bw[(size_t)k*N + n];
        #pragma unroll
        for (int m = 0; m < 16; m++) acc[m] += A[m*K + k] * bv;
    }
    float bs = bias[n];
    #pragma unroll
    for (int m = 0; m < 16; m++) {
        float v = acc[m] + bs;
        if (EPI == 2) v = gelu_exact(v);
        C[(size_t)m*N + n] = v;
    }
}

// ---------------- embedding ----------------
__global__ void embed_kernel(const int* __restrict__ x, const int* __restrict__ level,
                             const float* __restrict__ tok_emb, const float* __restrict__ level_emb,
                             const float* __restrict__ te, float* __restrict__ h) {
    int n = blockIdx.x;
    int b = n >> 9;
    int lvl = level[0];
    const float4* tk = (const float4*)(tok_emb + (size_t)x[n]*DD);
    const float4* le = (const float4*)(level_emb + (size_t)lvl*DD);
    const float4* tv = (const float4*)(te + (size_t)b*DD);
    float4* out = (float4*)(h + (size_t)n*DD);
    int i = threadIdx.x;
    float4 a = tk[i], c = le[i], d = tv[i];
    out[i] = make_float4(a.x+c.x+d.x, a.y+c.y+d.y, a.z+c.z+d.z, a.w+c.w+d.w);
}

// ---------------- layernorm -> half out ----------------
__global__ void __launch_bounds__(256) layernorm_kernel(
        const float* __restrict__ x, const float* __restrict__ g,
        const float* __restrict__ b, __half* __restrict__ y) {
    size_t row = blockIdx.x;
    int tid = threadIdx.x;
    const float4* xr = (const float4*)(x + row*DD);
    float4 v = xr[tid];
    float s  = v.x + v.y + v.z + v.w;
    float ss = v.x*v.x + v.y*v.y + v.z*v.z + v.w*v.w;
    __shared__ float sh1[8], sh2[8], shm[2];
    int lane = tid & 31, w = tid >> 5;
    #pragma unroll
    for (int o = 16; o > 0; o >>= 1) {
        s  += __shfl_xor_sync(0xffffffffu, s,  o);
        ss += __shfl_xor_sync(0xffffffffu, ss, o);
    }
    if (lane == 0) { sh1[w] = s; sh2[w] = ss; }
    __syncthreads();
    if (tid == 0) {
        float ts = 0.f, tss = 0.f;
        #pragma unroll
        for (int i = 0; i < 8; i++) { ts += sh1[i]; tss += sh2[i]; }
        float mean = ts * (1.0f/DD);
        float var  = tss * (1.0f/DD) - mean*mean;
        shm[0] = mean;
        shm[1] = rsqrtf(var + 1e-5f);
    }
    __syncthreads();
    float mean = shm[0], rs = shm[1];
    float4 gg = ((const float4*)g)[tid];
    float4 bb = ((const float4*)b)[tid];
    __half2* y2 = (__half2*)(y + row*DD);
    y2[tid*2+0] = __floats2half2_rn((v.x-mean)*rs*gg.x + bb.x, (v.y-mean)*rs*gg.y + bb.y);
    y2[tid*2+1] = __floats2half2_rn((v.z-mean)*rs*gg.z + bb.z, (v.w-mean)*rs*gg.w + bb.w);
}

// ---------------- final layernorm + gather (t=1..511) -> half, padded ----
__global__ void __launch_bounds__(256) lnf_gather_kernel(
        const float* __restrict__ x, const float* __restrict__ g,
        const float* __restrict__ b, __half* __restrict__ y) {
    int m = blockIdx.x;          // 0..8191
    int tid = threadIdx.x;
    __half2* y2 = (__half2*)(y + (size_t)m*DD);
    if (m >= NHEADROWS) {        // zero pad rows
        __half2 z = __floats2half2_rn(0.f, 0.f);
        y2[tid*2+0] = z; y2[tid*2+1] = z;
        return;
    }
    int bb_ = m / TOUT, tt_ = m % TOUT + 1;
    size_t row = (size_t)(bb_*TT + tt_);
    const float4* xr = (const float4*)(x + row*DD);
    float4 v = xr[tid];
    float s  = v.x + v.y + v.z + v.w;
    float ss = v.x*v.x + v.y*v.y + v.z*v.z + v.w*v.w;
    __shared__ float sh1[8], sh2[8], shm[2];
    int lane = tid & 31, w = tid >> 5;
    #pragma unroll
    for (int o = 16; o > 0; o >>= 1) {
        s  += __shfl_xor_sync(0xffffffffu, s,  o);
        ss += __shfl_xor_sync(0xffffffffu, ss, o);
    }
    if (lane == 0) { sh1[w] = s; sh2[w] = ss; }
    __syncthreads();
    if (tid == 0) {
        float ts = 0.f, tss = 0.f;
        #pragma unroll
        for (int i = 0; i < 8; i++) { ts += sh1[i]; tss += sh2[i]; }
        float mean = ts * (1.0f/DD);
        float var  = tss * (1.0f/DD) - mean*mean;
        shm[0] = mean;
        shm[1] = rsqrtf(var + 1e-5f);
    }
    __syncthreads();
    float mean = shm[0], rs = shm[1];
    float4 gg = ((const float4*)g)[tid];
    float4 bb = ((const float4*)b)[tid];
    y2[tid*2+0] = __floats2half2_rn((v.x-mean)*rs*gg.x + bb.x, (v.y-mean)*rs*gg.y + bb.y);
    y2[tid*2+1] = __floats2half2_rn((v.z-mean)*rs*gg.z + bb.z, (v.w-mean)*rs*gg.w + bb.w);
}

// =======================================================================
// fp16 GEMM (ldmatrix mainloop, single-barrier): C = A[M,K] @ BT[N,K]^T.
// M%128==0, N%128==0, K%32==0. 128x128x32 tile, 4-buffer cp.async ring.
// EPI: 0 = head (float out, stride NC, bounds), 1 = +residual(float out),
//      2 = gelu(half out), 3 = rope-qkv(half out, q*0.125)
// =======================================================================
#define HPITCH 40
#define HSTAGE 20480
#define HG_SMEM (4*HSTAGE)        // 81920

template<int EPI>
__global__ void __launch_bounds__(256) hgemm_kernel(
        const __half* __restrict__ A, const __half* __restrict__ BT,
        const float* __restrict__ Cres, void* __restrict__ Cv,
        int N, int K,
        const float* __restrict__ cosT, const float* __restrict__ sinT,
        int NC) {
    extern __shared__ __align__(16) char smem[];
    uint32_t sb = (uint32_t)__cvta_generic_to_shared(smem);
    int tid = threadIdx.x;
    int bn0 = blockIdx.x * 128, bm0 = blockIdx.y * 128;
    int wid = tid >> 5, lane = tid & 31;
    int wm = (wid & 3) * 32;
    int wn = (wid >> 2) * 64;
    int mc = lane >> 2;
    int kq2 = (lane & 3) * 2;

    float c[2][8][4];
    #pragma unroll
    for (int mt = 0; mt < 2; mt++)
        #pragma unroll
        for (int nt = 0; nt < 8; nt++)
            #pragma unroll
            for (int i = 0; i < 4; i++) c[mt][nt][i] = 0.f;

    int NIT = K >> 5;

    int a_r = lane & 15, a_c = (lane >> 4) * 8;
    int b_r = ((lane >> 4) << 3) + (lane & 7), b_c = ((lane >> 3) & 1) * 8;
    uint32_t aoff[2][2], boff[2][4];
    #pragma unroll
    for (int ks = 0; ks < 2; ks++) {
        #pragma unroll
        for (int mt = 0; mt < 2; mt++)
            aoff[ks][mt] = (uint32_t)((wm + mt*16 + a_r)*80 + (ks*16 + a_c)*2);
        #pragma unroll
        for (int p = 0; p < 4; p++)
            boff[ks][p] = (uint32_t)(10240 + (wn + p*16 + b_r)*80 + (ks*16 + b_c)*2);
    }

    auto load_stage = [&](int s) {
        int b = s & 3;
        int k0 = s << 5;
        uint32_t abase = sb + b*HSTAGE;
        uint32_t bbase = abase + 10240;
        #pragma unroll
        for (int j = 0; j < 2; j++) {
            int ch = (tid << 1) + j;
            int row = ch >> 2, q = ch & 3;
            cp_async16(abase + row*80 + q*16, A + (size_t)(bm0 + row)*K + k0 + q*8);
        }
        #pragma unroll
        for (int j = 0; j < 2; j++) {
            int ch = (tid << 1) + j;
            int row = ch >> 2, q = ch & 3;
            cp_async16(bbase + row*80 + q*16, BT + (size_t)(bn0 + row)*K + k0 + q*8);
        }
    };

    load_stage(0); asm volatile("cp.async.commit_group;");
    load_stage(1); asm volatile("cp.async.commit_group;");
    load_stage(2); asm volatile("cp.async.commit_group;");

    for (int it = 0; it < NIT; it++) {
        asm volatile("cp.async.wait_group 2;");
        __syncthreads();
        if (it + 3 < NIT) load_stage(it + 3);
        asm volatile("cp.async.commit_group;");

        uint32_t stage = sb + (it & 3)*HSTAGE;
        #pragma unroll
        for (int ks = 0; ks < 2; ks++) {
            uint32_t af[2][4], bf[8][2];
            LDSM_X4(af[0][0], af[0][1], af[0][2], af[0][3], stage + aoff[ks][0]);
            LDSM_X4(af[1][0], af[1][1], af[1][2], af[1][3], stage + aoff[ks][1]);
            #pragma unroll
            for (int p = 0; p < 4; p++)
                LDSM_X4(bf[2*p][0], bf[2*p][1], bf[2*p+1][0], bf[2*p+1][1],
                        stage + boff[ks][p]);
            #pragma unroll
            for (int mt = 0; mt < 2; mt++)
                #pragma unroll
                for (int nt = 0; nt < 8; nt++)
                    mma_f16(c[mt][nt], af[mt], bf[nt]);
        }
    }

    // ---------------- epilogue ----------------
    #pragma unroll
    for (int mt = 0; mt < 2; mt++) {
        int r0 = bm0 + wm + mt*16 + mc;
        #pragma unroll
        for (int nt = 0; nt < 8; nt++) {
            int col = bn0 + wn + nt*8 + kq2;
            #pragma unroll
            for (int half_ = 0; half_ < 2; half_++) {
                int r = r0 + half_*8;
                float v0 = c[mt][nt][half_*2 + 0];
                float v1 = c[mt][nt][half_*2 + 1];
                if (EPI == 0) {         // head: bounds-checked scalar stores
                    float* C = (float*)Cv;
                    if (r < NHEADROWS) {
                        if (col < NC)     C[(size_t)r*NC + col]     = v0;
                        if (col + 1 < NC) C[(size_t)r*NC + col + 1] = v1;
                    }
                } else if (EPI == 1) {
                    float* C = (float*)Cv;
                    const float2 res = *reinterpret_cast<const float2*>(Cres + (size_t)r*N + col);
                    v0 += res.x; v1 += res.y;
                    *reinterpret_cast<float2*>(C + (size_t)r*N + col) = make_float2(v0, v1);
                } else if (EPI == 2) {
                    __half* C = (__half*)Cv;
                    __half2 hv = __halves2half2(__float2half_rn(gelu_exact(v0)),
                                                __float2half_rn(gelu_exact(v1)));
                    *reinterpret_cast<__half2*>(C + (size_t)r*N + col) = hv;
                } else {   // EPI 3: rope on q/k pairs, q pre-scaled by 1/8 (exact)
                    __half* C = (__half*)Cv;
                    if (col < 2*DD) {
                        int j = (col & 63) >> 1;
                        int t = r & (TT-1);
                        float cc = cosT[t*32 + j], ssn = sinT[t*32 + j];
                        float x1 = v0, x2 = v1;
                        v0 = x1*cc - x2*ssn;
                        v1 = x1*ssn + x2*cc;
                        if (col < DD) { v0 *= 0.125f; v1 *= 0.125f; }
                    }
                    __half2 hv = __halves2half2(__float2half_rn(v0), __float2half_rn(v1));
                    *reinterpret_cast<__half2*>(C + (size_t)r*N + col) = hv;
                }
            }
        }
    }
}

// =======================================================================
// Flash attention: one block = 128 q rows x one (b,h). 8 warps (16 q each),
// online softmax in exp2/f16x2, row-sum via MMA-with-ones.
// Q pre-scaled by 1/sqrt(64). O written as half.
// =======================================================================
#define FA_SMEM (128*144 + 2*64*144 + 2*64*144)   // 55296
#define LOG2E 1.4426950408889634f

__global__ void __launch_bounds__(256) flash_attn_kernel(
        const __half* __restrict__ qkv, __half* __restrict__ o) {
    extern __shared__ __align__(16) char fsmem[];
    uint32_t sQ = (uint32_t)__cvta_generic_to_shared(fsmem);
    uint32_t sK = sQ + 128*144;
    uint32_t sV = sK + 2*64*144;
    int bh = blockIdx.y;
    int b = bh >> 4, h = bh & 15;
    int q0 = blockIdx.x * 128;
    int tid = threadIdx.x, wid = tid >> 5, lane = tid & 31;
    int mc = lane >> 2, kq2 = (lane & 3) * 2;

    auto load_kv = [&](int kc, int buf) {
        #pragma unroll
        for (int j = 0; j < 2; j++) {
            int ch = tid + j*256;
            int row = ch >> 3, seg = ch & 7;
            size_t base = (size_t)(b*TT + kc*64 + row)*3*DD + h*HDIM + seg*8;
            cp_async16(sK + buf*9216 + row*144 + seg*16, qkv + base + DD);
            cp_async16(sV + buf*9216 + row*144 + seg*16, qkv + base + 2*DD);
        }
    };

    #pragma unroll
    for (int j = 0; j < 4; j++) {
        int ch = tid + j*256;
        int row = ch >> 3, seg = ch & 7;
        cp_async16(sQ + row*144 + seg*16,
                   qkv + (size_t)(b*TT + q0 + row)*3*DD + h*HDIM + seg*8);
    }
    asm volatile("cp.async.commit_group;");
    load_kv(0, 0); asm volatile("cp.async.commit_group;");
    load_kv(1, 1); asm volatile("cp.async.commit_group;");

    asm volatile("cp.async.wait_group 2;");
    __syncthreads();

    uint32_t qf[4][4];
    {
        uint32_t qb = sQ + (uint32_t)((wid*16 + (lane & 15))*144 + ((lane >> 4)*8)*2);
        #pragma unroll
        for (int ks = 0; ks < 4; ks++)
            LDSM_X4(qf[ks][0], qf[ks][1], qf[ks][2], qf[ks][3], qb + ks*32);
    }

    uint32_t kRow = (uint32_t)(((lane >> 4) << 3) + (lane & 7));
    uint32_t kCol = (uint32_t)(((lane >> 3) & 1) * 8);
    uint32_t vRow = (uint32_t)(lane & 15);
    uint32_t vCol = (uint32_t)((lane >> 4) * 8);

    const uint32_t ONES2[2] = {0x3C003C00u, 0x3C003C00u};   // half2(1,1) x2

    float m0 = -1e30f, m1 = -1e30f;
    float lc[4] = {0.f, 0.f, 0.f, 0.f};   // row-sum accumulator (MMA vs ones)
    float oa[8][4];
    #pragma unroll
    for (int nt = 0; nt < 8; nt++)
        #pragma unroll
        for (int i = 0; i < 4; i++) oa[nt][i] = 0.f;

    for (int kc = 0; kc < 8; kc++) {
        asm volatile("cp.async.wait_group 1;");
        __syncthreads();
        uint32_t kb = sK + (kc & 1)*9216;
        uint32_t vb = sV + (kc & 1)*9216;

        // S = Q K^T (warp owns 16 q rows x 64 k-tokens)
        float s[8][4];
        #pragma unroll
        for (int nt = 0; nt < 8; nt++)
            #pragma unroll
            for (int i = 0; i < 4; i++) s[nt][i] = 0.f;
        #pragma unroll
        for (int ks = 0; ks < 4; ks++) {
            uint32_t bf[8][2];
            #pragma unroll
            for (int p = 0; p < 4; p++)
                LDSM_X4(bf[2*p][0], bf[2*p][1], bf[2*p+1][0], bf[2*p+1][1],
                        kb + (p*16 + kRow)*144 + (ks*16 + kCol)*2);
            #pragma unroll
            for (int nt = 0; nt < 8; nt++) mma_f16(s[nt], qf[ks], bf[nt]);
        }

        // online softmax: max (fp32), then p = 2^((s-m)*log2e) in f16x2 MUFU
        float mx0 = -1e30f, mx1 = -1e30f;
        #pragma unroll
        for (int nt = 0; nt < 8; nt++) {
            mx0 = fmaxf(mx0, fmaxf(s[nt][0], s[nt][1]));
            mx1 = fmaxf(mx1, fmaxf(s[nt][2], s[nt][3]));
        }
        mx0 = fmaxf(mx0, __shfl_xor_sync(0xffffffffu, mx0, 1));
        mx0 = fmaxf(mx0, __shfl_xor_sync(0xffffffffu, mx0, 2));
        mx1 = fmaxf(mx1, __shfl_xor_sync(0xffffffffu, mx1, 1));
        mx1 = fmaxf(mx1, __shfl_xor_sync(0xffffffffu, mx1, 2));
        float m0n = fmaxf(m0, mx0), m1n = fmaxf(m1, mx1);
        float a0 = __expf(m0 - m0n), a1 = __expf(m1 - m1n);
        float c0 = m0n * LOG2E, c1 = m1n * LOG2E;

        uint32_t pf[4][4];
        #pragma unroll
        for (int tp = 0; tp < 4; tp++) {
            pf[tp][0] = exp2h2(s[2*tp][0]  *LOG2E - c0, s[2*tp][1]  *LOG2E - c0);
            pf[tp][1] = exp2h2(s[2*tp][2]  *LOG2E - c1, s[2*tp][3]  *LOG2E - c1);
            pf[tp][2] = exp2h2(s[2*tp+1][0]*LOG2E - c0, s[2*tp+1][1]*LOG2E - c0);
            pf[tp][3] = exp2h2(s[2*tp+1][2]*LOG2E - c1, s[2*tp+1][3]*LOG2E - c1);
        }
        m0 = m0n; m1 = m1n;
        // rescale running O and l
        lc[0] *= a0; lc[1] *= a0; lc[2] *= a1; lc[3] *= a1;
        #pragma unroll
        for (int nt = 0; nt < 8; nt++) {
            oa[nt][0] *= a0; oa[nt][1] *= a0;
            oa[nt][2] *= a1; oa[nt][3] *= a1;
        }
        // l += row-sums of P (MMA against ones; exact sums of stored half p)
        #pragma unroll
        for (int kt = 0; kt < 4; kt++) mma_f16(lc, pf[kt], ONES2);

        // O += P V  (V fragments via ldmatrix.trans)
        #pragma unroll
        for (int kt = 0; kt < 4; kt++) {
            #pragma unroll
            for (int p = 0; p < 4; p++) {
                uint32_t v0, v1, v2, v3;
                LDSM_X4T(v0, v1, v2, v3,
                         vb + (kt*16 + vRow)*144 + (p*16 + vCol)*2);
                uint32_t bv0[2] = {v0, v1}, bv1[2] = {v2, v3};
                mma_f16(oa[2*p],   pf[kt], bv0);
                mma_f16(oa[2*p+1], pf[kt], bv1);
            }
        }

        __syncthreads();
        if (kc + 2 < 8) load_kv(kc + 2, kc & 1);
        asm volatile("cp.async.commit_group;");
    }

    float i0 = 1.f / lc[0], i1 = 1.f / lc[2];
    int r0 = b*TT + q0 + wid*16 + mc;
    #pragma unroll
    for (int nt = 0; nt < 8; nt++) {
        int col = h*HDIM + nt*8 + kq2;
        *reinterpret_cast<__half2*>(o + (size_t)r0*DD + col) =
            __halves2half2(__float2half_rn(oa[nt][0]*i0), __float2half_rn(oa[nt][1]*i0));
        *reinterpret_cast<__half2*>(o + (size_t)(r0+8)*DD + col) =
            __halves2half2(__float2half_rn(oa[nt][2]*i1), __float2half_rn(oa[nt][3]*i1));
    }
}

// ---------------- host side ----------------
static inline int cdiv(int a, int b) { return (a + b - 1) / b; }

extern "C" void kernel_launch(void* const* d_in, const int* in_sizes, int n_in,
                              void* d_out, int out_size) {
    const int*   x         = (const int*)  d_in[0];
    const int*   t         = (const int*)  d_in[1];
    const int*   level     = (const int*)  d_in[2];
    const float* tok_emb   = (const float*)d_in[3];
    const float* level_emb = (const float*)d_in[4];
    const float* time_w1   = (const float*)d_in[5];
    const float* time_b1   = (const float*)d_in[6];
    const float* time_w2   = (const float*)d_in[7];
    const float* time_b2   = (const float*)d_in[8];
    const float* ln1_g     = (const float*)d_in[9];
    const float* ln1_b     = (const float*)d_in[10];
    const float* qkv_w     = (const float*)d_in[11];
    const float* proj_w    = (const float*)d_in[12];
    const float* ln2_g     = (const float*)d_in[13];
    const float* ln2_b     = (const float*)d_in[14];
    const float* fc1_w     = (const float*)d_in[15];
    const float* fc2_w     = (const float*)d_in[16];
    const float* lnf_g     = (const float*)d_in[17];
    const float* lnf_b     = (const float*)d_in[18];
    const float* head0_w   = (const float*)d_in[19];

    float  *ph, *ptein, *pteh, *pte, *pcos, *psin;
    __half *phnh, *pqkvh, *poh, *pffnh;
    __half *pqkvw, *pprojw, *pfc1w, *pfc2w, *pheadw;
    cudaGetSymbolAddress((void**)&ph,    g_h);
    cudaGetSymbolAddress((void**)&ptein, g_tein);
    cudaGetSymbolAddress((void**)&pteh,  g_teh);
    cudaGetSymbolAddress((void**)&pte,   g_te);
    cudaGetSymbolAddress((void**)&pcos,  g_cos);
    cudaGetSymbolAddress((void**)&psin,  g_sin);
    cudaGetSymbolAddress((void**)&phnh,  g_hnh);
    cudaGetSymbolAddress((void**)&pqkvh, g_qkvh);
    cudaGetSymbolAddress((void**)&poh,   g_oh);
    cudaGetSymbolAddress((void**)&pffnh, g_ffnh);
    cudaGetSymbolAddress((void**)&pqkvw, g_qkvw);
    cudaGetSymbolAddress((void**)&pprojw,g_projw);
    cudaGetSymbolAddress((void**)&pfc1w, g_fc1w);
    cudaGetSymbolAddress((void**)&pfc2w, g_fc2w);
    cudaGetSymbolAddress((void**)&pheadw,g_headw);

    cudaFuncSetAttribute(hgemm_kernel<0>, cudaFuncAttributeMaxDynamicSharedMemorySize, HG_SMEM);
    cudaFuncSetAttribute(hgemm_kernel<1>, cudaFuncAttributeMaxDynamicSharedMemorySize, HG_SMEM);
    cudaFuncSetAttribute(hgemm_kernel<2>, cudaFuncAttributeMaxDynamicSharedMemorySize, HG_SMEM);
    cudaFuncSetAttribute(hgemm_kernel<3>, cudaFuncAttributeMaxDynamicSharedMemorySize, HG_SMEM);
    cudaFuncSetAttribute(flash_attn_kernel, cudaFuncAttributeMaxDynamicSharedMemorySize, FA_SMEM);

    // transpose + halve weights:  W[K,N] -> WT[N,K]
    dim3 tb(32, 8);
    transpose_half_kernel<<<dim3(3*DD/32, DD/32, LL), tb>>>(qkv_w,  pqkvw,  DD, 3*DD);
    transpose_half_kernel<<<dim3(DD/32,   DD/32, LL), tb>>>(proj_w, pprojw, DD, DD);
    transpose_half_kernel<<<dim3(DFF/32,  DD/32, LL), tb>>>(fc1_w,  pfc1w,  DD, DFF);
    transpose_half_kernel<<<dim3(DD/32,  DFF/32, LL), tb>>>(fc2_w,  pfc2w,  DFF, DD);
    transpose_head_kernel<<<dim3(NHPAD/32, DD/32), tb>>>(head0_w, pheadw);

    // rope tables + time embedding
    rope_init_kernel<<<cdiv(TT*32, 512), 512>>>(pcos, psin);
    te_in_kernel<<<BB, 512>>>(t, ptein);
    tgemm_kernel<2><<<cdiv(DFF,128), 128>>>(ptein, time_w1, time_b1, pteh, DD, DFF);
    tgemm_kernel<0><<<cdiv(DD,128), 128>>>(pteh, time_w2, time_b2, pte, DFF, DD);

    // token + level + time embedding
    embed_kernel<<<NTOK, 256>>>(x, level, tok_emb, level_emb, pte, ph);

    dim3 blk(256);
    for (int i = 0; i < LL; i++) {
        layernorm_kernel<<<NTOK, 256>>>(ph, ln1_g + i*DD, ln1_b + i*DD, phnh);

        hgemm_kernel<3><<<dim3(3*DD/128, NTOK/128), blk, HG_SMEM>>>(
            phnh, pqkvw + (size_t)i*DD*3*DD, nullptr, pqkvh, 3*DD, DD, pcos, psin, 0);

        flash_attn_kernel<<<dim3(TT/128, BB*HH), 256, FA_SMEM>>>(pqkvh, poh);

        hgemm_kernel<1><<<dim3(DD/128, NTOK/128), blk, HG_SMEM>>>(
            poh, pprojw + (size_t)i*DD*DD, ph, ph, DD, DD, pcos, psin, 0);

        layernorm_kernel<<<NTOK, 256>>>(ph, ln2_g + i*DD, ln2_b + i*DD, phnh);

        hgemm_kernel<2><<<dim3(DFF/128, NTOK/128), blk, HG_SMEM>>>(
            phnh, pfc1w + (size_t)i*DD*DFF, nullptr, pffnh, DFF, DD, pcos, psin, 0);

        hgemm_kernel<1><<<dim3(DD/128, NTOK/128), blk, HG_SMEM>>>(
            pffnh, pfc2w + (size_t)i*DFF*DD, ph, ph, DD, DFF, pcos, psin, 0);
    }

    // final LN fused with gather (zero-padded to 8192 rows), fp16 head GEMM
    lnf_gather_kernel<<<NTOK, 256>>>(ph, lnf_g, lnf_b, phnh);
    hgemm_kernel<0><<<dim3(NHPAD/128, NTOK/128), blk, HG_SMEM>>>(
        phnh, pheadw, nullptr, (float*)d_out, NHPAD, DD, pcos, psin, V0);
}